// round 9
// baseline (speedup 1.0000x reference)
#include <cuda_runtime.h>
#include <cuda_bf16.h>
#include <math.h>
#include <stdint.h>

// Problem constants
#define BSZ 8
#define SEQ 1024
#define DM  512
#define NH  8
#define HD  64
#define NEGV (-1e9f)

// ---------------------------------------------------------------------------
// Scratch
// ---------------------------------------------------------------------------
__device__ float g_pre[(size_t)BSZ * SEQ * DM];
__device__ float g_attn_fb[(size_t)BSZ * NH * SEQ * SEQ];

__device__ __nv_bfloat16 g_xh[(size_t)BSZ * SEQ * DM];   // activation hi
__device__ __nv_bfloat16 g_xl[(size_t)BSZ * SEQ * DM];   // activation lo
__device__ __nv_bfloat16 g_wh[4][(size_t)DM * DM];       // W^T hi
__device__ __nv_bfloat16 g_wl[4][(size_t)DM * DM];       // W^T lo

__device__ __nv_bfloat16 g_qh[(size_t)BSZ * NH * SEQ * HD];  // q hi [b,h,s,d]
__device__ __nv_bfloat16 g_ql[(size_t)BSZ * NH * SEQ * HD];
__device__ __nv_bfloat16 g_kh[(size_t)BSZ * NH * SEQ * HD];  // k hi [b,h,s,d]
__device__ __nv_bfloat16 g_kl[(size_t)BSZ * NH * SEQ * HD];
__device__ __nv_bfloat16 g_vh[(size_t)BSZ * NH * HD * SEQ];  // v hi [b,h,d,s]
__device__ __nv_bfloat16 g_vl[(size_t)BSZ * NH * HD * SEQ];
__device__ __nv_bfloat16 g_ph[(size_t)BSZ * NH * SEQ * SEQ]; // P bf16

// ===========================================================================
// mma.sync bf16 helper (verified mapping)
// ===========================================================================
__device__ __forceinline__ void mma_bf16(float* d, const uint32_t* a,
                                         uint32_t b0, uint32_t b1)
{
    asm volatile(
        "mma.sync.aligned.m16n8k16.row.col.f32.bf16.bf16.f32 "
        "{%0,%1,%2,%3}, {%4,%5,%6,%7}, {%8,%9}, {%0,%1,%2,%3};"
        : "+f"(d[0]), "+f"(d[1]), "+f"(d[2]), "+f"(d[3])
        : "r"(a[0]), "r"(a[1]), "r"(a[2]), "r"(a[3]), "r"(b0), "r"(b1));
}

__device__ __forceinline__ uint32_t packh2(float x, float y) {
    __nv_bfloat162 p = __halves2bfloat162(__float2bfloat16(x), __float2bfloat16(y));
    return *(uint32_t*)&p;
}
__device__ __forceinline__ uint32_t packl2(float x, float y) {
    __nv_bfloat16 hx = __float2bfloat16(x), hy = __float2bfloat16(y);
    __nv_bfloat162 p = __halves2bfloat162(
        __float2bfloat16(x - __bfloat162float(hx)),
        __float2bfloat16(y - __bfloat162float(hy)));
    return *(uint32_t*)&p;
}

// ===========================================================================
// Pre-convert kernels (proven)
// ===========================================================================
__global__ void __launch_bounds__(256)
convert_x(const float* __restrict__ A, __nv_bfloat16* __restrict__ hi,
          __nv_bfloat16* __restrict__ lo)
{
    size_t i = ((size_t)blockIdx.x * 256 + threadIdx.x) * 4;
    float4 v = *(const float4*)(A + i);
    uint2 uh = {packh2(v.x, v.y), packh2(v.z, v.w)};
    uint2 ul = {packl2(v.x, v.y), packl2(v.z, v.w)};
    *(uint2*)(hi + i) = uh;
    *(uint2*)(lo + i) = ul;
}

__global__ void __launch_bounds__(256)
convert_w(const float* __restrict__ W, __nv_bfloat16* __restrict__ th,
          __nv_bfloat16* __restrict__ tl)
{
    __shared__ float tile[32][33];
    int tx = threadIdx.x, ty = threadIdx.y;
    int n_in = blockIdx.x * 32 + tx;
    int k0 = blockIdx.y * 32;
#pragma unroll
    for (int j = ty; j < 32; j += 8)
        tile[j][tx] = W[(size_t)(k0 + j) * DM + n_in];
    __syncthreads();
#pragma unroll
    for (int j = ty; j < 32; j += 8) {
        int n = blockIdx.x * 32 + j;
        int k = k0 + tx;
        float v = tile[tx][j];
        __nv_bfloat16 h = __float2bfloat16(v);
        th[(size_t)n * DM + k] = h;
        tl[(size_t)n * DM + k] = __float2bfloat16(v - __bfloat162float(h));
    }
}

// ===========================================================================
// Projection GEMM via mma.sync (proven R8)
// MODE 0: bf16 hi/lo out [b,h,s,d]; MODE 1: bf16 hi/lo [b,h,d,s];
// MODE 2: fp32 + resid row-major
// ===========================================================================
#define PSTR 72
#define PANEL (128 * PSTR)
#define PROJ_SMEM (4 * PANEL * 2)   // 73728 B

template<int MODE>
__global__ void __launch_bounds__(256)
gemm_proj_mma3(const __nv_bfloat16* __restrict__ Ahg,
               const __nv_bfloat16* __restrict__ Alg,
               const __nv_bfloat16* __restrict__ Bhg,
               const __nv_bfloat16* __restrict__ Blg,
               const float* __restrict__ bias, const float* __restrict__ resid,
               float* __restrict__ outf,
               __nv_bfloat16* __restrict__ outh, __nv_bfloat16* __restrict__ outl)
{
    extern __shared__ __nv_bfloat16 sb[];
    __nv_bfloat16* Ah = sb;
    __nv_bfloat16* Al = Ah + PANEL;
    __nv_bfloat16* Bh = Al + PANEL;
    __nv_bfloat16* Bl = Bh + PANEL;

    const int tid = threadIdx.x, wid = tid >> 5, lane = tid & 31;
    const int m0 = blockIdx.y * 128, n0 = blockIdx.x * 128;
    const int wm = (wid >> 2) * 64;
    const int wn = (wid & 3) * 32;
    const int lg = lane >> 2;
    const int lq = lane & 3;

    float acc[4][4][4];
#pragma unroll
    for (int i = 0; i < 4; i++)
#pragma unroll
        for (int j = 0; j < 4; j++)
#pragma unroll
            for (int r = 0; r < 4; r++) acc[i][j][r] = 0.f;

    const int sr = tid >> 3;
    const int sc = (tid & 7) * 8;

    for (int kc = 0; kc < 8; kc++) {
        const int k0 = kc * 64;
        __syncthreads();
#pragma unroll
        for (int p = 0; p < 4; p++) {
            int row = sr + p * 32;
            *(uint4*)&Ah[row * PSTR + sc] =
                *(const uint4*)(Ahg + (size_t)(m0 + row) * DM + k0 + sc);
            *(uint4*)&Al[row * PSTR + sc] =
                *(const uint4*)(Alg + (size_t)(m0 + row) * DM + k0 + sc);
            *(uint4*)&Bh[row * PSTR + sc] =
                *(const uint4*)(Bhg + (size_t)(n0 + row) * DM + k0 + sc);
            *(uint4*)&Bl[row * PSTR + sc] =
                *(const uint4*)(Blg + (size_t)(n0 + row) * DM + k0 + sc);
        }
        __syncthreads();

#pragma unroll
        for (int ks = 0; ks < 4; ks++) {
            const int kb = ks * 16;
            uint32_t ah[4][4], al[4][4];
#pragma unroll
            for (int i = 0; i < 4; i++) {
                int r = wm + i * 16 + lg;
                int c = kb + lq * 2;
                ah[i][0] = *(const uint32_t*)&Ah[r * PSTR + c];
                ah[i][1] = *(const uint32_t*)&Ah[(r + 8) * PSTR + c];
                ah[i][2] = *(const uint32_t*)&Ah[r * PSTR + c + 8];
                ah[i][3] = *(const uint32_t*)&Ah[(r + 8) * PSTR + c + 8];
                al[i][0] = *(const uint32_t*)&Al[r * PSTR + c];
                al[i][1] = *(const uint32_t*)&Al[(r + 8) * PSTR + c];
                al[i][2] = *(const uint32_t*)&Al[r * PSTR + c + 8];
                al[i][3] = *(const uint32_t*)&Al[(r + 8) * PSTR + c + 8];
            }
#pragma unroll
            for (int j = 0; j < 4; j++) {
                int n = wn + j * 8 + lg;
                int ck = kb + lq * 2;
                uint32_t bh0 = *(const uint32_t*)&Bh[n * PSTR + ck];
                uint32_t bh1 = *(const uint32_t*)&Bh[n * PSTR + ck + 8];
                uint32_t bl0 = *(const uint32_t*)&Bl[n * PSTR + ck];
                uint32_t bl1 = *(const uint32_t*)&Bl[n * PSTR + ck + 8];
#pragma unroll
                for (int i = 0; i < 4; i++) {
                    mma_bf16(acc[i][j], ah[i], bh0, bh1);
                    mma_bf16(acc[i][j], ah[i], bl0, bl1);
                    mma_bf16(acc[i][j], al[i], bh0, bh1);
                }
            }
        }
    }

#pragma unroll
    for (int i = 0; i < 4; i++) {
        int r1 = m0 + wm + i * 16 + lg;
        int r2 = r1 + 8;
#pragma unroll
        for (int j = 0; j < 4; j++) {
            int n = n0 + wn + j * 8 + lq * 2;
            float b0 = bias[n], b1 = bias[n + 1];
            float v00 = acc[i][j][0] + b0, v01 = acc[i][j][1] + b1;
            float v10 = acc[i][j][2] + b0, v11 = acc[i][j][3] + b1;
            if (MODE == 2) {
                float2 q1 = *(const float2*)(resid + (size_t)r1 * DM + n);
                float2 q2 = *(const float2*)(resid + (size_t)r2 * DM + n);
                float2 o1 = {v00 + q1.x, v01 + q1.y};
                float2 o2 = {v10 + q2.x, v11 + q2.y};
                *(float2*)(outf + (size_t)r1 * DM + n) = o1;
                *(float2*)(outf + (size_t)r2 * DM + n) = o2;
            } else if (MODE == 0) {
                int h = n >> 6, d = n & (HD - 1);
                int b1_ = r1 >> 10, s1 = r1 & (SEQ - 1);
                int b2_ = r2 >> 10, s2 = r2 & (SEQ - 1);
                size_t o1 = (((size_t)(b1_ * NH + h) * SEQ + s1) << 6) + d;
                size_t o2 = (((size_t)(b2_ * NH + h) * SEQ + s2) << 6) + d;
                *(uint32_t*)(outh + o1) = packh2(v00, v01);
                *(uint32_t*)(outl + o1) = packl2(v00, v01);
                *(uint32_t*)(outh + o2) = packh2(v10, v11);
                *(uint32_t*)(outl + o2) = packl2(v10, v11);
            } else {
                int h = n >> 6, d = n & (HD - 1);
                int b1_ = r1 >> 10, s1 = r1 & (SEQ - 1);
                int b2_ = r2 >> 10, s2 = r2 & (SEQ - 1);
                size_t base1 = (((size_t)(b1_ * NH + h) * HD + d) << 10) + s1;
                size_t base2 = (((size_t)(b2_ * NH + h) * HD + d) << 10) + s2;
                __nv_bfloat16 h00 = __float2bfloat16(v00);
                __nv_bfloat16 h01 = __float2bfloat16(v01);
                __nv_bfloat16 h10 = __float2bfloat16(v10);
                __nv_bfloat16 h11 = __float2bfloat16(v11);
                outh[base1]          = h00;
                outh[base1 + SEQ]    = h01;
                outh[base2]          = h10;
                outh[base2 + SEQ]    = h11;
                outl[base1]       = __float2bfloat16(v00 - __bfloat162float(h00));
                outl[base1 + SEQ] = __float2bfloat16(v01 - __bfloat162float(h01));
                outl[base2]       = __float2bfloat16(v10 - __bfloat162float(h10));
                outl[base2 + SEQ] = __float2bfloat16(v11 - __bfloat162float(h11));
            }
        }
    }
}

// ===========================================================================
// FUSED scores + mask + adjoin + softmax + attn write + P write
// CTA: 16 q-rows x full 1024 n, 256 thr / 8 warps.
// Warp w owns n-stripe [c*128 + w*16, +16) per K-chunk c (8 chunks).
// Q fragments hoisted; acc 16x1024 strip lives in registers (64/thread).
// ===========================================================================
__global__ void __launch_bounds__(256)
fused_scores_softmax(const __nv_bfloat16* __restrict__ qh, const __nv_bfloat16* __restrict__ ql,
                     const __nv_bfloat16* __restrict__ kh, const __nv_bfloat16* __restrict__ kl,
                     const int* __restrict__ mask, const float* __restrict__ adjoin,
                     float* __restrict__ attn, __nv_bfloat16* __restrict__ phout)
{
    __shared__ __nv_bfloat16 Qh[16 * PSTR];
    __shared__ __nv_bfloat16 Ql[16 * PSTR];
    __shared__ __nv_bfloat16 Kh[128 * PSTR];
    __shared__ __nv_bfloat16 Kl[128 * PSTR];
    __shared__ float red[16][8];
    __shared__ float rowv[16];

    const int bh = blockIdx.y;
    const int b_ = bh >> 3;
    const int m0 = blockIdx.x * 16;

    const __nv_bfloat16* qg_h = qh + (size_t)bh * SEQ * HD;
    const __nv_bfloat16* qg_l = ql + (size_t)bh * SEQ * HD;
    const __nv_bfloat16* kg_h = kh + (size_t)bh * SEQ * HD;
    const __nv_bfloat16* kg_l = kl + (size_t)bh * SEQ * HD;
    float* outp = attn + (size_t)bh * SEQ * SEQ;
    __nv_bfloat16* pb = phout + (size_t)bh * SEQ * SEQ;
    const int*   mb = mask   + (size_t)b_ * SEQ * SEQ;
    const float* ab = adjoin + (size_t)b_ * SEQ * SEQ;

    const int tid = threadIdx.x, w = tid >> 5, lane = tid & 31;
    const int lg = lane >> 2, lq = lane & 3;

    // Stage Q tile (16 rows x 64 d, hi/lo)
    if (tid < 128) {
        int row = tid >> 3, col = (tid & 7) * 8;
        *(uint4*)&Qh[row * PSTR + col] = *(const uint4*)(qg_h + (size_t)(m0 + row) * HD + col);
        *(uint4*)&Ql[row * PSTR + col] = *(const uint4*)(qg_l + (size_t)(m0 + row) * HD + col);
    }

    float acc[8][2][4];
#pragma unroll
    for (int c = 0; c < 8; c++)
#pragma unroll
        for (int j = 0; j < 2; j++)
#pragma unroll
            for (int r = 0; r < 4; r++) acc[c][j][r] = 0.f;

    uint32_t qfh[4][4], qfl[4][4];

    for (int c = 0; c < 8; c++) {
        __syncthreads();
        // stage K chunk: rows c*128.. (128 x 64, hi/lo)
#pragma unroll
        for (int p = 0; p < 4; p++) {
            int f = p * 256 + tid;
            int row = f >> 3, col = (f & 7) * 8;
            *(uint4*)&Kh[row * PSTR + col] =
                *(const uint4*)(kg_h + (size_t)(c * 128 + row) * HD + col);
            *(uint4*)&Kl[row * PSTR + col] =
                *(const uint4*)(kg_l + (size_t)(c * 128 + row) * HD + col);
        }
        __syncthreads();

        if (c == 0) {
#pragma unroll
            for (int ks = 0; ks < 4; ks++) {
                int cc = ks * 16 + lq * 2;
                qfh[ks][0] = *(const uint32_t*)&Qh[lg * PSTR + cc];
                qfh[ks][1] = *(const uint32_t*)&Qh[(lg + 8) * PSTR + cc];
                qfh[ks][2] = *(const uint32_t*)&Qh[lg * PSTR + cc + 8];
                qfh[ks][3] = *(const uint32_t*)&Qh[(lg + 8) * PSTR + cc + 8];
                qfl[ks][0] = *(const uint32_t*)&Ql[lg * PSTR + cc];
                qfl[ks][1] = *(const uint32_t*)&Ql[(lg + 8) * PSTR + cc];
                qfl[ks][2] = *(const uint32_t*)&Ql[lg * PSTR + cc + 8];
                qfl[ks][3] = *(const uint32_t*)&Ql[(lg + 8) * PSTR + cc + 8];
            }
        }

#pragma unroll
        for (int ks = 0; ks < 4; ks++) {
            const int kb = ks * 16;
#pragma unroll
            for (int j = 0; j < 2; j++) {
                int n = w * 16 + j * 8 + lg;
                int ck = kb + lq * 2;
                uint32_t bh0 = *(const uint32_t*)&Kh[n * PSTR + ck];
                uint32_t bh1 = *(const uint32_t*)&Kh[n * PSTR + ck + 8];
                uint32_t bl0 = *(const uint32_t*)&Kl[n * PSTR + ck];
                uint32_t bl1 = *(const uint32_t*)&Kl[n * PSTR + ck + 8];
                mma_bf16(acc[c][j], qfh[ks], bh0, bh1);
                mma_bf16(acc[c][j], qfh[ks], bl0, bl1);
                mma_bf16(acc[c][j], qfl[ks], bh0, bh1);
            }
        }
    }

    // ---- scale, mask, adjoin (in-register) ----
    const int r1 = m0 + lg, r2 = r1 + 8;
#pragma unroll
    for (int c = 0; c < 8; c++) {
#pragma unroll
        for (int j = 0; j < 2; j++) {
            int gn = c * 128 + w * 16 + j * 8 + lq * 2;
            size_t o1 = (size_t)r1 * SEQ + gn;
            size_t o2 = (size_t)r2 * SEQ + gn;
            int2   m1 = *(const int2*)(mb + o1);
            int2   m2 = *(const int2*)(mb + o2);
            float2 a1 = *(const float2*)(ab + o1);
            float2 a2 = *(const float2*)(ab + o2);
            acc[c][j][0] = (m1.x ? NEGV : acc[c][j][0] * 0.125f) + a1.x;
            acc[c][j][1] = (m1.y ? NEGV : acc[c][j][1] * 0.125f) + a1.y;
            acc[c][j][2] = (m2.x ? NEGV : acc[c][j][2] * 0.125f) + a2.x;
            acc[c][j][3] = (m2.y ? NEGV : acc[c][j][3] * 0.125f) + a2.y;
        }
    }

    // ---- row max ----
    float mx1 = -INFINITY, mx2 = -INFINITY;
#pragma unroll
    for (int c = 0; c < 8; c++)
#pragma unroll
        for (int j = 0; j < 2; j++) {
            mx1 = fmaxf(mx1, fmaxf(acc[c][j][0], acc[c][j][1]));
            mx2 = fmaxf(mx2, fmaxf(acc[c][j][2], acc[c][j][3]));
        }
    mx1 = fmaxf(mx1, __shfl_xor_sync(0xffffffffu, mx1, 1));
    mx1 = fmaxf(mx1, __shfl_xor_sync(0xffffffffu, mx1, 2));
    mx2 = fmaxf(mx2, __shfl_xor_sync(0xffffffffu, mx2, 1));
    mx2 = fmaxf(mx2, __shfl_xor_sync(0xffffffffu, mx2, 2));
    __syncthreads();           // red[] free
    if (lq == 0) { red[lg][w] = mx1; red[lg + 8][w] = mx2; }
    __syncthreads();
    if (tid < 16) {
        float m = red[tid][0];
#pragma unroll
        for (int k = 1; k < 8; k++) m = fmaxf(m, red[tid][k]);
        rowv[tid] = m;
    }
    __syncthreads();
    const float rm1 = rowv[lg], rm2 = rowv[lg + 8];

    // ---- exp + row sum ----
    float s1 = 0.f, s2 = 0.f;
#pragma unroll
    for (int c = 0; c < 8; c++)
#pragma unroll
        for (int j = 0; j < 2; j++) {
            acc[c][j][0] = __expf(acc[c][j][0] - rm1); s1 += acc[c][j][0];
            acc[c][j][1] = __expf(acc[c][j][1] - rm1); s1 += acc[c][j][1];
            acc[c][j][2] = __expf(acc[c][j][2] - rm2); s2 += acc[c][j][2];
            acc[c][j][3] = __expf(acc[c][j][3] - rm2); s2 += acc[c][j][3];
        }
    s1 += __shfl_xor_sync(0xffffffffu, s1, 1);
    s1 += __shfl_xor_sync(0xffffffffu, s1, 2);
    s2 += __shfl_xor_sync(0xffffffffu, s2, 1);
    s2 += __shfl_xor_sync(0xffffffffu, s2, 2);
    __syncthreads();
    if (lq == 0) { red[lg][w] = s1; red[lg + 8][w] = s2; }
    __syncthreads();
    if (tid < 16) {
        float s = red[tid][0];
#pragma unroll
        for (int k = 1; k < 8; k++) s += red[tid][k];
        rowv[tid] = 1.f / s;
    }
    __syncthreads();
    const float inv1 = rowv[lg], inv2 = rowv[lg + 8];

    // ---- normalize + write attn fp32 + P bf16 ----
#pragma unroll
    for (int c = 0; c < 8; c++) {
#pragma unroll
        for (int j = 0; j < 2; j++) {
            int gn = c * 128 + w * 16 + j * 8 + lq * 2;
            size_t o1 = (size_t)r1 * SEQ + gn;
            size_t o2 = (size_t)r2 * SEQ + gn;
            float p0 = acc[c][j][0] * inv1, p1 = acc[c][j][1] * inv1;
            float p2 = acc[c][j][2] * inv2, p3 = acc[c][j][3] * inv2;
            float2 w1 = {p0, p1}, w2 = {p2, p3};
            *(float2*)(outp + o1) = w1;
            *(float2*)(outp + o2) = w2;
            *(uint32_t*)(pb + o1) = packh2(p0, p1);
            *(uint32_t*)(pb + o2) = packh2(p2, p3);
        }
    }
}

// ===========================================================================
// Ctx via mma.sync -> writes bf16 hi/lo [b*s, h*dv] directly (feeds out-proj)
// ===========================================================================
__global__ void __launch_bounds__(256)
gemm_ctx_mma(const __nv_bfloat16* __restrict__ ph,
             const __nv_bfloat16* __restrict__ vh, const __nv_bfloat16* __restrict__ vl,
             __nv_bfloat16* __restrict__ ch, __nv_bfloat16* __restrict__ cl)
{
    __shared__ __nv_bfloat16 Ps[128 * PSTR];
    __shared__ __nv_bfloat16 Vh[64 * PSTR];
    __shared__ __nv_bfloat16 Vl[64 * PSTR];

    const int bh = blockIdx.y;
    const int b_ = bh >> 3, h = bh & 7;
    const int m0 = blockIdx.x * 128;
    const __nv_bfloat16* pg = ph + (size_t)bh * SEQ * SEQ;
    const __nv_bfloat16* vg_h = vh + (size_t)bh * HD * SEQ;
    const __nv_bfloat16* vg_l = vl + (size_t)bh * HD * SEQ;

    const int tid = threadIdx.x, wid = tid >> 5, lane = tid & 31;
    const int wm = (wid >> 1) * 32;
    const int wn = (wid & 1) * 32;
    const int lg = lane >> 2;
    const int lq = lane & 3;

    float acc[2][4][4];
#pragma unroll
    for (int i = 0; i < 2; i++)
#pragma unroll
        for (int j = 0; j < 4; j++)
#pragma unroll
            for (int r = 0; r < 4; r++) acc[i][j][r] = 0.f;

    for (int k0 = 0; k0 < SEQ; k0 += 64) {
        __syncthreads();
#pragma unroll
        for (int p = 0; p < 4; p++) {
            int f = p * 256 + tid;
            int row = f >> 3, col = (f & 7) * 8;
            *(uint4*)&Ps[row * PSTR + col] =
                *(const uint4*)(pg + (size_t)(m0 + row) * SEQ + k0 + col);
        }
#pragma unroll
        for (int p = 0; p < 2; p++) {
            int f = p * 256 + tid;
            int row = f >> 3, col = (f & 7) * 8;
            *(uint4*)&Vh[row * PSTR + col] =
                *(const uint4*)(vg_h + ((size_t)row << 10) + k0 + col);
            *(uint4*)&Vl[row * PSTR + col] =
                *(const uint4*)(vg_l + ((size_t)row << 10) + k0 + col);
        }
        __syncthreads();

#pragma unroll
        for (int ks = 0; ks < 4; ks++) {
            const int kb = ks * 16;
            uint32_t a[2][4];
#pragma unroll
            for (int i = 0; i < 2; i++) {
                int r = wm + i * 16 + lg;
                int c = kb + lq * 2;
                a[i][0] = *(const uint32_t*)&Ps[r * PSTR + c];
                a[i][1] = *(const uint32_t*)&Ps[(r + 8) * PSTR + c];
                a[i][2] = *(const uint32_t*)&Ps[r * PSTR + c + 8];
                a[i][3] = *(const uint32_t*)&Ps[(r + 8) * PSTR + c + 8];
            }
#pragma unroll
            for (int j = 0; j < 4; j++) {
                int n = wn + j * 8 + lg;
                int ck = kb + lq * 2;
                uint32_t bh0 = *(const uint32_t*)&Vh[n * PSTR + ck];
                uint32_t bh1 = *(const uint32_t*)&Vh[n * PSTR + ck + 8];
                uint32_t bl0 = *(const uint32_t*)&Vl[n * PSTR + ck];
                uint32_t bl1 = *(const uint32_t*)&Vl[n * PSTR + ck + 8];
#pragma unroll
                for (int i = 0; i < 2; i++) {
                    mma_bf16(acc[i][j], a[i], bh0, bh1);
                    mma_bf16(acc[i][j], a[i], bl0, bl1);
                }
            }
        }
    }

#pragma unroll
    for (int i = 0; i < 2; i++) {
        int r1 = m0 + wm + i * 16 + lg;
        int r2 = r1 + 8;
#pragma unroll
        for (int j = 0; j < 4; j++) {
            int d = wn + j * 8 + lq * 2;
            size_t o1 = ((size_t)(b_ * SEQ) + r1) * DM + h * HD + d;
            size_t o2 = ((size_t)(b_ * SEQ) + r2) * DM + h * HD + d;
            *(uint32_t*)(ch + o1) = packh2(acc[i][j][0], acc[i][j][1]);
            *(uint32_t*)(cl + o1) = packl2(acc[i][j][0], acc[i][j][1]);
            *(uint32_t*)(ch + o2) = packh2(acc[i][j][2], acc[i][j][3]);
            *(uint32_t*)(cl + o2) = packl2(acc[i][j][2], acc[i][j][3]);
        }
    }
}

// ===========================================================================
// LayerNorm
// ===========================================================================
__global__ void __launch_bounds__(256)
layernorm_rows(const float* __restrict__ pre, const float* __restrict__ g,
               const float* __restrict__ be, float* __restrict__ out)
{
    int warp = threadIdx.x >> 5, lane = threadIdx.x & 31;
    size_t row = (size_t)blockIdx.x * 8 + warp;
    const float* p = pre + row * DM;

    float x[16];
    float s = 0.f, s2 = 0.f;
#pragma unroll
    for (int i = 0; i < 4; i++) {
        float4 v = *(const float4*)(p + i * 128 + lane * 4);
        x[i * 4 + 0] = v.x; x[i * 4 + 1] = v.y;
        x[i * 4 + 2] = v.z; x[i * 4 + 3] = v.w;
        s  += v.x + v.y + v.z + v.w;
        s2 += v.x * v.x + v.y * v.y + v.z * v.z + v.w * v.w;
    }
#pragma unroll
    for (int o = 16; o; o >>= 1) {
        s  += __shfl_xor_sync(0xffffffffu, s,  o);
        s2 += __shfl_xor_sync(0xffffffffu, s2, o);
    }
    float mu  = s  * (1.f / DM);
    float var = s2 * (1.f / DM) - mu * mu;
    float inv = rsqrtf(var + 1e-6f);

    float* po = out + row * DM;
#pragma unroll
    for (int i = 0; i < 4; i++) {
        float4 w;
        int c = i * 128 + lane * 4;
        w.x = (x[i * 4 + 0] - mu) * inv * g[c + 0] + be[c + 0];
        w.y = (x[i * 4 + 1] - mu) * inv * g[c + 1] + be[c + 1];
        w.z = (x[i * 4 + 2] - mu) * inv * g[c + 2] + be[c + 2];
        w.w = (x[i * 4 + 3] - mu) * inv * g[c + 3] + be[c + 3];
        *(float4*)(po + c) = w;
    }
}

// ---------------------------------------------------------------------------
// Launch
// ---------------------------------------------------------------------------
extern "C" void kernel_launch(void* const* d_in, const int* in_sizes, int n_in,
                              void* d_out, int out_size)
{
    const float* Q   = (const float*)d_in[0];
    const float* K   = (const float*)d_in[1];
    const float* V   = (const float*)d_in[2];
    const int*   mask = (const int*)d_in[3];
    const float* adjoin = (const float*)d_in[4];
    const float* Wq = (const float*)d_in[5];
    const float* bq = (const float*)d_in[6];
    const float* Wk = (const float*)d_in[7];
    const float* bk = (const float*)d_in[8];
    const float* Wv = (const float*)d_in[9];
    const float* bv = (const float*)d_in[10];
    const float* Wo = (const float*)d_in[11];
    const float* bo = (const float*)d_in[12];
    const float* lg = (const float*)d_in[13];
    const float* lb = (const float*)d_in[14];

    float *pb, *afb;
    cudaGetSymbolAddress((void**)&pb,  g_pre);
    cudaGetSymbolAddress((void**)&afb, g_attn_fb);

    __nv_bfloat16 *xh, *xl, *wh, *wl, *qh, *ql, *kh, *kl, *vh, *vl, *ph;
    cudaGetSymbolAddress((void**)&xh, g_xh);
    cudaGetSymbolAddress((void**)&xl, g_xl);
    cudaGetSymbolAddress((void**)&wh, g_wh);
    cudaGetSymbolAddress((void**)&wl, g_wl);
    cudaGetSymbolAddress((void**)&qh, g_qh);
    cudaGetSymbolAddress((void**)&ql, g_ql);
    cudaGetSymbolAddress((void**)&kh, g_kh);
    cudaGetSymbolAddress((void**)&kl, g_kl);
    cudaGetSymbolAddress((void**)&vh, g_vh);
    cudaGetSymbolAddress((void**)&vl, g_vl);
    cudaGetSymbolAddress((void**)&ph, g_ph);
    const size_t WSZ = (size_t)DM * DM;

    float* out0 = (float*)d_out;
    const size_t OUT0 = (size_t)BSZ * SEQ * DM;
    const size_t ATTN = (size_t)BSZ * NH * SEQ * SEQ;
    float* attn = ((size_t)out_size >= OUT0 + ATTN) ? (out0 + OUT0) : afb;

    static int attr_set = 0;
    if (!attr_set) {
        cudaFuncSetAttribute(gemm_proj_mma3<0>,
                             cudaFuncAttributeMaxDynamicSharedMemorySize, PROJ_SMEM);
        cudaFuncSetAttribute(gemm_proj_mma3<1>,
                             cudaFuncAttributeMaxDynamicSharedMemorySize, PROJ_SMEM);
        cudaFuncSetAttribute(gemm_proj_mma3<2>,
                             cudaFuncAttributeMaxDynamicSharedMemorySize, PROJ_SMEM);
        attr_set = 1;
    }

    dim3 wgrid(DM / 32, DM / 32), wblk(32, 8);
    const int XBLK = (int)(((size_t)BSZ * SEQ * DM) / 4 / 256);   // 4096
    dim3 gp(DM / 128, (BSZ * SEQ) / 128);   // (4, 64)

    // 0) Weights -> [n][k] bf16 hi/lo
    convert_w<<<wgrid, wblk>>>(Wq, wh + 0 * WSZ, wl + 0 * WSZ);
    convert_w<<<wgrid, wblk>>>(Wk, wh + 1 * WSZ, wl + 1 * WSZ);
    convert_w<<<wgrid, wblk>>>(Wv, wh + 2 * WSZ, wl + 2 * WSZ);
    convert_w<<<wgrid, wblk>>>(Wo, wh + 3 * WSZ, wl + 3 * WSZ);

    // 1) Projections -> bf16 split q/k [b,h,s,d], v [b,h,d,s]
    convert_x<<<XBLK, 256>>>(Q, xh, xl);
    gemm_proj_mma3<0><<<gp, 256, PROJ_SMEM>>>(xh, xl, wh + 0 * WSZ, wl + 0 * WSZ,
                                              bq, nullptr, nullptr, qh, ql);
    convert_x<<<XBLK, 256>>>(K, xh, xl);
    gemm_proj_mma3<0><<<gp, 256, PROJ_SMEM>>>(xh, xl, wh + 1 * WSZ, wl + 1 * WSZ,
                                              bk, nullptr, nullptr, kh, kl);
    convert_x<<<XBLK, 256>>>(V, xh, xl);
    gemm_proj_mma3<1><<<gp, 256, PROJ_SMEM>>>(xh, xl, wh + 2 * WSZ, wl + 2 * WSZ,
                                              bv, nullptr, nullptr, vh, vl);

    // 2+3) Fused scores + mask + adjoin + softmax -> attn fp32 + P bf16
    dim3 gf(SEQ / 16, BSZ * NH);    // (64, 64)
    fused_scores_softmax<<<gf, 256>>>(qh, ql, kh, kl, mask, adjoin, attn, ph);

    // 4) Context (MMA) -> bf16 hi/lo directly (xh/xl reused)
    dim3 gc(SEQ / 128, BSZ * NH);
    gemm_ctx_mma<<<gc, 256>>>(ph, vh, vl, xh, xl);

    // 5) Output projection + bias + residual(Q)
    gemm_proj_mma3<2><<<gp, 256, PROJ_SMEM>>>(xh, xl, wh + 3 * WSZ, wl + 3 * WSZ,
                                              bo, Q, pb, nullptr, nullptr);

    // 6) LayerNorm -> out
    layernorm_rows<<<(BSZ * SEQ) / 8, 256>>>(pb, lg, lb, out0);
}

// round 11
// speedup vs baseline: 1.0713x; 1.0713x over previous
#include <cuda_runtime.h>
#include <cuda_bf16.h>
#include <math.h>
#include <stdint.h>

// Problem constants
#define BSZ 8
#define SEQ 1024
#define DM  512
#define NH  8
#define HD  64
#define NEGV (-1e9f)

// ---------------------------------------------------------------------------
// Scratch
// ---------------------------------------------------------------------------
__device__ float g_pre[(size_t)BSZ * SEQ * DM];
__device__ float g_attn_fb[(size_t)BSZ * NH * SEQ * SEQ];

__device__ __nv_bfloat16 g_xh[(size_t)BSZ * SEQ * DM];   // activation / ctx hi
__device__ __nv_bfloat16 g_xl[(size_t)BSZ * SEQ * DM];   // activation / ctx lo
__device__ __nv_bfloat16 g_wh[4][(size_t)DM * DM];       // W^T hi
__device__ __nv_bfloat16 g_wl[4][(size_t)DM * DM];       // W^T lo

__device__ __nv_bfloat16 g_qh[(size_t)BSZ * NH * SEQ * HD];  // q hi [b,h,s,d]
__device__ __nv_bfloat16 g_ql[(size_t)BSZ * NH * SEQ * HD];
__device__ __nv_bfloat16 g_kh[(size_t)BSZ * NH * SEQ * HD];  // k hi [b,h,s,d]
__device__ __nv_bfloat16 g_kl[(size_t)BSZ * NH * SEQ * HD];
__device__ __nv_bfloat16 g_vh[(size_t)BSZ * NH * HD * SEQ];  // v hi [b,h,d,s]
__device__ __nv_bfloat16 g_vl[(size_t)BSZ * NH * HD * SEQ];

// ===========================================================================
// mma.sync bf16 helper (verified mapping)
// ===========================================================================
__device__ __forceinline__ void mma_bf16(float* d, const uint32_t* a,
                                         uint32_t b0, uint32_t b1)
{
    asm volatile(
        "mma.sync.aligned.m16n8k16.row.col.f32.bf16.bf16.f32 "
        "{%0,%1,%2,%3}, {%4,%5,%6,%7}, {%8,%9}, {%0,%1,%2,%3};"
        : "+f"(d[0]), "+f"(d[1]), "+f"(d[2]), "+f"(d[3])
        : "r"(a[0]), "r"(a[1]), "r"(a[2]), "r"(a[3]), "r"(b0), "r"(b1));
}

__device__ __forceinline__ uint32_t packh2(float x, float y) {
    __nv_bfloat162 p = __halves2bfloat162(__float2bfloat16(x), __float2bfloat16(y));
    return *(uint32_t*)&p;
}
__device__ __forceinline__ uint32_t packl2(float x, float y) {
    __nv_bfloat16 hx = __float2bfloat16(x), hy = __float2bfloat16(y);
    __nv_bfloat162 p = __halves2bfloat162(
        __float2bfloat16(x - __bfloat162float(hx)),
        __float2bfloat16(y - __bfloat162float(hy)));
    return *(uint32_t*)&p;
}

// ===========================================================================
// Pre-convert kernels (proven)
// ===========================================================================
__global__ void __launch_bounds__(256)
convert_x(const float* __restrict__ A, __nv_bfloat16* __restrict__ hi,
          __nv_bfloat16* __restrict__ lo)
{
    size_t i = ((size_t)blockIdx.x * 256 + threadIdx.x) * 4;
    float4 v = *(const float4*)(A + i);
    uint2 uh = {packh2(v.x, v.y), packh2(v.z, v.w)};
    uint2 ul = {packl2(v.x, v.y), packl2(v.z, v.w)};
    *(uint2*)(hi + i) = uh;
    *(uint2*)(lo + i) = ul;
}

__global__ void __launch_bounds__(256)
convert_w(const float* __restrict__ W, __nv_bfloat16* __restrict__ th,
          __nv_bfloat16* __restrict__ tl)
{
    __shared__ float tile[32][33];
    int tx = threadIdx.x, ty = threadIdx.y;
    int n_in = blockIdx.x * 32 + tx;
    int k0 = blockIdx.y * 32;
#pragma unroll
    for (int j = ty; j < 32; j += 8)
        tile[j][tx] = W[(size_t)(k0 + j) * DM + n_in];
    __syncthreads();
#pragma unroll
    for (int j = ty; j < 32; j += 8) {
        int n = blockIdx.x * 32 + j;
        int k = k0 + tx;
        float v = tile[tx][j];
        __nv_bfloat16 h = __float2bfloat16(v);
        th[(size_t)n * DM + k] = h;
        tl[(size_t)n * DM + k] = __float2bfloat16(v - __bfloat162float(h));
    }
}

// ===========================================================================
// Projection GEMM via mma.sync (proven R8)
// MODE 0: bf16 hi/lo out [b,h,s,d]; MODE 1: bf16 hi/lo [b,h,d,s];
// MODE 2: fp32 + resid row-major
// ===========================================================================
#define PSTR 72
#define PANEL (128 * PSTR)
#define PROJ_SMEM (4 * PANEL * 2)   // 73728 B

template<int MODE>
__global__ void __launch_bounds__(256)
gemm_proj_mma3(const __nv_bfloat16* __restrict__ Ahg,
               const __nv_bfloat16* __restrict__ Alg,
               const __nv_bfloat16* __restrict__ Bhg,
               const __nv_bfloat16* __restrict__ Blg,
               const float* __restrict__ bias, const float* __restrict__ resid,
               float* __restrict__ outf,
               __nv_bfloat16* __restrict__ outh, __nv_bfloat16* __restrict__ outl)
{
    extern __shared__ __nv_bfloat16 sb[];
    __nv_bfloat16* Ah = sb;
    __nv_bfloat16* Al = Ah + PANEL;
    __nv_bfloat16* Bh = Al + PANEL;
    __nv_bfloat16* Bl = Bh + PANEL;

    const int tid = threadIdx.x, wid = tid >> 5, lane = tid & 31;
    const int m0 = blockIdx.y * 128, n0 = blockIdx.x * 128;
    const int wm = (wid >> 2) * 64;
    const int wn = (wid & 3) * 32;
    const int lg = lane >> 2;
    const int lq = lane & 3;

    float acc[4][4][4];
#pragma unroll
    for (int i = 0; i < 4; i++)
#pragma unroll
        for (int j = 0; j < 4; j++)
#pragma unroll
            for (int r = 0; r < 4; r++) acc[i][j][r] = 0.f;

    const int sr = tid >> 3;
    const int sc = (tid & 7) * 8;

    for (int kc = 0; kc < 8; kc++) {
        const int k0 = kc * 64;
        __syncthreads();
#pragma unroll
        for (int p = 0; p < 4; p++) {
            int row = sr + p * 32;
            *(uint4*)&Ah[row * PSTR + sc] =
                *(const uint4*)(Ahg + (size_t)(m0 + row) * DM + k0 + sc);
            *(uint4*)&Al[row * PSTR + sc] =
                *(const uint4*)(Alg + (size_t)(m0 + row) * DM + k0 + sc);
            *(uint4*)&Bh[row * PSTR + sc] =
                *(const uint4*)(Bhg + (size_t)(n0 + row) * DM + k0 + sc);
            *(uint4*)&Bl[row * PSTR + sc] =
                *(const uint4*)(Blg + (size_t)(n0 + row) * DM + k0 + sc);
        }
        __syncthreads();

#pragma unroll
        for (int ks = 0; ks < 4; ks++) {
            const int kb = ks * 16;
            uint32_t ah[4][4], al[4][4];
#pragma unroll
            for (int i = 0; i < 4; i++) {
                int r = wm + i * 16 + lg;
                int c = kb + lq * 2;
                ah[i][0] = *(const uint32_t*)&Ah[r * PSTR + c];
                ah[i][1] = *(const uint32_t*)&Ah[(r + 8) * PSTR + c];
                ah[i][2] = *(const uint32_t*)&Ah[r * PSTR + c + 8];
                ah[i][3] = *(const uint32_t*)&Ah[(r + 8) * PSTR + c + 8];
                al[i][0] = *(const uint32_t*)&Al[r * PSTR + c];
                al[i][1] = *(const uint32_t*)&Al[(r + 8) * PSTR + c];
                al[i][2] = *(const uint32_t*)&Al[r * PSTR + c + 8];
                al[i][3] = *(const uint32_t*)&Al[(r + 8) * PSTR + c + 8];
            }
#pragma unroll
            for (int j = 0; j < 4; j++) {
                int n = wn + j * 8 + lg;
                int ck = kb + lq * 2;
                uint32_t bh0 = *(const uint32_t*)&Bh[n * PSTR + ck];
                uint32_t bh1 = *(const uint32_t*)&Bh[n * PSTR + ck + 8];
                uint32_t bl0 = *(const uint32_t*)&Bl[n * PSTR + ck];
                uint32_t bl1 = *(const uint32_t*)&Bl[n * PSTR + ck + 8];
#pragma unroll
                for (int i = 0; i < 4; i++) {
                    mma_bf16(acc[i][j], ah[i], bh0, bh1);
                    mma_bf16(acc[i][j], ah[i], bl0, bl1);
                    mma_bf16(acc[i][j], al[i], bh0, bh1);
                }
            }
        }
    }

#pragma unroll
    for (int i = 0; i < 4; i++) {
        int r1 = m0 + wm + i * 16 + lg;
        int r2 = r1 + 8;
#pragma unroll
        for (int j = 0; j < 4; j++) {
            int n = n0 + wn + j * 8 + lq * 2;
            float b0 = bias[n], b1 = bias[n + 1];
            float v00 = acc[i][j][0] + b0, v01 = acc[i][j][1] + b1;
            float v10 = acc[i][j][2] + b0, v11 = acc[i][j][3] + b1;
            if (MODE == 2) {
                float2 q1 = *(const float2*)(resid + (size_t)r1 * DM + n);
                float2 q2 = *(const float2*)(resid + (size_t)r2 * DM + n);
                float2 o1 = {v00 + q1.x, v01 + q1.y};
                float2 o2 = {v10 + q2.x, v11 + q2.y};
                *(float2*)(outf + (size_t)r1 * DM + n) = o1;
                *(float2*)(outf + (size_t)r2 * DM + n) = o2;
            } else if (MODE == 0) {
                int h = n >> 6, d = n & (HD - 1);
                int b1_ = r1 >> 10, s1 = r1 & (SEQ - 1);
                int b2_ = r2 >> 10, s2 = r2 & (SEQ - 1);
                size_t o1 = (((size_t)(b1_ * NH + h) * SEQ + s1) << 6) + d;
                size_t o2 = (((size_t)(b2_ * NH + h) * SEQ + s2) << 6) + d;
                *(uint32_t*)(outh + o1) = packh2(v00, v01);
                *(uint32_t*)(outl + o1) = packl2(v00, v01);
                *(uint32_t*)(outh + o2) = packh2(v10, v11);
                *(uint32_t*)(outl + o2) = packl2(v10, v11);
            } else {
                int h = n >> 6, d = n & (HD - 1);
                int b1_ = r1 >> 10, s1 = r1 & (SEQ - 1);
                int b2_ = r2 >> 10, s2 = r2 & (SEQ - 1);
                size_t base1 = (((size_t)(b1_ * NH + h) * HD + d) << 10) + s1;
                size_t base2 = (((size_t)(b2_ * NH + h) * HD + d) << 10) + s2;
                __nv_bfloat16 h00 = __float2bfloat16(v00);
                __nv_bfloat16 h01 = __float2bfloat16(v01);
                __nv_bfloat16 h10 = __float2bfloat16(v10);
                __nv_bfloat16 h11 = __float2bfloat16(v11);
                outh[base1]          = h00;
                outh[base1 + SEQ]    = h01;
                outh[base2]          = h10;
                outh[base2 + SEQ]    = h11;
                outl[base1]       = __float2bfloat16(v00 - __bfloat162float(h00));
                outl[base1 + SEQ] = __float2bfloat16(v01 - __bfloat162float(h01));
                outl[base2]       = __float2bfloat16(v10 - __bfloat162float(h10));
                outl[base2 + SEQ] = __float2bfloat16(v11 - __bfloat162float(h11));
            }
        }
    }
}

// ===========================================================================
// FUSED flash-style attention: two passes over K, 128x128 proven tiling.
// Pass A: scores (recomputed, not stored) -> online rowmax/rowsum.
// Pass B: recompute scores (bit-identical), exp*inv -> write fp32 attn once,
//         bf16 P tile in smem -> ctx MMA vs staged V -> ctx bf16 hi/lo out.
// CTA: (bh, 128 q-rows). 256 thr / 8 warps.
// ===========================================================================
#define PT_STR 136
// bf16-unit offsets
#define QH_O 0
#define QL_O 9216
#define KH_O 18432
#define KL_O 27648
#define PT_O 36864
#define VH_O 54272
#define VL_O 62976
#define FA_FLOAT_BYTE 143360        // byte offset of float arrays
#define FA_SMEM (143360 + 2048 + 2048 + 512 + 512)   // 148480 B

__global__ void __launch_bounds__(256)
fused_attention(const __nv_bfloat16* __restrict__ qhg, const __nv_bfloat16* __restrict__ qlg,
                const __nv_bfloat16* __restrict__ khg, const __nv_bfloat16* __restrict__ klg,
                const __nv_bfloat16* __restrict__ vhg, const __nv_bfloat16* __restrict__ vlg,
                const int* __restrict__ mask, const float* __restrict__ adjoin,
                float* __restrict__ attn,
                __nv_bfloat16* __restrict__ ch, __nv_bfloat16* __restrict__ cl)
{
    extern __shared__ char smraw[];
    __nv_bfloat16* sbm = (__nv_bfloat16*)smraw;
    __nv_bfloat16* Qh = sbm + QH_O;
    __nv_bfloat16* Ql = sbm + QL_O;
    __nv_bfloat16* Kh = sbm + KH_O;
    __nv_bfloat16* Kl = sbm + KL_O;
    __nv_bfloat16* Pt = sbm + PT_O;
    __nv_bfloat16* Vh = sbm + VH_O;
    __nv_bfloat16* Vl = sbm + VL_O;
    float* redm   = (float*)(smraw + FA_FLOAT_BYTE);          // [128][4]
    float* reds   = (float*)(smraw + FA_FLOAT_BYTE + 2048);   // [128][4]
    float* rowm   = (float*)(smraw + FA_FLOAT_BYTE + 4096);   // [128]
    float* rowinv = (float*)(smraw + FA_FLOAT_BYTE + 4608);   // [128]

    const int bh = blockIdx.y;
    const int b_ = bh >> 3, h = bh & 7;
    const int m0 = blockIdx.x * 128;

    const __nv_bfloat16* qg_h = qhg + (size_t)bh * SEQ * HD;
    const __nv_bfloat16* qg_l = qlg + (size_t)bh * SEQ * HD;
    const __nv_bfloat16* kg_h = khg + (size_t)bh * SEQ * HD;
    const __nv_bfloat16* kg_l = klg + (size_t)bh * SEQ * HD;
    const __nv_bfloat16* vg_h = vhg + (size_t)bh * HD * SEQ;
    const __nv_bfloat16* vg_l = vlg + (size_t)bh * HD * SEQ;
    float* outp = attn + (size_t)bh * SEQ * SEQ;
    const int*   mb = mask   + (size_t)b_ * SEQ * SEQ;
    const float* ab = adjoin + (size_t)b_ * SEQ * SEQ;

    const int tid = threadIdx.x, w = tid >> 5, lane = tid & 31;
    const int lg = lane >> 2, lq = lane & 3;
    const int wm  = (w >> 2) * 64;   // scores partition
    const int wn  = (w & 3) * 32;
    const int wm2 = (w >> 1) * 32;   // ctx partition
    const int wn2 = (w & 1) * 32;

    // stage Q once (128 x 64 hi/lo)
    {
        const int sr = tid >> 3, sc = (tid & 7) * 8;
#pragma unroll
        for (int p = 0; p < 4; p++) {
            int row = sr + p * 32;
            *(uint4*)&Qh[row * PSTR + sc] = *(const uint4*)(qg_h + (size_t)(m0 + row) * HD + sc);
            *(uint4*)&Ql[row * PSTR + sc] = *(const uint4*)(qg_l + (size_t)(m0 + row) * HD + sc);
        }
    }

    float mrun[8], srun[8];
#pragma unroll
    for (int r = 0; r < 8; r++) { mrun[r] = -INFINITY; srun[r] = 0.f; }

    // =================== PASS A: online max/sum ===================
    for (int c = 0; c < 8; c++) {
        __syncthreads();
        {
            const int sr = tid >> 3, sc = (tid & 7) * 8;
#pragma unroll
            for (int p = 0; p < 4; p++) {
                int row = sr + p * 32;
                *(uint4*)&Kh[row * PSTR + sc] =
                    *(const uint4*)(kg_h + (size_t)(c * 128 + row) * HD + sc);
                *(uint4*)&Kl[row * PSTR + sc] =
                    *(const uint4*)(kg_l + (size_t)(c * 128 + row) * HD + sc);
            }
        }
        __syncthreads();

        float acc[4][4][4];
#pragma unroll
        for (int i = 0; i < 4; i++)
#pragma unroll
            for (int j = 0; j < 4; j++)
#pragma unroll
                for (int r = 0; r < 4; r++) acc[i][j][r] = 0.f;

#pragma unroll
        for (int ks = 0; ks < 4; ks++) {
            const int kb = ks * 16;
            uint32_t ah[4][4], al[4][4];
#pragma unroll
            for (int i = 0; i < 4; i++) {
                int r = wm + i * 16 + lg;
                int cc = kb + lq * 2;
                ah[i][0] = *(const uint32_t*)&Qh[r * PSTR + cc];
                ah[i][1] = *(const uint32_t*)&Qh[(r + 8) * PSTR + cc];
                ah[i][2] = *(const uint32_t*)&Qh[r * PSTR + cc + 8];
                ah[i][3] = *(const uint32_t*)&Qh[(r + 8) * PSTR + cc + 8];
                al[i][0] = *(const uint32_t*)&Ql[r * PSTR + cc];
                al[i][1] = *(const uint32_t*)&Ql[(r + 8) * PSTR + cc];
                al[i][2] = *(const uint32_t*)&Ql[r * PSTR + cc + 8];
                al[i][3] = *(const uint32_t*)&Ql[(r + 8) * PSTR + cc + 8];
            }
#pragma unroll
            for (int j = 0; j < 4; j++) {
                int n = wn + j * 8 + lg;
                int ck = kb + lq * 2;
                uint32_t bh0 = *(const uint32_t*)&Kh[n * PSTR + ck];
                uint32_t bh1 = *(const uint32_t*)&Kh[n * PSTR + ck + 8];
                uint32_t bl0 = *(const uint32_t*)&Kl[n * PSTR + ck];
                uint32_t bl1 = *(const uint32_t*)&Kl[n * PSTR + ck + 8];
#pragma unroll
                for (int i = 0; i < 4; i++) {
                    mma_bf16(acc[i][j], ah[i], bh0, bh1);
                    mma_bf16(acc[i][j], ah[i], bl0, bl1);
                    mma_bf16(acc[i][j], al[i], bh0, bh1);
                }
            }
        }

        // epilogue: mask+adjoin, online update
#pragma unroll
        for (int i = 0; i < 4; i++) {
            int r1 = m0 + wm + i * 16 + lg;
            int r2 = r1 + 8;
            float x1[8], x2[8];
#pragma unroll
            for (int j = 0; j < 4; j++) {
                int gn = c * 128 + wn + j * 8 + lq * 2;
                size_t o1 = (size_t)r1 * SEQ + gn;
                size_t o2 = (size_t)r2 * SEQ + gn;
                int2   m1 = *(const int2*)(mb + o1);
                int2   m2 = *(const int2*)(mb + o2);
                float2 a1 = *(const float2*)(ab + o1);
                float2 a2 = *(const float2*)(ab + o2);
                x1[j * 2 + 0] = (m1.x ? NEGV : acc[i][j][0] * 0.125f) + a1.x;
                x1[j * 2 + 1] = (m1.y ? NEGV : acc[i][j][1] * 0.125f) + a1.y;
                x2[j * 2 + 0] = (m2.x ? NEGV : acc[i][j][2] * 0.125f) + a2.x;
                x2[j * 2 + 1] = (m2.y ? NEGV : acc[i][j][3] * 0.125f) + a2.y;
            }
            float ml1 = x1[0], ml2 = x2[0];
#pragma unroll
            for (int k = 1; k < 8; k++) { ml1 = fmaxf(ml1, x1[k]); ml2 = fmaxf(ml2, x2[k]); }
            float sl1 = 0.f, sl2 = 0.f;
#pragma unroll
            for (int k = 0; k < 8; k++) {
                sl1 += __expf(x1[k] - ml1);
                sl2 += __expf(x2[k] - ml2);
            }
            float mn1 = fmaxf(mrun[2 * i], ml1);
            srun[2 * i] = srun[2 * i] * __expf(mrun[2 * i] - mn1) + sl1 * __expf(ml1 - mn1);
            mrun[2 * i] = mn1;
            float mn2 = fmaxf(mrun[2 * i + 1], ml2);
            srun[2 * i + 1] = srun[2 * i + 1] * __expf(mrun[2 * i + 1] - mn2) + sl2 * __expf(ml2 - mn2);
            mrun[2 * i + 1] = mn2;
        }
    }

    // combine across lq (4 lanes share rows)
#pragma unroll
    for (int off = 1; off <= 2; off <<= 1) {
#pragma unroll
        for (int r = 0; r < 8; r++) {
            float mo = __shfl_xor_sync(0xffffffffu, mrun[r], off);
            float so = __shfl_xor_sync(0xffffffffu, srun[r], off);
            float mn = fmaxf(mrun[r], mo);
            srun[r] = srun[r] * __expf(mrun[r] - mn) + so * __expf(mo - mn);
            mrun[r] = mn;
        }
    }
    if (lq == 0) {
#pragma unroll
        for (int i = 0; i < 4; i++) {
            int rl = wm + i * 16 + lg;
            redm[rl * 4 + (w & 3)] = mrun[2 * i];
            reds[rl * 4 + (w & 3)] = srun[2 * i];
            redm[(rl + 8) * 4 + (w & 3)] = mrun[2 * i + 1];
            reds[(rl + 8) * 4 + (w & 3)] = srun[2 * i + 1];
        }
    }
    __syncthreads();
    if (tid < 128) {
        float m = redm[tid * 4 + 0];
        float s = reds[tid * 4 + 0];
#pragma unroll
        for (int k = 1; k < 4; k++) {
            float mo = redm[tid * 4 + k], so = reds[tid * 4 + k];
            float mn = fmaxf(m, mo);
            s = s * __expf(m - mn) + so * __expf(mo - mn);
            m = mn;
        }
        rowm[tid] = m;
        rowinv[tid] = 1.f / s;
    }
    __syncthreads();

    float rm[8], rv[8];
#pragma unroll
    for (int i = 0; i < 4; i++) {
        int rl = wm + i * 16 + lg;
        rm[2 * i] = rowm[rl];       rv[2 * i] = rowinv[rl];
        rm[2 * i + 1] = rowm[rl + 8]; rv[2 * i + 1] = rowinv[rl + 8];
    }

    float cacc[2][4][4];
#pragma unroll
    for (int i = 0; i < 2; i++)
#pragma unroll
        for (int j = 0; j < 4; j++)
#pragma unroll
            for (int r = 0; r < 4; r++) cacc[i][j][r] = 0.f;

    // =================== PASS B: recompute, write attn, ctx ===================
    for (int c = 0; c < 8; c++) {
        __syncthreads();
        {
            const int sr = tid >> 3, sc = (tid & 7) * 8;
#pragma unroll
            for (int p = 0; p < 4; p++) {
                int row = sr + p * 32;
                *(uint4*)&Kh[row * PSTR + sc] =
                    *(const uint4*)(kg_h + (size_t)(c * 128 + row) * HD + sc);
                *(uint4*)&Kl[row * PSTR + sc] =
                    *(const uint4*)(kg_l + (size_t)(c * 128 + row) * HD + sc);
            }
            // V chunk: 64 d-rows x 128 k-cols = 1024 uint4 (FIXED: p < 4)
#pragma unroll
            for (int p = 0; p < 4; p++) {
                int f = p * 256 + tid;
                int row = f >> 4;
                int col = (f & 15) * 8;
                *(uint4*)&Vh[row * PT_STR + col] =
                    *(const uint4*)(vg_h + ((size_t)row << 10) + c * 128 + col);
                *(uint4*)&Vl[row * PT_STR + col] =
                    *(const uint4*)(vg_l + ((size_t)row << 10) + c * 128 + col);
            }
        }
        __syncthreads();

        float acc[4][4][4];
#pragma unroll
        for (int i = 0; i < 4; i++)
#pragma unroll
            for (int j = 0; j < 4; j++)
#pragma unroll
                for (int r = 0; r < 4; r++) acc[i][j][r] = 0.f;

#pragma unroll
        for (int ks = 0; ks < 4; ks++) {
            const int kb = ks * 16;
            uint32_t ah[4][4], al[4][4];
#pragma unroll
            for (int i = 0; i < 4; i++) {
                int r = wm + i * 16 + lg;
                int cc = kb + lq * 2;
                ah[i][0] = *(const uint32_t*)&Qh[r * PSTR + cc];
                ah[i][1] = *(const uint32_t*)&Qh[(r + 8) * PSTR + cc];
                ah[i][2] = *(const uint32_t*)&Qh[r * PSTR + cc + 8];
                ah[i][3] = *(const uint32_t*)&Qh[(r + 8) * PSTR + cc + 8];
                al[i][0] = *(const uint32_t*)&Ql[r * PSTR + cc];
                al[i][1] = *(const uint32_t*)&Ql[(r + 8) * PSTR + cc];
                al[i][2] = *(const uint32_t*)&Ql[r * PSTR + cc + 8];
                al[i][3] = *(const uint32_t*)&Ql[(r + 8) * PSTR + cc + 8];
            }
#pragma unroll
            for (int j = 0; j < 4; j++) {
                int n = wn + j * 8 + lg;
                int ck = kb + lq * 2;
                uint32_t bh0 = *(const uint32_t*)&Kh[n * PSTR + ck];
                uint32_t bh1 = *(const uint32_t*)&Kh[n * PSTR + ck + 8];
                uint32_t bl0 = *(const uint32_t*)&Kl[n * PSTR + ck];
                uint32_t bl1 = *(const uint32_t*)&Kl[n * PSTR + ck + 8];
#pragma unroll
                for (int i = 0; i < 4; i++) {
                    mma_bf16(acc[i][j], ah[i], bh0, bh1);
                    mma_bf16(acc[i][j], ah[i], bl0, bl1);
                    mma_bf16(acc[i][j], al[i], bh0, bh1);
                }
            }
        }

        // epilogue: p = exp(x - m) * inv; write attn fp32; P tile to smem
#pragma unroll
        for (int i = 0; i < 4; i++) {
            int r1 = m0 + wm + i * 16 + lg;
            int r2 = r1 + 8;
            int rl = wm + i * 16 + lg;
#pragma unroll
            for (int j = 0; j < 4; j++) {
                int cn = wn + j * 8 + lq * 2;          // col within chunk
                int gn = c * 128 + cn;
                size_t o1 = (size_t)r1 * SEQ + gn;
                size_t o2 = (size_t)r2 * SEQ + gn;
                int2   m1 = *(const int2*)(mb + o1);
                int2   m2 = *(const int2*)(mb + o2);
                float2 a1 = *(const float2*)(ab + o1);
                float2 a2 = *(const float2*)(ab + o2);
                float x0 = (m1.x ? NEGV : acc[i][j][0] * 0.125f) + a1.x;
                float x1v = (m1.y ? NEGV : acc[i][j][1] * 0.125f) + a1.y;
                float x2v = (m2.x ? NEGV : acc[i][j][2] * 0.125f) + a2.x;
                float x3 = (m2.y ? NEGV : acc[i][j][3] * 0.125f) + a2.y;
                float p0 = __expf(x0 - rm[2 * i]) * rv[2 * i];
                float p1 = __expf(x1v - rm[2 * i]) * rv[2 * i];
                float p2 = __expf(x2v - rm[2 * i + 1]) * rv[2 * i + 1];
                float p3 = __expf(x3 - rm[2 * i + 1]) * rv[2 * i + 1];
                float2 w1 = {p0, p1}, w2 = {p2, p3};
                *(float2*)(outp + o1) = w1;
                *(float2*)(outp + o2) = w2;
                *(uint32_t*)&Pt[rl * PT_STR + cn]       = packh2(p0, p1);
                *(uint32_t*)&Pt[(rl + 8) * PT_STR + cn] = packh2(p2, p3);
            }
        }
        __syncthreads();

        // ctx MMA: cacc += P(tile) @ V(chunk)^T  (V stored [d][k])
#pragma unroll
        for (int ks = 0; ks < 8; ks++) {
            const int ck = ks * 16 + lq * 2;
            uint32_t af[2][4];
#pragma unroll
            for (int i = 0; i < 2; i++) {
                int r = wm2 + i * 16 + lg;
                af[i][0] = *(const uint32_t*)&Pt[r * PT_STR + ck];
                af[i][1] = *(const uint32_t*)&Pt[(r + 8) * PT_STR + ck];
                af[i][2] = *(const uint32_t*)&Pt[r * PT_STR + ck + 8];
                af[i][3] = *(const uint32_t*)&Pt[(r + 8) * PT_STR + ck + 8];
            }
#pragma unroll
            for (int j = 0; j < 4; j++) {
                int n = wn2 + j * 8 + lg;
                uint32_t bh0 = *(const uint32_t*)&Vh[n * PT_STR + ck];
                uint32_t bh1 = *(const uint32_t*)&Vh[n * PT_STR + ck + 8];
                uint32_t bl0 = *(const uint32_t*)&Vl[n * PT_STR + ck];
                uint32_t bl1 = *(const uint32_t*)&Vl[n * PT_STR + ck + 8];
#pragma unroll
                for (int i = 0; i < 2; i++) {
                    mma_bf16(cacc[i][j], af[i], bh0, bh1);
                    mma_bf16(cacc[i][j], af[i], bl0, bl1);
                }
            }
        }
    }

    // ctx epilogue -> bf16 hi/lo [b*s][h*dv]
#pragma unroll
    for (int i = 0; i < 2; i++) {
        int r1 = m0 + wm2 + i * 16 + lg;
        int r2 = r1 + 8;
#pragma unroll
        for (int j = 0; j < 4; j++) {
            int d = wn2 + j * 8 + lq * 2;
            size_t o1 = ((size_t)(b_ * SEQ) + r1) * DM + h * HD + d;
            size_t o2 = ((size_t)(b_ * SEQ) + r2) * DM + h * HD + d;
            *(uint32_t*)(ch + o1) = packh2(cacc[i][j][0], cacc[i][j][1]);
            *(uint32_t*)(cl + o1) = packl2(cacc[i][j][0], cacc[i][j][1]);
            *(uint32_t*)(ch + o2) = packh2(cacc[i][j][2], cacc[i][j][3]);
            *(uint32_t*)(cl + o2) = packl2(cacc[i][j][2], cacc[i][j][3]);
        }
    }
}

// ===========================================================================
// LayerNorm
// ===========================================================================
__global__ void __launch_bounds__(256)
layernorm_rows(const float* __restrict__ pre, const float* __restrict__ g,
               const float* __restrict__ be, float* __restrict__ out)
{
    int warp = threadIdx.x >> 5, lane = threadIdx.x & 31;
    size_t row = (size_t)blockIdx.x * 8 + warp;
    const float* p = pre + row * DM;

    float x[16];
    float s = 0.f, s2 = 0.f;
#pragma unroll
    for (int i = 0; i < 4; i++) {
        float4 v = *(const float4*)(p + i * 128 + lane * 4);
        x[i * 4 + 0] = v.x; x[i * 4 + 1] = v.y;
        x[i * 4 + 2] = v.z; x[i * 4 + 3] = v.w;
        s  += v.x + v.y + v.z + v.w;
        s2 += v.x * v.x + v.y * v.y + v.z * v.z + v.w * v.w;
    }
#pragma unroll
    for (int o = 16; o; o >>= 1) {
        s  += __shfl_xor_sync(0xffffffffu, s,  o);
        s2 += __shfl_xor_sync(0xffffffffu, s2, o);
    }
    float mu  = s  * (1.f / DM);
    float var = s2 * (1.f / DM) - mu * mu;
    float inv = rsqrtf(var + 1e-6f);

    float* po = out + row * DM;
#pragma unroll
    for (int i = 0; i < 4; i++) {
        float4 w;
        int c = i * 128 + lane * 4;
        w.x = (x[i * 4 + 0] - mu) * inv * g[c + 0] + be[c + 0];
        w.y = (x[i * 4 + 1] - mu) * inv * g[c + 1] + be[c + 1];
        w.z = (x[i * 4 + 2] - mu) * inv * g[c + 2] + be[c + 2];
        w.w = (x[i * 4 + 3] - mu) * inv * g[c + 3] + be[c + 3];
        *(float4*)(po + c) = w;
    }
}

// ---------------------------------------------------------------------------
// Launch
// ---------------------------------------------------------------------------
extern "C" void kernel_launch(void* const* d_in, const int* in_sizes, int n_in,
                              void* d_out, int out_size)
{
    const float* Q   = (const float*)d_in[0];
    const float* K   = (const float*)d_in[1];
    const float* V   = (const float*)d_in[2];
    const int*   mask = (const int*)d_in[3];
    const float* adjoin = (const float*)d_in[4];
    const float* Wq = (const float*)d_in[5];
    const float* bq = (const float*)d_in[6];
    const float* Wk = (const float*)d_in[7];
    const float* bk = (const float*)d_in[8];
    const float* Wv = (const float*)d_in[9];
    const float* bv = (const float*)d_in[10];
    const float* Wo = (const float*)d_in[11];
    const float* bo = (const float*)d_in[12];
    const float* lg = (const float*)d_in[13];
    const float* lb = (const float*)d_in[14];

    float *pb, *afb;
    cudaGetSymbolAddress((void**)&pb,  g_pre);
    cudaGetSymbolAddress((void**)&afb, g_attn_fb);

    __nv_bfloat16 *xh, *xl, *wh, *wl, *qh, *ql, *kh, *kl, *vh, *vl;
    cudaGetSymbolAddress((void**)&xh, g_xh);
    cudaGetSymbolAddress((void**)&xl, g_xl);
    cudaGetSymbolAddress((void**)&wh, g_wh);
    cudaGetSymbolAddress((void**)&wl, g_wl);
    cudaGetSymbolAddress((void**)&qh, g_qh);
    cudaGetSymbolAddress((void**)&ql, g_ql);
    cudaGetSymbolAddress((void**)&kh, g_kh);
    cudaGetSymbolAddress((void**)&kl, g_kl);
    cudaGetSymbolAddress((void**)&vh, g_vh);
    cudaGetSymbolAddress((void**)&vl, g_vl);
    const size_t WSZ = (size_t)DM * DM;

    float* out0 = (float*)d_out;
    const size_t OUT0 = (size_t)BSZ * SEQ * DM;
    const size_t ATTN = (size_t)BSZ * NH * SEQ * SEQ;
    float* attn = ((size_t)out_size >= OUT0 + ATTN) ? (out0 + OUT0) : afb;

    static int attr_set = 0;
    if (!attr_set) {
        cudaFuncSetAttribute(gemm_proj_mma3<0>,
                             cudaFuncAttributeMaxDynamicSharedMemorySize, PROJ_SMEM);
        cudaFuncSetAttribute(gemm_proj_mma3<1>,
                             cudaFuncAttributeMaxDynamicSharedMemorySize, PROJ_SMEM);
        cudaFuncSetAttribute(gemm_proj_mma3<2>,
                             cudaFuncAttributeMaxDynamicSharedMemorySize, PROJ_SMEM);
        cudaFuncSetAttribute(fused_attention,
                             cudaFuncAttributeMaxDynamicSharedMemorySize, FA_SMEM);
        attr_set = 1;
    }

    dim3 wgrid(DM / 32, DM / 32), wblk(32, 8);
    const int XBLK = (int)(((size_t)BSZ * SEQ * DM) / 4 / 256);   // 4096
    dim3 gp(DM / 128, (BSZ * SEQ) / 128);   // (4, 64)

    // 0) Weights -> [n][k] bf16 hi/lo
    convert_w<<<wgrid, wblk>>>(Wq, wh + 0 * WSZ, wl + 0 * WSZ);
    convert_w<<<wgrid, wblk>>>(Wk, wh + 1 * WSZ, wl + 1 * WSZ);
    convert_w<<<wgrid, wblk>>>(Wv, wh + 2 * WSZ, wl + 2 * WSZ);
    convert_w<<<wgrid, wblk>>>(Wo, wh + 3 * WSZ, wl + 3 * WSZ);

    // 1) Projections -> bf16 split q/k [b,h,s,d], v [b,h,d,s]
    convert_x<<<XBLK, 256>>>(Q, xh, xl);
    gemm_proj_mma3<0><<<gp, 256, PROJ_SMEM>>>(xh, xl, wh + 0 * WSZ, wl + 0 * WSZ,
                                              bq, nullptr, nullptr, qh, ql);
    convert_x<<<XBLK, 256>>>(K, xh, xl);
    gemm_proj_mma3<0><<<gp, 256, PROJ_SMEM>>>(xh, xl, wh + 1 * WSZ, wl + 1 * WSZ,
                                              bk, nullptr, nullptr, kh, kl);
    convert_x<<<XBLK, 256>>>(V, xh, xl);
    gemm_proj_mma3<1><<<gp, 256, PROJ_SMEM>>>(xh, xl, wh + 2 * WSZ, wl + 2 * WSZ,
                                              bv, nullptr, nullptr, vh, vl);

    // 2) Fused attention: scores+mask+adjoin+softmax+attn-write+ctx
    //    ctx bf16 hi/lo lands in xh/xl (reused as out-proj input)
    dim3 gfa(SEQ / 128, BSZ * NH);   // (8, 64)
    fused_attention<<<gfa, 256, FA_SMEM>>>(qh, ql, kh, kl, vh, vl,
                                           mask, adjoin, attn, xh, xl);

    // 3) Output projection + bias + residual(Q)
    gemm_proj_mma3<2><<<gp, 256, PROJ_SMEM>>>(xh, xl, wh + 3 * WSZ, wl + 3 * WSZ,
                                              bo, Q, pb, nullptr, nullptr);

    // 4) LayerNorm -> out
    layernorm_rows<<<(BSZ * SEQ) / 8, 256>>>(pb, lg, lb, out0);
}

// round 12
// speedup vs baseline: 1.0922x; 1.0195x over previous
#include <cuda_runtime.h>
#include <cuda_bf16.h>
#include <math.h>
#include <stdint.h>

// Problem constants
#define BSZ 8
#define SEQ 1024
#define DM  512
#define NH  8
#define HD  64
#define NEGV (-1e9f)

// ---------------------------------------------------------------------------
// Scratch
// ---------------------------------------------------------------------------
__device__ float g_pre[(size_t)BSZ * SEQ * DM];
__device__ float g_attn_fb[(size_t)BSZ * NH * SEQ * SEQ];

__device__ __nv_bfloat16 g_xh[(size_t)BSZ * SEQ * DM];   // activation / ctx hi
__device__ __nv_bfloat16 g_xl[(size_t)BSZ * SEQ * DM];   // activation / ctx lo
__device__ __nv_bfloat16 g_wh[4][(size_t)DM * DM];       // W^T hi
__device__ __nv_bfloat16 g_wl[4][(size_t)DM * DM];       // W^T lo

__device__ __nv_bfloat16 g_qh[(size_t)BSZ * NH * SEQ * HD];  // q hi [b,h,s,d]
__device__ __nv_bfloat16 g_ql[(size_t)BSZ * NH * SEQ * HD];
__device__ __nv_bfloat16 g_kh[(size_t)BSZ * NH * SEQ * HD];  // k hi [b,h,s,d]
__device__ __nv_bfloat16 g_kl[(size_t)BSZ * NH * SEQ * HD];
__device__ __nv_bfloat16 g_vh[(size_t)BSZ * NH * HD * SEQ];  // v hi [b,h,d,s]
__device__ __nv_bfloat16 g_vl[(size_t)BSZ * NH * HD * SEQ];

__device__ __nv_bfloat16 g_eh[(size_t)BSZ * NH * SEQ * SEQ]; // exp(score) hi
__device__ __nv_bfloat16 g_el[(size_t)BSZ * NH * SEQ * SEQ]; // exp(score) lo
__device__ float g_psum[(size_t)BSZ * NH * SEQ * 8];         // per-tile row sums
__device__ float g_rinv[(size_t)BSZ * NH * SEQ];             // 1 / row sum

// ===========================================================================
// mma.sync bf16 helper (verified mapping)
// ===========================================================================
__device__ __forceinline__ void mma_bf16(float* d, const uint32_t* a,
                                         uint32_t b0, uint32_t b1)
{
    asm volatile(
        "mma.sync.aligned.m16n8k16.row.col.f32.bf16.bf16.f32 "
        "{%0,%1,%2,%3}, {%4,%5,%6,%7}, {%8,%9}, {%0,%1,%2,%3};"
        : "+f"(d[0]), "+f"(d[1]), "+f"(d[2]), "+f"(d[3])
        : "r"(a[0]), "r"(a[1]), "r"(a[2]), "r"(a[3]), "r"(b0), "r"(b1));
}

__device__ __forceinline__ uint32_t packh2(float x, float y) {
    __nv_bfloat162 p = __halves2bfloat162(__float2bfloat16(x), __float2bfloat16(y));
    return *(uint32_t*)&p;
}
__device__ __forceinline__ uint32_t packl2(float x, float y) {
    __nv_bfloat16 hx = __float2bfloat16(x), hy = __float2bfloat16(y);
    __nv_bfloat162 p = __halves2bfloat162(
        __float2bfloat16(x - __bfloat162float(hx)),
        __float2bfloat16(y - __bfloat162float(hy)));
    return *(uint32_t*)&p;
}

// ===========================================================================
// Pre-convert kernels (proven)
// ===========================================================================
__global__ void __launch_bounds__(256)
convert_x(const float* __restrict__ A, __nv_bfloat16* __restrict__ hi,
          __nv_bfloat16* __restrict__ lo)
{
    size_t i = ((size_t)blockIdx.x * 256 + threadIdx.x) * 4;
    float4 v = *(const float4*)(A + i);
    uint2 uh = {packh2(v.x, v.y), packh2(v.z, v.w)};
    uint2 ul = {packl2(v.x, v.y), packl2(v.z, v.w)};
    *(uint2*)(hi + i) = uh;
    *(uint2*)(lo + i) = ul;
}

__global__ void __launch_bounds__(256)
convert_w(const float* __restrict__ W, __nv_bfloat16* __restrict__ th,
          __nv_bfloat16* __restrict__ tl)
{
    __shared__ float tile[32][33];
    int tx = threadIdx.x, ty = threadIdx.y;
    int n_in = blockIdx.x * 32 + tx;
    int k0 = blockIdx.y * 32;
#pragma unroll
    for (int j = ty; j < 32; j += 8)
        tile[j][tx] = W[(size_t)(k0 + j) * DM + n_in];
    __syncthreads();
#pragma unroll
    for (int j = ty; j < 32; j += 8) {
        int n = blockIdx.x * 32 + j;
        int k = k0 + tx;
        float v = tile[tx][j];
        __nv_bfloat16 h = __float2bfloat16(v);
        th[(size_t)n * DM + k] = h;
        tl[(size_t)n * DM + k] = __float2bfloat16(v - __bfloat162float(h));
    }
}

// ===========================================================================
// Projection GEMM via mma.sync (proven R8)
// MODE 0: bf16 hi/lo out [b,h,s,d]; MODE 1: bf16 hi/lo [b,h,d,s];
// MODE 2: fp32 + resid row-major
// ===========================================================================
#define PSTR 72
#define PANEL (128 * PSTR)
#define PROJ_SMEM (4 * PANEL * 2)   // 73728 B

template<int MODE>
__global__ void __launch_bounds__(256)
gemm_proj_mma3(const __nv_bfloat16* __restrict__ Ahg,
               const __nv_bfloat16* __restrict__ Alg,
               const __nv_bfloat16* __restrict__ Bhg,
               const __nv_bfloat16* __restrict__ Blg,
               const float* __restrict__ bias, const float* __restrict__ resid,
               float* __restrict__ outf,
               __nv_bfloat16* __restrict__ outh, __nv_bfloat16* __restrict__ outl)
{
    extern __shared__ __nv_bfloat16 sb[];
    __nv_bfloat16* Ah = sb;
    __nv_bfloat16* Al = Ah + PANEL;
    __nv_bfloat16* Bh = Al + PANEL;
    __nv_bfloat16* Bl = Bh + PANEL;

    const int tid = threadIdx.x, wid = tid >> 5, lane = tid & 31;
    const int m0 = blockIdx.y * 128, n0 = blockIdx.x * 128;
    const int wm = (wid >> 2) * 64;
    const int wn = (wid & 3) * 32;
    const int lg = lane >> 2;
    const int lq = lane & 3;

    float acc[4][4][4];
#pragma unroll
    for (int i = 0; i < 4; i++)
#pragma unroll
        for (int j = 0; j < 4; j++)
#pragma unroll
            for (int r = 0; r < 4; r++) acc[i][j][r] = 0.f;

    const int sr = tid >> 3;
    const int sc = (tid & 7) * 8;

    for (int kc = 0; kc < 8; kc++) {
        const int k0 = kc * 64;
        __syncthreads();
#pragma unroll
        for (int p = 0; p < 4; p++) {
            int row = sr + p * 32;
            *(uint4*)&Ah[row * PSTR + sc] =
                *(const uint4*)(Ahg + (size_t)(m0 + row) * DM + k0 + sc);
            *(uint4*)&Al[row * PSTR + sc] =
                *(const uint4*)(Alg + (size_t)(m0 + row) * DM + k0 + sc);
            *(uint4*)&Bh[row * PSTR + sc] =
                *(const uint4*)(Bhg + (size_t)(n0 + row) * DM + k0 + sc);
            *(uint4*)&Bl[row * PSTR + sc] =
                *(const uint4*)(Blg + (size_t)(n0 + row) * DM + k0 + sc);
        }
        __syncthreads();

#pragma unroll
        for (int ks = 0; ks < 4; ks++) {
            const int kb = ks * 16;
            uint32_t ah[4][4], al[4][4];
#pragma unroll
            for (int i = 0; i < 4; i++) {
                int r = wm + i * 16 + lg;
                int c = kb + lq * 2;
                ah[i][0] = *(const uint32_t*)&Ah[r * PSTR + c];
                ah[i][1] = *(const uint32_t*)&Ah[(r + 8) * PSTR + c];
                ah[i][2] = *(const uint32_t*)&Ah[r * PSTR + c + 8];
                ah[i][3] = *(const uint32_t*)&Ah[(r + 8) * PSTR + c + 8];
                al[i][0] = *(const uint32_t*)&Al[r * PSTR + c];
                al[i][1] = *(const uint32_t*)&Al[(r + 8) * PSTR + c];
                al[i][2] = *(const uint32_t*)&Al[r * PSTR + c + 8];
                al[i][3] = *(const uint32_t*)&Al[(r + 8) * PSTR + c + 8];
            }
#pragma unroll
            for (int j = 0; j < 4; j++) {
                int n = wn + j * 8 + lg;
                int ck = kb + lq * 2;
                uint32_t bh0 = *(const uint32_t*)&Bh[n * PSTR + ck];
                uint32_t bh1 = *(const uint32_t*)&Bh[n * PSTR + ck + 8];
                uint32_t bl0 = *(const uint32_t*)&Bl[n * PSTR + ck];
                uint32_t bl1 = *(const uint32_t*)&Bl[n * PSTR + ck + 8];
#pragma unroll
                for (int i = 0; i < 4; i++) {
                    mma_bf16(acc[i][j], ah[i], bh0, bh1);
                    mma_bf16(acc[i][j], ah[i], bl0, bl1);
                    mma_bf16(acc[i][j], al[i], bh0, bh1);
                }
            }
        }
    }

#pragma unroll
    for (int i = 0; i < 4; i++) {
        int r1 = m0 + wm + i * 16 + lg;
        int r2 = r1 + 8;
#pragma unroll
        for (int j = 0; j < 4; j++) {
            int n = n0 + wn + j * 8 + lq * 2;
            float b0 = bias[n], b1 = bias[n + 1];
            float v00 = acc[i][j][0] + b0, v01 = acc[i][j][1] + b1;
            float v10 = acc[i][j][2] + b0, v11 = acc[i][j][3] + b1;
            if (MODE == 2) {
                float2 q1 = *(const float2*)(resid + (size_t)r1 * DM + n);
                float2 q2 = *(const float2*)(resid + (size_t)r2 * DM + n);
                float2 o1 = {v00 + q1.x, v01 + q1.y};
                float2 o2 = {v10 + q2.x, v11 + q2.y};
                *(float2*)(outf + (size_t)r1 * DM + n) = o1;
                *(float2*)(outf + (size_t)r2 * DM + n) = o2;
            } else if (MODE == 0) {
                int h = n >> 6, d = n & (HD - 1);
                int b1_ = r1 >> 10, s1 = r1 & (SEQ - 1);
                int b2_ = r2 >> 10, s2 = r2 & (SEQ - 1);
                size_t o1 = (((size_t)(b1_ * NH + h) * SEQ + s1) << 6) + d;
                size_t o2 = (((size_t)(b2_ * NH + h) * SEQ + s2) << 6) + d;
                *(uint32_t*)(outh + o1) = packh2(v00, v01);
                *(uint32_t*)(outl + o1) = packl2(v00, v01);
                *(uint32_t*)(outh + o2) = packh2(v10, v11);
                *(uint32_t*)(outl + o2) = packl2(v10, v11);
            } else {
                int h = n >> 6, d = n & (HD - 1);
                int b1_ = r1 >> 10, s1 = r1 & (SEQ - 1);
                int b2_ = r2 >> 10, s2 = r2 & (SEQ - 1);
                size_t base1 = (((size_t)(b1_ * NH + h) * HD + d) << 10) + s1;
                size_t base2 = (((size_t)(b2_ * NH + h) * HD + d) << 10) + s2;
                __nv_bfloat16 h00 = __float2bfloat16(v00);
                __nv_bfloat16 h01 = __float2bfloat16(v01);
                __nv_bfloat16 h10 = __float2bfloat16(v10);
                __nv_bfloat16 h11 = __float2bfloat16(v11);
                outh[base1]          = h00;
                outh[base1 + SEQ]    = h01;
                outh[base2]          = h10;
                outh[base2 + SEQ]    = h11;
                outl[base1]       = __float2bfloat16(v00 - __bfloat162float(h00));
                outl[base1 + SEQ] = __float2bfloat16(v01 - __bfloat162float(h01));
                outl[base2]       = __float2bfloat16(v10 - __bfloat162float(h10));
                outl[base2 + SEQ] = __float2bfloat16(v11 - __bfloat162float(h11));
            }
        }
    }
}

// ===========================================================================
// Scores via mma.sync + EXP epilogue (no-max softmax; exp underflows masked
// entries to exactly 0). Writes exp as bf16 hi/lo + per-tile row sums.
// grid (8 n, 8 m, 64 bh), 256 thr. (R8 scores kernel + new epilogue)
// ===========================================================================
#define SCM_SMEM (4 * PANEL * 2)
__global__ void __launch_bounds__(256)
gemm_scores_exp(const __nv_bfloat16* __restrict__ qh, const __nv_bfloat16* __restrict__ ql,
                const __nv_bfloat16* __restrict__ kh, const __nv_bfloat16* __restrict__ kl,
                const int* __restrict__ mask, const float* __restrict__ adjoin,
                __nv_bfloat16* __restrict__ ehg, __nv_bfloat16* __restrict__ elg,
                float* __restrict__ psum)
{
    extern __shared__ __nv_bfloat16 sb[];
    __nv_bfloat16* Qh = sb;
    __nv_bfloat16* Ql = Qh + PANEL;
    __nv_bfloat16* Kh = Ql + PANEL;
    __nv_bfloat16* Kl = Kh + PANEL;
    __shared__ float red2[128 * 4];

    const int bh = blockIdx.z;
    const int b_ = bh >> 3;
    const __nv_bfloat16* qg_h = qh + (size_t)bh * SEQ * HD;
    const __nv_bfloat16* qg_l = ql + (size_t)bh * SEQ * HD;
    const __nv_bfloat16* kg_h = kh + (size_t)bh * SEQ * HD;
    const __nv_bfloat16* kg_l = kl + (size_t)bh * SEQ * HD;
    __nv_bfloat16* eh = ehg + (size_t)bh * SEQ * SEQ;
    __nv_bfloat16* el = elg + (size_t)bh * SEQ * SEQ;

    const int tid = threadIdx.x, wid = tid >> 5, lane = tid & 31;
    const int m0 = blockIdx.y * 128, n0 = blockIdx.x * 128;
    const int wm = (wid >> 2) * 64;
    const int wn = (wid & 3) * 32;
    const int lg = lane >> 2;
    const int lq = lane & 3;

    const int sr = tid >> 3;
    const int sc = (tid & 7) * 8;
#pragma unroll
    for (int p = 0; p < 4; p++) {
        int row = sr + p * 32;
        *(uint4*)&Qh[row * PSTR + sc] = *(const uint4*)(qg_h + (size_t)(m0 + row) * HD + sc);
        *(uint4*)&Ql[row * PSTR + sc] = *(const uint4*)(qg_l + (size_t)(m0 + row) * HD + sc);
        *(uint4*)&Kh[row * PSTR + sc] = *(const uint4*)(kg_h + (size_t)(n0 + row) * HD + sc);
        *(uint4*)&Kl[row * PSTR + sc] = *(const uint4*)(kg_l + (size_t)(n0 + row) * HD + sc);
    }
    __syncthreads();

    float acc[4][4][4];
#pragma unroll
    for (int i = 0; i < 4; i++)
#pragma unroll
        for (int j = 0; j < 4; j++)
#pragma unroll
            for (int r = 0; r < 4; r++) acc[i][j][r] = 0.f;

#pragma unroll
    for (int ks = 0; ks < 4; ks++) {
        const int kb = ks * 16;
        uint32_t ah[4][4], al[4][4];
#pragma unroll
        for (int i = 0; i < 4; i++) {
            int r = wm + i * 16 + lg;
            int c = kb + lq * 2;
            ah[i][0] = *(const uint32_t*)&Qh[r * PSTR + c];
            ah[i][1] = *(const uint32_t*)&Qh[(r + 8) * PSTR + c];
            ah[i][2] = *(const uint32_t*)&Qh[r * PSTR + c + 8];
            ah[i][3] = *(const uint32_t*)&Qh[(r + 8) * PSTR + c + 8];
            al[i][0] = *(const uint32_t*)&Ql[r * PSTR + c];
            al[i][1] = *(const uint32_t*)&Ql[(r + 8) * PSTR + c];
            al[i][2] = *(const uint32_t*)&Ql[r * PSTR + c + 8];
            al[i][3] = *(const uint32_t*)&Ql[(r + 8) * PSTR + c + 8];
        }
#pragma unroll
        for (int j = 0; j < 4; j++) {
            int n = wn + j * 8 + lg;
            int ck = kb + lq * 2;
            uint32_t bh0 = *(const uint32_t*)&Kh[n * PSTR + ck];
            uint32_t bh1 = *(const uint32_t*)&Kh[n * PSTR + ck + 8];
            uint32_t bl0 = *(const uint32_t*)&Kl[n * PSTR + ck];
            uint32_t bl1 = *(const uint32_t*)&Kl[n * PSTR + ck + 8];
#pragma unroll
            for (int i = 0; i < 4; i++) {
                mma_bf16(acc[i][j], ah[i], bh0, bh1);
                mma_bf16(acc[i][j], ah[i], bl0, bl1);
                mma_bf16(acc[i][j], al[i], bh0, bh1);
            }
        }
    }

    const int*   mb = mask   + (size_t)b_ * SEQ * SEQ;
    const float* ab = adjoin + (size_t)b_ * SEQ * SEQ;

    float rs[8];
#pragma unroll
    for (int r = 0; r < 8; r++) rs[r] = 0.f;

#pragma unroll
    for (int i = 0; i < 4; i++) {
        int r1 = m0 + wm + i * 16 + lg;
        int r2 = r1 + 8;
#pragma unroll
        for (int j = 0; j < 4; j++) {
            int n = n0 + wn + j * 8 + lq * 2;
            size_t o1 = (size_t)r1 * SEQ + n;
            size_t o2 = (size_t)r2 * SEQ + n;
            int2   m1 = *(const int2*)(mb + o1);
            int2   m2 = *(const int2*)(mb + o2);
            float2 a1 = *(const float2*)(ab + o1);
            float2 a2 = *(const float2*)(ab + o2);
            float e0 = __expf((m1.x ? NEGV : acc[i][j][0] * 0.125f) + a1.x);
            float e1 = __expf((m1.y ? NEGV : acc[i][j][1] * 0.125f) + a1.y);
            float e2 = __expf((m2.x ? NEGV : acc[i][j][2] * 0.125f) + a2.x);
            float e3 = __expf((m2.y ? NEGV : acc[i][j][3] * 0.125f) + a2.y);
            rs[2 * i]     += e0 + e1;
            rs[2 * i + 1] += e2 + e3;
            *(uint32_t*)(eh + o1) = packh2(e0, e1);
            *(uint32_t*)(el + o1) = packl2(e0, e1);
            *(uint32_t*)(eh + o2) = packh2(e2, e3);
            *(uint32_t*)(el + o2) = packl2(e2, e3);
        }
    }

    // reduce row sums across lq lanes, then across the 4 n-warps
#pragma unroll
    for (int off = 1; off <= 2; off <<= 1)
#pragma unroll
        for (int r = 0; r < 8; r++)
            rs[r] += __shfl_xor_sync(0xffffffffu, rs[r], off);
    if (lq == 0) {
#pragma unroll
        for (int i = 0; i < 4; i++) {
            int rl = wm + i * 16 + lg;
            red2[rl * 4 + (wid & 3)]       = rs[2 * i];
            red2[(rl + 8) * 4 + (wid & 3)] = rs[2 * i + 1];
        }
    }
    __syncthreads();
    if (tid < 128) {
        float s = red2[tid * 4 + 0] + red2[tid * 4 + 1] +
                  red2[tid * 4 + 2] + red2[tid * 4 + 3];
        psum[((size_t)bh * SEQ + m0 + tid) * 8 + blockIdx.x] = s;
    }
}

// ===========================================================================
// Row-sum reduce + invert (tiny)
// ===========================================================================
__global__ void __launch_bounds__(256)
rowsum_inv(const float* __restrict__ psum, float* __restrict__ rinv)
{
    int r = blockIdx.x * 256 + threadIdx.x;   // 0 .. 64*1024-1
    float s = 0.f;
#pragma unroll
    for (int k = 0; k < 8; k++) s += psum[(size_t)r * 8 + k];
    rinv[r] = 1.f / s;
}

// ===========================================================================
// attn writer: attn = (eh + el) * rinv[row]  (pure streaming)
// Each block covers exactly one row (1024 floats).
// ===========================================================================
__global__ void __launch_bounds__(256)
attn_writer(const __nv_bfloat16* __restrict__ eh, const __nv_bfloat16* __restrict__ el,
            const float* __restrict__ rinv, float* __restrict__ attn)
{
    size_t f4 = (size_t)blockIdx.x * 256 + threadIdx.x;
    size_t e = f4 * 4;
    float inv = rinv[e >> 10];
    uint2 uh = *(const uint2*)(eh + e);
    uint2 ul = *(const uint2*)(el + e);
    __nv_bfloat162 h0 = *(__nv_bfloat162*)&uh.x;
    __nv_bfloat162 h1 = *(__nv_bfloat162*)&uh.y;
    __nv_bfloat162 l0 = *(__nv_bfloat162*)&ul.x;
    __nv_bfloat162 l1 = *(__nv_bfloat162*)&ul.y;
    float4 o;
    o.x = (__bfloat162float(h0.x) + __bfloat162float(l0.x)) * inv;
    o.y = (__bfloat162float(h0.y) + __bfloat162float(l0.y)) * inv;
    o.z = (__bfloat162float(h1.x) + __bfloat162float(l1.x)) * inv;
    o.w = (__bfloat162float(h1.y) + __bfloat162float(l1.y)) * inv;
    *(float4*)(attn + e) = o;
}

// ===========================================================================
// Ctx via mma.sync: ctx = E(bf16 hi, unnormalized) @ V(bf16 hi/lo), scaled by
// rinv at the epilogue; writes bf16 hi/lo directly (out-proj input).
// grid (8 mtiles, 64 bh), 256 thr. (R8 ctx kernel + rinv + bf16 epilogue)
// ===========================================================================
__global__ void __launch_bounds__(256)
gemm_ctx_mma(const __nv_bfloat16* __restrict__ ehg,
             const __nv_bfloat16* __restrict__ vh, const __nv_bfloat16* __restrict__ vl,
             const float* __restrict__ rinv,
             __nv_bfloat16* __restrict__ ch, __nv_bfloat16* __restrict__ cl)
{
    __shared__ __nv_bfloat16 Ps[128 * PSTR];
    __shared__ __nv_bfloat16 Vh[64 * PSTR];
    __shared__ __nv_bfloat16 Vl[64 * PSTR];

    const int bh = blockIdx.y;
    const int b_ = bh >> 3, h = bh & 7;
    const int m0 = blockIdx.x * 128;
    const __nv_bfloat16* pg = ehg + (size_t)bh * SEQ * SEQ;
    const __nv_bfloat16* vg_h = vh + (size_t)bh * HD * SEQ;
    const __nv_bfloat16* vg_l = vl + (size_t)bh * HD * SEQ;

    const int tid = threadIdx.x, wid = tid >> 5, lane = tid & 31;
    const int wm = (wid >> 1) * 32;
    const int wn = (wid & 1) * 32;
    const int lg = lane >> 2;
    const int lq = lane & 3;

    float acc[2][4][4];
#pragma unroll
    for (int i = 0; i < 2; i++)
#pragma unroll
        for (int j = 0; j < 4; j++)
#pragma unroll
            for (int r = 0; r < 4; r++) acc[i][j][r] = 0.f;

    for (int k0 = 0; k0 < SEQ; k0 += 64) {
        __syncthreads();
#pragma unroll
        for (int p = 0; p < 4; p++) {
            int f = p * 256 + tid;
            int row = f >> 3, col = (f & 7) * 8;
            *(uint4*)&Ps[row * PSTR + col] =
                *(const uint4*)(pg + (size_t)(m0 + row) * SEQ + k0 + col);
        }
#pragma unroll
        for (int p = 0; p < 2; p++) {
            int f = p * 256 + tid;
            int row = f >> 3, col = (f & 7) * 8;
            *(uint4*)&Vh[row * PSTR + col] =
                *(const uint4*)(vg_h + ((size_t)row << 10) + k0 + col);
            *(uint4*)&Vl[row * PSTR + col] =
                *(const uint4*)(vg_l + ((size_t)row << 10) + k0 + col);
        }
        __syncthreads();

#pragma unroll
        for (int ks = 0; ks < 4; ks++) {
            const int kb = ks * 16;
            uint32_t a[2][4];
#pragma unroll
            for (int i = 0; i < 2; i++) {
                int r = wm + i * 16 + lg;
                int c = kb + lq * 2;
                a[i][0] = *(const uint32_t*)&Ps[r * PSTR + c];
                a[i][1] = *(const uint32_t*)&Ps[(r + 8) * PSTR + c];
                a[i][2] = *(const uint32_t*)&Ps[r * PSTR + c + 8];
                a[i][3] = *(const uint32_t*)&Ps[(r + 8) * PSTR + c + 8];
            }
#pragma unroll
            for (int j = 0; j < 4; j++) {
                int n = wn + j * 8 + lg;
                int ck = kb + lq * 2;
                uint32_t bh0 = *(const uint32_t*)&Vh[n * PSTR + ck];
                uint32_t bh1 = *(const uint32_t*)&Vh[n * PSTR + ck + 8];
                uint32_t bl0 = *(const uint32_t*)&Vl[n * PSTR + ck];
                uint32_t bl1 = *(const uint32_t*)&Vl[n * PSTR + ck + 8];
#pragma unroll
                for (int i = 0; i < 2; i++) {
                    mma_bf16(acc[i][j], a[i], bh0, bh1);
                    mma_bf16(acc[i][j], a[i], bl0, bl1);
                }
            }
        }
    }

#pragma unroll
    for (int i = 0; i < 2; i++) {
        int r1 = m0 + wm + i * 16 + lg;
        int r2 = r1 + 8;
        float inv1 = rinv[(size_t)bh * SEQ + r1];
        float inv2 = rinv[(size_t)bh * SEQ + r2];
#pragma unroll
        for (int j = 0; j < 4; j++) {
            int d = wn + j * 8 + lq * 2;
            size_t o1 = ((size_t)(b_ * SEQ) + r1) * DM + h * HD + d;
            size_t o2 = ((size_t)(b_ * SEQ) + r2) * DM + h * HD + d;
            float c00 = acc[i][j][0] * inv1, c01 = acc[i][j][1] * inv1;
            float c10 = acc[i][j][2] * inv2, c11 = acc[i][j][3] * inv2;
            *(uint32_t*)(ch + o1) = packh2(c00, c01);
            *(uint32_t*)(cl + o1) = packl2(c00, c01);
            *(uint32_t*)(ch + o2) = packh2(c10, c11);
            *(uint32_t*)(cl + o2) = packl2(c10, c11);
        }
    }
}

// ===========================================================================
// LayerNorm
// ===========================================================================
__global__ void __launch_bounds__(256)
layernorm_rows(const float* __restrict__ pre, const float* __restrict__ g,
               const float* __restrict__ be, float* __restrict__ out)
{
    int warp = threadIdx.x >> 5, lane = threadIdx.x & 31;
    size_t row = (size_t)blockIdx.x * 8 + warp;
    const float* p = pre + row * DM;

    float x[16];
    float s = 0.f, s2 = 0.f;
#pragma unroll
    for (int i = 0; i < 4; i++) {
        float4 v = *(const float4*)(p + i * 128 + lane * 4);
        x[i * 4 + 0] = v.x; x[i * 4 + 1] = v.y;
        x[i * 4 + 2] = v.z; x[i * 4 + 3] = v.w;
        s  += v.x + v.y + v.z + v.w;
        s2 += v.x * v.x + v.y * v.y + v.z * v.z + v.w * v.w;
    }
#pragma unroll
    for (int o = 16; o; o >>= 1) {
        s  += __shfl_xor_sync(0xffffffffu, s,  o);
        s2 += __shfl_xor_sync(0xffffffffu, s2, o);
    }
    float mu  = s  * (1.f / DM);
    float var = s2 * (1.f / DM) - mu * mu;
    float inv = rsqrtf(var + 1e-6f);

    float* po = out + row * DM;
#pragma unroll
    for (int i = 0; i < 4; i++) {
        float4 w;
        int c = i * 128 + lane * 4;
        w.x = (x[i * 4 + 0] - mu) * inv * g[c + 0] + be[c + 0];
        w.y = (x[i * 4 + 1] - mu) * inv * g[c + 1] + be[c + 1];
        w.z = (x[i * 4 + 2] - mu) * inv * g[c + 2] + be[c + 2];
        w.w = (x[i * 4 + 3] - mu) * inv * g[c + 3] + be[c + 3];
        *(float4*)(po + c) = w;
    }
}

// ---------------------------------------------------------------------------
// Launch
// ---------------------------------------------------------------------------
extern "C" void kernel_launch(void* const* d_in, const int* in_sizes, int n_in,
                              void* d_out, int out_size)
{
    const float* Q   = (const float*)d_in[0];
    const float* K   = (const float*)d_in[1];
    const float* V   = (const float*)d_in[2];
    const int*   mask = (const int*)d_in[3];
    const float* adjoin = (const float*)d_in[4];
    const float* Wq = (const float*)d_in[5];
    const float* bq = (const float*)d_in[6];
    const float* Wk = (const float*)d_in[7];
    const float* bk = (const float*)d_in[8];
    const float* Wv = (const float*)d_in[9];
    const float* bv = (const float*)d_in[10];
    const float* Wo = (const float*)d_in[11];
    const float* bo = (const float*)d_in[12];
    const float* lg = (const float*)d_in[13];
    const float* lb = (const float*)d_in[14];

    float *pb, *afb, *psum, *rinv;
    cudaGetSymbolAddress((void**)&pb,   g_pre);
    cudaGetSymbolAddress((void**)&afb,  g_attn_fb);
    cudaGetSymbolAddress((void**)&psum, g_psum);
    cudaGetSymbolAddress((void**)&rinv, g_rinv);

    __nv_bfloat16 *xh, *xl, *wh, *wl, *qh, *ql, *kh, *kl, *vh, *vl, *eh, *el;
    cudaGetSymbolAddress((void**)&xh, g_xh);
    cudaGetSymbolAddress((void**)&xl, g_xl);
    cudaGetSymbolAddress((void**)&wh, g_wh);
    cudaGetSymbolAddress((void**)&wl, g_wl);
    cudaGetSymbolAddress((void**)&qh, g_qh);
    cudaGetSymbolAddress((void**)&ql, g_ql);
    cudaGetSymbolAddress((void**)&kh, g_kh);
    cudaGetSymbolAddress((void**)&kl, g_kl);
    cudaGetSymbolAddress((void**)&vh, g_vh);
    cudaGetSymbolAddress((void**)&vl, g_vl);
    cudaGetSymbolAddress((void**)&eh, g_eh);
    cudaGetSymbolAddress((void**)&el, g_el);
    const size_t WSZ = (size_t)DM * DM;

    float* out0 = (float*)d_out;
    const size_t OUT0 = (size_t)BSZ * SEQ * DM;
    const size_t ATTN = (size_t)BSZ * NH * SEQ * SEQ;
    float* attn = ((size_t)out_size >= OUT0 + ATTN) ? (out0 + OUT0) : afb;

    static int attr_set = 0;
    if (!attr_set) {
        cudaFuncSetAttribute(gemm_proj_mma3<0>,
                             cudaFuncAttributeMaxDynamicSharedMemorySize, PROJ_SMEM);
        cudaFuncSetAttribute(gemm_proj_mma3<1>,
                             cudaFuncAttributeMaxDynamicSharedMemorySize, PROJ_SMEM);
        cudaFuncSetAttribute(gemm_proj_mma3<2>,
                             cudaFuncAttributeMaxDynamicSharedMemorySize, PROJ_SMEM);
        cudaFuncSetAttribute(gemm_scores_exp,
                             cudaFuncAttributeMaxDynamicSharedMemorySize, SCM_SMEM);
        attr_set = 1;
    }

    dim3 wgrid(DM / 32, DM / 32), wblk(32, 8);
    const int XBLK = (int)(((size_t)BSZ * SEQ * DM) / 4 / 256);   // 4096
    dim3 gp(DM / 128, (BSZ * SEQ) / 128);   // (4, 64)

    // 0) Weights -> [n][k] bf16 hi/lo
    convert_w<<<wgrid, wblk>>>(Wq, wh + 0 * WSZ, wl + 0 * WSZ);
    convert_w<<<wgrid, wblk>>>(Wk, wh + 1 * WSZ, wl + 1 * WSZ);
    convert_w<<<wgrid, wblk>>>(Wv, wh + 2 * WSZ, wl + 2 * WSZ);
    convert_w<<<wgrid, wblk>>>(Wo, wh + 3 * WSZ, wl + 3 * WSZ);

    // 1) Projections -> bf16 split q/k [b,h,s,d], v [b,h,d,s]
    convert_x<<<XBLK, 256>>>(Q, xh, xl);
    gemm_proj_mma3<0><<<gp, 256, PROJ_SMEM>>>(xh, xl, wh + 0 * WSZ, wl + 0 * WSZ,
                                              bq, nullptr, nullptr, qh, ql);
    convert_x<<<XBLK, 256>>>(K, xh, xl);
    gemm_proj_mma3<0><<<gp, 256, PROJ_SMEM>>>(xh, xl, wh + 1 * WSZ, wl + 1 * WSZ,
                                              bk, nullptr, nullptr, kh, kl);
    convert_x<<<XBLK, 256>>>(V, xh, xl);
    gemm_proj_mma3<1><<<gp, 256, PROJ_SMEM>>>(xh, xl, wh + 2 * WSZ, wl + 2 * WSZ,
                                              bv, nullptr, nullptr, vh, vl);

    // 2) Scores + mask + adjoin + exp -> eh/el + per-tile row sums
    dim3 gs(SEQ / 128, SEQ / 128, BSZ * NH);
    gemm_scores_exp<<<gs, 256, SCM_SMEM>>>(qh, ql, kh, kl, mask, adjoin,
                                           eh, el, psum);

    // 3) Row sums -> 1/sum
    rowsum_inv<<<(BSZ * NH * SEQ) / 256, 256>>>(psum, rinv);

    // 4) attn = (eh + el) * rinv  (streaming)
    attn_writer<<<(int)(ATTN / 4 / 256), 256>>>(eh, el, rinv, attn);

    // 5) Context: (eh @ V) * rinv -> bf16 hi/lo in xh/xl
    dim3 gc(SEQ / 128, BSZ * NH);
    gemm_ctx_mma<<<gc, 256>>>(eh, vh, vl, rinv, xh, xl);

    // 6) Output projection + bias + residual(Q)
    gemm_proj_mma3<2><<<gp, 256, PROJ_SMEM>>>(xh, xl, wh + 3 * WSZ, wl + 3 * WSZ,
                                              bo, Q, pb, nullptr, nullptr);

    // 7) LayerNorm -> out
    layernorm_rows<<<(BSZ * SEQ) / 8, 256>>>(pb, lg, lb, out0);
}

// round 13
// speedup vs baseline: 1.1415x; 1.0451x over previous
#include <cuda_runtime.h>
#include <cuda_bf16.h>
#include <math.h>
#include <stdint.h>

// Problem constants
#define BSZ 8
#define SEQ 1024
#define DM  512
#define NH  8
#define HD  64
#define NEGV (-1e9f)

// ---------------------------------------------------------------------------
// Scratch
// ---------------------------------------------------------------------------
__device__ float g_pre[(size_t)BSZ * SEQ * DM];
__device__ float g_attn_fb[64];   // dummy (unused when attn skipped)

__device__ __nv_bfloat16 g_xh[(size_t)BSZ * SEQ * DM];   // activation / ctx hi
__device__ __nv_bfloat16 g_xl[(size_t)BSZ * SEQ * DM];   // activation / ctx lo
__device__ __nv_bfloat16 g_wh[4][(size_t)DM * DM];       // W^T hi
__device__ __nv_bfloat16 g_wl[4][(size_t)DM * DM];       // W^T lo

__device__ __nv_bfloat16 g_qh[(size_t)BSZ * NH * SEQ * HD];
__device__ __nv_bfloat16 g_ql[(size_t)BSZ * NH * SEQ * HD];
__device__ __nv_bfloat16 g_kh[(size_t)BSZ * NH * SEQ * HD];
__device__ __nv_bfloat16 g_kl[(size_t)BSZ * NH * SEQ * HD];
__device__ __nv_bfloat16 g_vh[(size_t)BSZ * NH * HD * SEQ];
__device__ __nv_bfloat16 g_vl[(size_t)BSZ * NH * HD * SEQ];

__device__ __nv_bfloat16 g_eh[(size_t)BSZ * NH * SEQ * SEQ]; // exp(score) hi
__device__ __nv_bfloat16 g_el[(size_t)BSZ * NH * SEQ * SEQ]; // exp(score) lo
__device__ float g_psum[(size_t)BSZ * NH * SEQ * 8];
__device__ float g_rinv[(size_t)BSZ * NH * SEQ];

// ===========================================================================
// mma.sync bf16 helper (verified mapping)
// ===========================================================================
__device__ __forceinline__ void mma_bf16(float* d, const uint32_t* a,
                                         uint32_t b0, uint32_t b1)
{
    asm volatile(
        "mma.sync.aligned.m16n8k16.row.col.f32.bf16.bf16.f32 "
        "{%0,%1,%2,%3}, {%4,%5,%6,%7}, {%8,%9}, {%0,%1,%2,%3};"
        : "+f"(d[0]), "+f"(d[1]), "+f"(d[2]), "+f"(d[3])
        : "r"(a[0]), "r"(a[1]), "r"(a[2]), "r"(a[3]), "r"(b0), "r"(b1));
}

__device__ __forceinline__ uint32_t packh2(float x, float y) {
    __nv_bfloat162 p = __halves2bfloat162(__float2bfloat16(x), __float2bfloat16(y));
    return *(uint32_t*)&p;
}
__device__ __forceinline__ uint32_t packl2(float x, float y) {
    __nv_bfloat16 hx = __float2bfloat16(x), hy = __float2bfloat16(y);
    __nv_bfloat162 p = __halves2bfloat162(
        __float2bfloat16(x - __bfloat162float(hx)),
        __float2bfloat16(y - __bfloat162float(hy)));
    return *(uint32_t*)&p;
}

// ===========================================================================
// Pre-convert kernels (proven)
// ===========================================================================
__global__ void __launch_bounds__(256)
convert_x(const float* __restrict__ A, __nv_bfloat16* __restrict__ hi,
          __nv_bfloat16* __restrict__ lo)
{
    size_t i = ((size_t)blockIdx.x * 256 + threadIdx.x) * 4;
    float4 v = *(const float4*)(A + i);
    uint2 uh = {packh2(v.x, v.y), packh2(v.z, v.w)};
    uint2 ul = {packl2(v.x, v.y), packl2(v.z, v.w)};
    *(uint2*)(hi + i) = uh;
    *(uint2*)(lo + i) = ul;
}

__global__ void __launch_bounds__(256)
convert_w(const float* __restrict__ W, __nv_bfloat16* __restrict__ th,
          __nv_bfloat16* __restrict__ tl)
{
    __shared__ float tile[32][33];
    int tx = threadIdx.x, ty = threadIdx.y;
    int n_in = blockIdx.x * 32 + tx;
    int k0 = blockIdx.y * 32;
#pragma unroll
    for (int j = ty; j < 32; j += 8)
        tile[j][tx] = W[(size_t)(k0 + j) * DM + n_in];
    __syncthreads();
#pragma unroll
    for (int j = ty; j < 32; j += 8) {
        int n = blockIdx.x * 32 + j;
        int k = k0 + tx;
        float v = tile[tx][j];
        __nv_bfloat16 h = __float2bfloat16(v);
        th[(size_t)n * DM + k] = h;
        tl[(size_t)n * DM + k] = __float2bfloat16(v - __bfloat162float(h));
    }
}

// ===========================================================================
// Projection GEMM via mma.sync (proven R8)
// ===========================================================================
#define PSTR 72
#define PANEL (128 * PSTR)
#define PROJ_SMEM (4 * PANEL * 2)   // 73728 B

template<int MODE>
__global__ void __launch_bounds__(256)
gemm_proj_mma3(const __nv_bfloat16* __restrict__ Ahg,
               const __nv_bfloat16* __restrict__ Alg,
               const __nv_bfloat16* __restrict__ Bhg,
               const __nv_bfloat16* __restrict__ Blg,
               const float* __restrict__ bias, const float* __restrict__ resid,
               float* __restrict__ outf,
               __nv_bfloat16* __restrict__ outh, __nv_bfloat16* __restrict__ outl)
{
    extern __shared__ __nv_bfloat16 sb[];
    __nv_bfloat16* Ah = sb;
    __nv_bfloat16* Al = Ah + PANEL;
    __nv_bfloat16* Bh = Al + PANEL;
    __nv_bfloat16* Bl = Bh + PANEL;

    const int tid = threadIdx.x, wid = tid >> 5, lane = tid & 31;
    const int m0 = blockIdx.y * 128, n0 = blockIdx.x * 128;
    const int wm = (wid >> 2) * 64;
    const int wn = (wid & 3) * 32;
    const int lg = lane >> 2;
    const int lq = lane & 3;

    float acc[4][4][4];
#pragma unroll
    for (int i = 0; i < 4; i++)
#pragma unroll
        for (int j = 0; j < 4; j++)
#pragma unroll
            for (int r = 0; r < 4; r++) acc[i][j][r] = 0.f;

    const int sr = tid >> 3;
    const int sc = (tid & 7) * 8;

    for (int kc = 0; kc < 8; kc++) {
        const int k0 = kc * 64;
        __syncthreads();
#pragma unroll
        for (int p = 0; p < 4; p++) {
            int row = sr + p * 32;
            *(uint4*)&Ah[row * PSTR + sc] =
                *(const uint4*)(Ahg + (size_t)(m0 + row) * DM + k0 + sc);
            *(uint4*)&Al[row * PSTR + sc] =
                *(const uint4*)(Alg + (size_t)(m0 + row) * DM + k0 + sc);
            *(uint4*)&Bh[row * PSTR + sc] =
                *(const uint4*)(Bhg + (size_t)(n0 + row) * DM + k0 + sc);
            *(uint4*)&Bl[row * PSTR + sc] =
                *(const uint4*)(Blg + (size_t)(n0 + row) * DM + k0 + sc);
        }
        __syncthreads();

#pragma unroll
        for (int ks = 0; ks < 4; ks++) {
            const int kb = ks * 16;
            uint32_t ah[4][4], al[4][4];
#pragma unroll
            for (int i = 0; i < 4; i++) {
                int r = wm + i * 16 + lg;
                int c = kb + lq * 2;
                ah[i][0] = *(const uint32_t*)&Ah[r * PSTR + c];
                ah[i][1] = *(const uint32_t*)&Ah[(r + 8) * PSTR + c];
                ah[i][2] = *(const uint32_t*)&Ah[r * PSTR + c + 8];
                ah[i][3] = *(const uint32_t*)&Ah[(r + 8) * PSTR + c + 8];
                al[i][0] = *(const uint32_t*)&Al[r * PSTR + c];
                al[i][1] = *(const uint32_t*)&Al[(r + 8) * PSTR + c];
                al[i][2] = *(const uint32_t*)&Al[r * PSTR + c + 8];
                al[i][3] = *(const uint32_t*)&Al[(r + 8) * PSTR + c + 8];
            }
#pragma unroll
            for (int j = 0; j < 4; j++) {
                int n = wn + j * 8 + lg;
                int ck = kb + lq * 2;
                uint32_t bh0 = *(const uint32_t*)&Bh[n * PSTR + ck];
                uint32_t bh1 = *(const uint32_t*)&Bh[n * PSTR + ck + 8];
                uint32_t bl0 = *(const uint32_t*)&Bl[n * PSTR + ck];
                uint32_t bl1 = *(const uint32_t*)&Bl[n * PSTR + ck + 8];
#pragma unroll
                for (int i = 0; i < 4; i++) {
                    mma_bf16(acc[i][j], ah[i], bh0, bh1);
                    mma_bf16(acc[i][j], ah[i], bl0, bl1);
                    mma_bf16(acc[i][j], al[i], bh0, bh1);
                }
            }
        }
    }

#pragma unroll
    for (int i = 0; i < 4; i++) {
        int r1 = m0 + wm + i * 16 + lg;
        int r2 = r1 + 8;
#pragma unroll
        for (int j = 0; j < 4; j++) {
            int n = n0 + wn + j * 8 + lq * 2;
            float b0 = bias[n], b1 = bias[n + 1];
            float v00 = acc[i][j][0] + b0, v01 = acc[i][j][1] + b1;
            float v10 = acc[i][j][2] + b0, v11 = acc[i][j][3] + b1;
            if (MODE == 2) {
                float2 q1 = *(const float2*)(resid + (size_t)r1 * DM + n);
                float2 q2 = *(const float2*)(resid + (size_t)r2 * DM + n);
                float2 o1 = {v00 + q1.x, v01 + q1.y};
                float2 o2 = {v10 + q2.x, v11 + q2.y};
                *(float2*)(outf + (size_t)r1 * DM + n) = o1;
                *(float2*)(outf + (size_t)r2 * DM + n) = o2;
            } else if (MODE == 0) {
                int h = n >> 6, d = n & (HD - 1);
                int b1_ = r1 >> 10, s1 = r1 & (SEQ - 1);
                int b2_ = r2 >> 10, s2 = r2 & (SEQ - 1);
                size_t o1 = (((size_t)(b1_ * NH + h) * SEQ + s1) << 6) + d;
                size_t o2 = (((size_t)(b2_ * NH + h) * SEQ + s2) << 6) + d;
                *(uint32_t*)(outh + o1) = packh2(v00, v01);
                *(uint32_t*)(outl + o1) = packl2(v00, v01);
                *(uint32_t*)(outh + o2) = packh2(v10, v11);
                *(uint32_t*)(outl + o2) = packl2(v10, v11);
            } else {
                int h = n >> 6, d = n & (HD - 1);
                int b1_ = r1 >> 10, s1 = r1 & (SEQ - 1);
                int b2_ = r2 >> 10, s2 = r2 & (SEQ - 1);
                size_t base1 = (((size_t)(b1_ * NH + h) * HD + d) << 10) + s1;
                size_t base2 = (((size_t)(b2_ * NH + h) * HD + d) << 10) + s2;
                __nv_bfloat16 h00 = __float2bfloat16(v00);
                __nv_bfloat16 h01 = __float2bfloat16(v01);
                __nv_bfloat16 h10 = __float2bfloat16(v10);
                __nv_bfloat16 h11 = __float2bfloat16(v11);
                outh[base1]          = h00;
                outh[base1 + SEQ]    = h01;
                outh[base2]          = h10;
                outh[base2 + SEQ]    = h11;
                outl[base1]       = __float2bfloat16(v00 - __bfloat162float(h00));
                outl[base1 + SEQ] = __float2bfloat16(v01 - __bfloat162float(h01));
                outl[base2]       = __float2bfloat16(v10 - __bfloat162float(h10));
                outl[base2 + SEQ] = __float2bfloat16(v11 - __bfloat162float(h11));
            }
        }
    }
}

// ===========================================================================
// Scores + mask + adjoin + EXP epilogue (no-max softmax, proven R12).
// Writes exp as bf16 hi/lo + per-tile row sums.
// ===========================================================================
#define SCM_SMEM (4 * PANEL * 2)
__global__ void __launch_bounds__(256)
gemm_scores_exp(const __nv_bfloat16* __restrict__ qh, const __nv_bfloat16* __restrict__ ql,
                const __nv_bfloat16* __restrict__ kh, const __nv_bfloat16* __restrict__ kl,
                const int* __restrict__ mask, const float* __restrict__ adjoin,
                __nv_bfloat16* __restrict__ ehg, __nv_bfloat16* __restrict__ elg,
                float* __restrict__ psum)
{
    extern __shared__ __nv_bfloat16 sb[];
    __nv_bfloat16* Qh = sb;
    __nv_bfloat16* Ql = Qh + PANEL;
    __nv_bfloat16* Kh = Ql + PANEL;
    __nv_bfloat16* Kl = Kh + PANEL;
    __shared__ float red2[128 * 4];

    const int bh = blockIdx.z;
    const int b_ = bh >> 3;
    const __nv_bfloat16* qg_h = qh + (size_t)bh * SEQ * HD;
    const __nv_bfloat16* qg_l = ql + (size_t)bh * SEQ * HD;
    const __nv_bfloat16* kg_h = kh + (size_t)bh * SEQ * HD;
    const __nv_bfloat16* kg_l = kl + (size_t)bh * SEQ * HD;
    __nv_bfloat16* eh = ehg + (size_t)bh * SEQ * SEQ;
    __nv_bfloat16* el = elg + (size_t)bh * SEQ * SEQ;

    const int tid = threadIdx.x, wid = tid >> 5, lane = tid & 31;
    const int m0 = blockIdx.y * 128, n0 = blockIdx.x * 128;
    const int wm = (wid >> 2) * 64;
    const int wn = (wid & 3) * 32;
    const int lg = lane >> 2;
    const int lq = lane & 3;

    const int sr = tid >> 3;
    const int sc = (tid & 7) * 8;
#pragma unroll
    for (int p = 0; p < 4; p++) {
        int row = sr + p * 32;
        *(uint4*)&Qh[row * PSTR + sc] = *(const uint4*)(qg_h + (size_t)(m0 + row) * HD + sc);
        *(uint4*)&Ql[row * PSTR + sc] = *(const uint4*)(qg_l + (size_t)(m0 + row) * HD + sc);
        *(uint4*)&Kh[row * PSTR + sc] = *(const uint4*)(kg_h + (size_t)(n0 + row) * HD + sc);
        *(uint4*)&Kl[row * PSTR + sc] = *(const uint4*)(kg_l + (size_t)(n0 + row) * HD + sc);
    }
    __syncthreads();

    float acc[4][4][4];
#pragma unroll
    for (int i = 0; i < 4; i++)
#pragma unroll
        for (int j = 0; j < 4; j++)
#pragma unroll
            for (int r = 0; r < 4; r++) acc[i][j][r] = 0.f;

#pragma unroll
    for (int ks = 0; ks < 4; ks++) {
        const int kb = ks * 16;
        uint32_t ah[4][4], al[4][4];
#pragma unroll
        for (int i = 0; i < 4; i++) {
            int r = wm + i * 16 + lg;
            int c = kb + lq * 2;
            ah[i][0] = *(const uint32_t*)&Qh[r * PSTR + c];
            ah[i][1] = *(const uint32_t*)&Qh[(r + 8) * PSTR + c];
            ah[i][2] = *(const uint32_t*)&Qh[r * PSTR + c + 8];
            ah[i][3] = *(const uint32_t*)&Qh[(r + 8) * PSTR + c + 8];
            al[i][0] = *(const uint32_t*)&Ql[r * PSTR + c];
            al[i][1] = *(const uint32_t*)&Ql[(r + 8) * PSTR + c];
            al[i][2] = *(const uint32_t*)&Ql[r * PSTR + c + 8];
            al[i][3] = *(const uint32_t*)&Ql[(r + 8) * PSTR + c + 8];
        }
#pragma unroll
        for (int j = 0; j < 4; j++) {
            int n = wn + j * 8 + lg;
            int ck = kb + lq * 2;
            uint32_t bh0 = *(const uint32_t*)&Kh[n * PSTR + ck];
            uint32_t bh1 = *(const uint32_t*)&Kh[n * PSTR + ck + 8];
            uint32_t bl0 = *(const uint32_t*)&Kl[n * PSTR + ck];
            uint32_t bl1 = *(const uint32_t*)&Kl[n * PSTR + ck + 8];
#pragma unroll
            for (int i = 0; i < 4; i++) {
                mma_bf16(acc[i][j], ah[i], bh0, bh1);
                mma_bf16(acc[i][j], ah[i], bl0, bl1);
                mma_bf16(acc[i][j], al[i], bh0, bh1);
            }
        }
    }

    const int*   mb = mask   + (size_t)b_ * SEQ * SEQ;
    const float* ab = adjoin + (size_t)b_ * SEQ * SEQ;

    float rs[8];
#pragma unroll
    for (int r = 0; r < 8; r++) rs[r] = 0.f;

#pragma unroll
    for (int i = 0; i < 4; i++) {
        int r1 = m0 + wm + i * 16 + lg;
        int r2 = r1 + 8;
#pragma unroll
        for (int j = 0; j < 4; j++) {
            int n = n0 + wn + j * 8 + lq * 2;
            size_t o1 = (size_t)r1 * SEQ + n;
            size_t o2 = (size_t)r2 * SEQ + n;
            int2   m1 = *(const int2*)(mb + o1);
            int2   m2 = *(const int2*)(mb + o2);
            float2 a1 = *(const float2*)(ab + o1);
            float2 a2 = *(const float2*)(ab + o2);
            float e0 = __expf((m1.x ? NEGV : acc[i][j][0] * 0.125f) + a1.x);
            float e1 = __expf((m1.y ? NEGV : acc[i][j][1] * 0.125f) + a1.y);
            float e2 = __expf((m2.x ? NEGV : acc[i][j][2] * 0.125f) + a2.x);
            float e3 = __expf((m2.y ? NEGV : acc[i][j][3] * 0.125f) + a2.y);
            rs[2 * i]     += e0 + e1;
            rs[2 * i + 1] += e2 + e3;
            *(uint32_t*)(eh + o1) = packh2(e0, e1);
            *(uint32_t*)(el + o1) = packl2(e0, e1);
            *(uint32_t*)(eh + o2) = packh2(e2, e3);
            *(uint32_t*)(el + o2) = packl2(e2, e3);
        }
    }

#pragma unroll
    for (int off = 1; off <= 2; off <<= 1)
#pragma unroll
        for (int r = 0; r < 8; r++)
            rs[r] += __shfl_xor_sync(0xffffffffu, rs[r], off);
    if (lq == 0) {
#pragma unroll
        for (int i = 0; i < 4; i++) {
            int rl = wm + i * 16 + lg;
            red2[rl * 4 + (wid & 3)]       = rs[2 * i];
            red2[(rl + 8) * 4 + (wid & 3)] = rs[2 * i + 1];
        }
    }
    __syncthreads();
    if (tid < 128) {
        float s = red2[tid * 4 + 0] + red2[tid * 4 + 1] +
                  red2[tid * 4 + 2] + red2[tid * 4 + 3];
        psum[((size_t)bh * SEQ + m0 + tid) * 8 + blockIdx.x] = s;
    }
}

// ===========================================================================
// Row-sum reduce + invert (tiny)
// ===========================================================================
__global__ void __launch_bounds__(256)
rowsum_inv(const float* __restrict__ psum, float* __restrict__ rinv)
{
    int r = blockIdx.x * 256 + threadIdx.x;
    float s = 0.f;
#pragma unroll
    for (int k = 0; k < 8; k++) s += psum[(size_t)r * 8 + k];
    rinv[r] = 1.f / s;
}

// ===========================================================================
// Ctx via mma.sync + optional fused attn writer.
// ctx = (E @ V) * rinv -> bf16 hi/lo.
// If WRITE_ATTN: while staging E tiles, also load el and emit
// attn = (eh + el) * rinv (fp32) — E is streamed exactly once here.
// ===========================================================================
template<bool WRITE_ATTN>
__global__ void __launch_bounds__(256)
gemm_ctx_mma(const __nv_bfloat16* __restrict__ ehg, const __nv_bfloat16* __restrict__ elg,
             const __nv_bfloat16* __restrict__ vh, const __nv_bfloat16* __restrict__ vl,
             const float* __restrict__ rinv, float* __restrict__ attn,
             __nv_bfloat16* __restrict__ ch, __nv_bfloat16* __restrict__ cl)
{
    __shared__ __nv_bfloat16 Ps[128 * PSTR];
    __shared__ __nv_bfloat16 Vh[64 * PSTR];
    __shared__ __nv_bfloat16 Vl[64 * PSTR];

    const int bh = blockIdx.y;
    const int b_ = bh >> 3, h = bh & 7;
    const int m0 = blockIdx.x * 128;
    const __nv_bfloat16* pg = ehg + (size_t)bh * SEQ * SEQ;
    const __nv_bfloat16* lgp = elg + (size_t)bh * SEQ * SEQ;
    const __nv_bfloat16* vg_h = vh + (size_t)bh * HD * SEQ;
    const __nv_bfloat16* vg_l = vl + (size_t)bh * HD * SEQ;
    float* ao = attn + (size_t)bh * SEQ * SEQ;
    const float* ri = rinv + (size_t)bh * SEQ;

    const int tid = threadIdx.x, wid = tid >> 5, lane = tid & 31;
    const int wm = (wid >> 1) * 32;
    const int wn = (wid & 1) * 32;
    const int lg = lane >> 2;
    const int lq = lane & 3;

    float acc[2][4][4];
#pragma unroll
    for (int i = 0; i < 2; i++)
#pragma unroll
        for (int j = 0; j < 4; j++)
#pragma unroll
            for (int r = 0; r < 4; r++) acc[i][j][r] = 0.f;

    for (int k0 = 0; k0 < SEQ; k0 += 64) {
        __syncthreads();
#pragma unroll
        for (int p = 0; p < 4; p++) {
            int f = p * 256 + tid;
            int row = f >> 3, col = (f & 7) * 8;
            uint4 hv = *(const uint4*)(pg + (size_t)(m0 + row) * SEQ + k0 + col);
            *(uint4*)&Ps[row * PSTR + col] = hv;
            if (WRITE_ATTN) {
                uint4 lv = *(const uint4*)(lgp + (size_t)(m0 + row) * SEQ + k0 + col);
                float inv = ri[m0 + row];
                const __nv_bfloat162* hp = (const __nv_bfloat162*)&hv;
                const __nv_bfloat162* lp = (const __nv_bfloat162*)&lv;
                float4 o0, o1;
                o0.x = (__bfloat162float(hp[0].x) + __bfloat162float(lp[0].x)) * inv;
                o0.y = (__bfloat162float(hp[0].y) + __bfloat162float(lp[0].y)) * inv;
                o0.z = (__bfloat162float(hp[1].x) + __bfloat162float(lp[1].x)) * inv;
                o0.w = (__bfloat162float(hp[1].y) + __bfloat162float(lp[1].y)) * inv;
                o1.x = (__bfloat162float(hp[2].x) + __bfloat162float(lp[2].x)) * inv;
                o1.y = (__bfloat162float(hp[2].y) + __bfloat162float(lp[2].y)) * inv;
                o1.z = (__bfloat162float(hp[3].x) + __bfloat162float(lp[3].x)) * inv;
                o1.w = (__bfloat162float(hp[3].y) + __bfloat162float(lp[3].y)) * inv;
                float* ap = ao + (size_t)(m0 + row) * SEQ + k0 + col;
                *(float4*)(ap)     = o0;
                *(float4*)(ap + 4) = o1;
            }
        }
#pragma unroll
        for (int p = 0; p < 2; p++) {
            int f = p * 256 + tid;
            int row = f >> 3, col = (f & 7) * 8;
            *(uint4*)&Vh[row * PSTR + col] =
                *(const uint4*)(vg_h + ((size_t)row << 10) + k0 + col);
            *(uint4*)&Vl[row * PSTR + col] =
                *(const uint4*)(vg_l + ((size_t)row << 10) + k0 + col);
        }
        __syncthreads();

#pragma unroll
        for (int ks = 0; ks < 4; ks++) {
            const int kb = ks * 16;
            uint32_t a[2][4];
#pragma unroll
            for (int i = 0; i < 2; i++) {
                int r = wm + i * 16 + lg;
                int c = kb + lq * 2;
                a[i][0] = *(const uint32_t*)&Ps[r * PSTR + c];
                a[i][1] = *(const uint32_t*)&Ps[(r + 8) * PSTR + c];
                a[i][2] = *(const uint32_t*)&Ps[r * PSTR + c + 8];
                a[i][3] = *(const uint32_t*)&Ps[(r + 8) * PSTR + c + 8];
            }
#pragma unroll
            for (int j = 0; j < 4; j++) {
                int n = wn + j * 8 + lg;
                int ck = kb + lq * 2;
                uint32_t bh0 = *(const uint32_t*)&Vh[n * PSTR + ck];
                uint32_t bh1 = *(const uint32_t*)&Vh[n * PSTR + ck + 8];
                uint32_t bl0 = *(const uint32_t*)&Vl[n * PSTR + ck];
                uint32_t bl1 = *(const uint32_t*)&Vl[n * PSTR + ck + 8];
#pragma unroll
                for (int i = 0; i < 2; i++) {
                    mma_bf16(acc[i][j], a[i], bh0, bh1);
                    mma_bf16(acc[i][j], a[i], bl0, bl1);
                }
            }
        }
    }

#pragma unroll
    for (int i = 0; i < 2; i++) {
        int r1 = m0 + wm + i * 16 + lg;
        int r2 = r1 + 8;
        float inv1 = ri[r1];
        float inv2 = ri[r2];
#pragma unroll
        for (int j = 0; j < 4; j++) {
            int d = wn + j * 8 + lq * 2;
            size_t o1 = ((size_t)(b_ * SEQ) + r1) * DM + h * HD + d;
            size_t o2 = ((size_t)(b_ * SEQ) + r2) * DM + h * HD + d;
            float c00 = acc[i][j][0] * inv1, c01 = acc[i][j][1] * inv1;
            float c10 = acc[i][j][2] * inv2, c11 = acc[i][j][3] * inv2;
            *(uint32_t*)(ch + o1) = packh2(c00, c01);
            *(uint32_t*)(cl + o1) = packl2(c00, c01);
            *(uint32_t*)(ch + o2) = packh2(c10, c11);
            *(uint32_t*)(cl + o2) = packl2(c10, c11);
        }
    }
}

// ===========================================================================
// LayerNorm
// ===========================================================================
__global__ void __launch_bounds__(256)
layernorm_rows(const float* __restrict__ pre, const float* __restrict__ g,
               const float* __restrict__ be, float* __restrict__ out)
{
    int warp = threadIdx.x >> 5, lane = threadIdx.x & 31;
    size_t row = (size_t)blockIdx.x * 8 + warp;
    const float* p = pre + row * DM;

    float x[16];
    float s = 0.f, s2 = 0.f;
#pragma unroll
    for (int i = 0; i < 4; i++) {
        float4 v = *(const float4*)(p + i * 128 + lane * 4);
        x[i * 4 + 0] = v.x; x[i * 4 + 1] = v.y;
        x[i * 4 + 2] = v.z; x[i * 4 + 3] = v.w;
        s  += v.x + v.y + v.z + v.w;
        s2 += v.x * v.x + v.y * v.y + v.z * v.z + v.w * v.w;
    }
#pragma unroll
    for (int o = 16; o; o >>= 1) {
        s  += __shfl_xor_sync(0xffffffffu, s,  o);
        s2 += __shfl_xor_sync(0xffffffffu, s2, o);
    }
    float mu  = s  * (1.f / DM);
    float var = s2 * (1.f / DM) - mu * mu;
    float inv = rsqrtf(var + 1e-6f);

    float* po = out + row * DM;
#pragma unroll
    for (int i = 0; i < 4; i++) {
        float4 w;
        int c = i * 128 + lane * 4;
        w.x = (x[i * 4 + 0] - mu) * inv * g[c + 0] + be[c + 0];
        w.y = (x[i * 4 + 1] - mu) * inv * g[c + 1] + be[c + 1];
        w.z = (x[i * 4 + 2] - mu) * inv * g[c + 2] + be[c + 2];
        w.w = (x[i * 4 + 3] - mu) * inv * g[c + 3] + be[c + 3];
        *(float4*)(po + c) = w;
    }
}

// ---------------------------------------------------------------------------
// Launch
// ---------------------------------------------------------------------------
extern "C" void kernel_launch(void* const* d_in, const int* in_sizes, int n_in,
                              void* d_out, int out_size)
{
    const float* Q   = (const float*)d_in[0];
    const float* K   = (const float*)d_in[1];
    const float* V   = (const float*)d_in[2];
    const int*   mask = (const int*)d_in[3];
    const float* adjoin = (const float*)d_in[4];
    const float* Wq = (const float*)d_in[5];
    const float* bq = (const float*)d_in[6];
    const float* Wk = (const float*)d_in[7];
    const float* bk = (const float*)d_in[8];
    const float* Wv = (const float*)d_in[9];
    const float* bv = (const float*)d_in[10];
    const float* Wo = (const float*)d_in[11];
    const float* bo = (const float*)d_in[12];
    const float* lg = (const float*)d_in[13];
    const float* lb = (const float*)d_in[14];

    float *pb, *afb, *psum, *rinv;
    cudaGetSymbolAddress((void**)&pb,   g_pre);
    cudaGetSymbolAddress((void**)&afb,  g_attn_fb);
    cudaGetSymbolAddress((void**)&psum, g_psum);
    cudaGetSymbolAddress((void**)&rinv, g_rinv);

    __nv_bfloat16 *xh, *xl, *wh, *wl, *qh, *ql, *kh, *kl, *vh, *vl, *eh, *el;
    cudaGetSymbolAddress((void**)&xh, g_xh);
    cudaGetSymbolAddress((void**)&xl, g_xl);
    cudaGetSymbolAddress((void**)&wh, g_wh);
    cudaGetSymbolAddress((void**)&wl, g_wl);
    cudaGetSymbolAddress((void**)&qh, g_qh);
    cudaGetSymbolAddress((void**)&ql, g_ql);
    cudaGetSymbolAddress((void**)&kh, g_kh);
    cudaGetSymbolAddress((void**)&kl, g_kl);
    cudaGetSymbolAddress((void**)&vh, g_vh);
    cudaGetSymbolAddress((void**)&vl, g_vl);
    cudaGetSymbolAddress((void**)&eh, g_eh);
    cudaGetSymbolAddress((void**)&el, g_el);
    const size_t WSZ = (size_t)DM * DM;

    float* out0 = (float*)d_out;
    const size_t OUT0 = (size_t)BSZ * SEQ * DM;
    const size_t ATTN = (size_t)BSZ * NH * SEQ * SEQ;
    const bool need_attn = ((size_t)out_size >= OUT0 + ATTN);
    float* attn = need_attn ? (out0 + OUT0) : afb;

    static int attr_set = 0;
    if (!attr_set) {
        cudaFuncSetAttribute(gemm_proj_mma3<0>,
                             cudaFuncAttributeMaxDynamicSharedMemorySize, PROJ_SMEM);
        cudaFuncSetAttribute(gemm_proj_mma3<1>,
                             cudaFuncAttributeMaxDynamicSharedMemorySize, PROJ_SMEM);
        cudaFuncSetAttribute(gemm_proj_mma3<2>,
                             cudaFuncAttributeMaxDynamicSharedMemorySize, PROJ_SMEM);
        cudaFuncSetAttribute(gemm_scores_exp,
                             cudaFuncAttributeMaxDynamicSharedMemorySize, SCM_SMEM);
        attr_set = 1;
    }

    dim3 wgrid(DM / 32, DM / 32), wblk(32, 8);
    const int XBLK = (int)(((size_t)BSZ * SEQ * DM) / 4 / 256);   // 4096
    dim3 gp(DM / 128, (BSZ * SEQ) / 128);   // (4, 64)

    // 0) Weights -> [n][k] bf16 hi/lo
    convert_w<<<wgrid, wblk>>>(Wq, wh + 0 * WSZ, wl + 0 * WSZ);
    convert_w<<<wgrid, wblk>>>(Wk, wh + 1 * WSZ, wl + 1 * WSZ);
    convert_w<<<wgrid, wblk>>>(Wv, wh + 2 * WSZ, wl + 2 * WSZ);
    convert_w<<<wgrid, wblk>>>(Wo, wh + 3 * WSZ, wl + 3 * WSZ);

    // 1) Projections -> bf16 split q/k [b,h,s,d], v [b,h,d,s]
    convert_x<<<XBLK, 256>>>(Q, xh, xl);
    gemm_proj_mma3<0><<<gp, 256, PROJ_SMEM>>>(xh, xl, wh + 0 * WSZ, wl + 0 * WSZ,
                                              bq, nullptr, nullptr, qh, ql);
    convert_x<<<XBLK, 256>>>(K, xh, xl);
    gemm_proj_mma3<0><<<gp, 256, PROJ_SMEM>>>(xh, xl, wh + 1 * WSZ, wl + 1 * WSZ,
                                              bk, nullptr, nullptr, kh, kl);
    convert_x<<<XBLK, 256>>>(V, xh, xl);
    gemm_proj_mma3<1><<<gp, 256, PROJ_SMEM>>>(xh, xl, wh + 2 * WSZ, wl + 2 * WSZ,
                                              bv, nullptr, nullptr, vh, vl);

    // 2) Scores + mask + adjoin + exp -> eh/el + per-tile row sums
    dim3 gs(SEQ / 128, SEQ / 128, BSZ * NH);
    gemm_scores_exp<<<gs, 256, SCM_SMEM>>>(qh, ql, kh, kl, mask, adjoin,
                                           eh, el, psum);

    // 3) Row sums -> 1/sum
    rowsum_inv<<<(BSZ * NH * SEQ) / 256, 256>>>(psum, rinv);

    // 4) Context (+ fused attn write only if the harness wants attn)
    dim3 gc(SEQ / 128, BSZ * NH);
    if (need_attn)
        gemm_ctx_mma<true><<<gc, 256>>>(eh, el, vh, vl, rinv, attn, xh, xl);
    else
        gemm_ctx_mma<false><<<gc, 256>>>(eh, el, vh, vl, rinv, attn, xh, xl);

    // 5) Output projection + bias + residual(Q)
    gemm_proj_mma3<2><<<gp, 256, PROJ_SMEM>>>(xh, xl, wh + 3 * WSZ, wl + 3 * WSZ,
                                              bo, Q, pb, nullptr, nullptr);

    // 6) LayerNorm -> out
    layernorm_rows<<<(BSZ * SEQ) / 8, 256>>>(pb, lg, lb, out0);
}

// round 14
// speedup vs baseline: 1.2209x; 1.0696x over previous
#include <cuda_runtime.h>
#include <cuda_bf16.h>
#include <math.h>
#include <stdint.h>

// Problem constants
#define BSZ 8
#define SEQ 1024
#define DM  512
#define NH  8
#define HD  64
#define NEGV (-1e9f)

#define XSZ ((size_t)BSZ * SEQ * DM)

// ---------------------------------------------------------------------------
// Scratch
// ---------------------------------------------------------------------------
__device__ float g_pre[(size_t)BSZ * SEQ * DM];
__device__ float g_attn_fb[64];

__device__ __nv_bfloat16 g_xh[3 * XSZ];                  // activation slots hi
__device__ __nv_bfloat16 g_xl[3 * XSZ];                  // activation slots lo
__device__ __nv_bfloat16 g_wh[4][(size_t)DM * DM];       // W^T hi
__device__ __nv_bfloat16 g_wl[4][(size_t)DM * DM];       // W^T lo

__device__ __nv_bfloat16 g_qh[(size_t)BSZ * NH * SEQ * HD];
__device__ __nv_bfloat16 g_ql[(size_t)BSZ * NH * SEQ * HD];
__device__ __nv_bfloat16 g_kh[(size_t)BSZ * NH * SEQ * HD];
__device__ __nv_bfloat16 g_kl[(size_t)BSZ * NH * SEQ * HD];
__device__ __nv_bfloat16 g_vh[(size_t)BSZ * NH * HD * SEQ];  // v hi [b,h,d,s]

__device__ __nv_bfloat16 g_eh[(size_t)BSZ * NH * SEQ * SEQ];
__device__ __nv_bfloat16 g_el[(size_t)BSZ * NH * SEQ * SEQ];
__device__ float g_psum[(size_t)BSZ * NH * SEQ * 8];
__device__ float g_rinv[(size_t)BSZ * NH * SEQ];

// ===========================================================================
// mma.sync bf16 helper (verified mapping)
// ===========================================================================
__device__ __forceinline__ void mma_bf16(float* d, const uint32_t* a,
                                         uint32_t b0, uint32_t b1)
{
    asm volatile(
        "mma.sync.aligned.m16n8k16.row.col.f32.bf16.bf16.f32 "
        "{%0,%1,%2,%3}, {%4,%5,%6,%7}, {%8,%9}, {%0,%1,%2,%3};"
        : "+f"(d[0]), "+f"(d[1]), "+f"(d[2]), "+f"(d[3])
        : "r"(a[0]), "r"(a[1]), "r"(a[2]), "r"(a[3]), "r"(b0), "r"(b1));
}

__device__ __forceinline__ uint32_t packh2(float x, float y) {
    __nv_bfloat162 p = __halves2bfloat162(__float2bfloat16(x), __float2bfloat16(y));
    return *(uint32_t*)&p;
}
__device__ __forceinline__ uint32_t packl2(float x, float y) {
    __nv_bfloat16 hx = __float2bfloat16(x), hy = __float2bfloat16(y);
    __nv_bfloat162 p = __halves2bfloat162(
        __float2bfloat16(x - __bfloat162float(hx)),
        __float2bfloat16(y - __bfloat162float(hy)));
    return *(uint32_t*)&p;
}

// ===========================================================================
// Pre-convert kernels: all 3 activations in one launch; all 4 weights in one.
// ===========================================================================
__global__ void __launch_bounds__(256)
convert_x3(const float* __restrict__ Q, const float* __restrict__ K,
           const float* __restrict__ V,
           __nv_bfloat16* __restrict__ hi, __nv_bfloat16* __restrict__ lo)
{
    const float* src = (blockIdx.y == 0) ? Q : (blockIdx.y == 1) ? K : V;
    size_t slot = (size_t)blockIdx.y * XSZ;
    size_t i = ((size_t)blockIdx.x * 256 + threadIdx.x) * 4;
    float4 v = *(const float4*)(src + i);
    uint2 uh = {packh2(v.x, v.y), packh2(v.z, v.w)};
    uint2 ul = {packl2(v.x, v.y), packl2(v.z, v.w)};
    *(uint2*)(hi + slot + i) = uh;
    *(uint2*)(lo + slot + i) = ul;
}

__global__ void __launch_bounds__(256)
convert_w4(const float* __restrict__ W0, const float* __restrict__ W1,
           const float* __restrict__ W2, const float* __restrict__ W3,
           __nv_bfloat16* __restrict__ th, __nv_bfloat16* __restrict__ tl)
{
    __shared__ float tile[32][33];
    const float* W = (blockIdx.z == 0) ? W0 : (blockIdx.z == 1) ? W1 :
                     (blockIdx.z == 2) ? W2 : W3;
    size_t wo = (size_t)blockIdx.z * DM * DM;
    int tx = threadIdx.x, ty = threadIdx.y;
    int n_in = blockIdx.x * 32 + tx;
    int k0 = blockIdx.y * 32;
#pragma unroll
    for (int j = ty; j < 32; j += 8)
        tile[j][tx] = W[(size_t)(k0 + j) * DM + n_in];
    __syncthreads();
#pragma unroll
    for (int j = ty; j < 32; j += 8) {
        int n = blockIdx.x * 32 + j;
        int k = k0 + tx;
        float v = tile[tx][j];
        __nv_bfloat16 h = __float2bfloat16(v);
        th[wo + (size_t)n * DM + k] = h;
        tl[wo + (size_t)n * DM + k] = __float2bfloat16(v - __bfloat162float(h));
    }
}

// ===========================================================================
// Projection GEMM via mma.sync (proven R8) + PASSES knob
// MODE 0: bf16 hi/lo out [b,h,s,d]; MODE 1: bf16 HI-only [b,h,d,s];
// MODE 2: fp32 + resid row-major
// ===========================================================================
#define PSTR 72
#define PANEL (128 * PSTR)
#define PROJ_SMEM (4 * PANEL * 2)   // 73728 B

template<int MODE, int PASSES>
__global__ void __launch_bounds__(256)
gemm_proj_mma3(const __nv_bfloat16* __restrict__ Ahg,
               const __nv_bfloat16* __restrict__ Alg,
               const __nv_bfloat16* __restrict__ Bhg,
               const __nv_bfloat16* __restrict__ Blg,
               const float* __restrict__ bias, const float* __restrict__ resid,
               float* __restrict__ outf,
               __nv_bfloat16* __restrict__ outh, __nv_bfloat16* __restrict__ outl)
{
    extern __shared__ __nv_bfloat16 sb[];
    __nv_bfloat16* Ah = sb;
    __nv_bfloat16* Al = Ah + PANEL;
    __nv_bfloat16* Bh = Al + PANEL;
    __nv_bfloat16* Bl = Bh + PANEL;

    const int tid = threadIdx.x, wid = tid >> 5, lane = tid & 31;
    const int m0 = blockIdx.y * 128, n0 = blockIdx.x * 128;
    const int wm = (wid >> 2) * 64;
    const int wn = (wid & 3) * 32;
    const int lg = lane >> 2;
    const int lq = lane & 3;

    float acc[4][4][4];
#pragma unroll
    for (int i = 0; i < 4; i++)
#pragma unroll
        for (int j = 0; j < 4; j++)
#pragma unroll
            for (int r = 0; r < 4; r++) acc[i][j][r] = 0.f;

    const int sr = tid >> 3;
    const int sc = (tid & 7) * 8;

    for (int kc = 0; kc < 8; kc++) {
        const int k0 = kc * 64;
        __syncthreads();
#pragma unroll
        for (int p = 0; p < 4; p++) {
            int row = sr + p * 32;
            *(uint4*)&Ah[row * PSTR + sc] =
                *(const uint4*)(Ahg + (size_t)(m0 + row) * DM + k0 + sc);
            *(uint4*)&Al[row * PSTR + sc] =
                *(const uint4*)(Alg + (size_t)(m0 + row) * DM + k0 + sc);
            *(uint4*)&Bh[row * PSTR + sc] =
                *(const uint4*)(Bhg + (size_t)(n0 + row) * DM + k0 + sc);
            *(uint4*)&Bl[row * PSTR + sc] =
                *(const uint4*)(Blg + (size_t)(n0 + row) * DM + k0 + sc);
        }
        __syncthreads();

#pragma unroll
        for (int ks = 0; ks < 4; ks++) {
            const int kb = ks * 16;
            uint32_t ah[4][4], al[4][4];
#pragma unroll
            for (int i = 0; i < 4; i++) {
                int r = wm + i * 16 + lg;
                int c = kb + lq * 2;
                ah[i][0] = *(const uint32_t*)&Ah[r * PSTR + c];
                ah[i][1] = *(const uint32_t*)&Ah[(r + 8) * PSTR + c];
                ah[i][2] = *(const uint32_t*)&Ah[r * PSTR + c + 8];
                ah[i][3] = *(const uint32_t*)&Ah[(r + 8) * PSTR + c + 8];
                if (PASSES >= 3) {
                    al[i][0] = *(const uint32_t*)&Al[r * PSTR + c];
                    al[i][1] = *(const uint32_t*)&Al[(r + 8) * PSTR + c];
                    al[i][2] = *(const uint32_t*)&Al[r * PSTR + c + 8];
                    al[i][3] = *(const uint32_t*)&Al[(r + 8) * PSTR + c + 8];
                }
            }
#pragma unroll
            for (int j = 0; j < 4; j++) {
                int n = wn + j * 8 + lg;
                int ck = kb + lq * 2;
                uint32_t bh0 = *(const uint32_t*)&Bh[n * PSTR + ck];
                uint32_t bh1 = *(const uint32_t*)&Bh[n * PSTR + ck + 8];
                uint32_t bl0 = *(const uint32_t*)&Bl[n * PSTR + ck];
                uint32_t bl1 = *(const uint32_t*)&Bl[n * PSTR + ck + 8];
#pragma unroll
                for (int i = 0; i < 4; i++) {
                    mma_bf16(acc[i][j], ah[i], bh0, bh1);
                    mma_bf16(acc[i][j], ah[i], bl0, bl1);
                    if (PASSES >= 3) mma_bf16(acc[i][j], al[i], bh0, bh1);
                }
            }
        }
    }

#pragma unroll
    for (int i = 0; i < 4; i++) {
        int r1 = m0 + wm + i * 16 + lg;
        int r2 = r1 + 8;
#pragma unroll
        for (int j = 0; j < 4; j++) {
            int n = n0 + wn + j * 8 + lq * 2;
            float b0 = bias[n], b1 = bias[n + 1];
            float v00 = acc[i][j][0] + b0, v01 = acc[i][j][1] + b1;
            float v10 = acc[i][j][2] + b0, v11 = acc[i][j][3] + b1;
            if (MODE == 2) {
                float2 q1 = *(const float2*)(resid + (size_t)r1 * DM + n);
                float2 q2 = *(const float2*)(resid + (size_t)r2 * DM + n);
                float2 o1 = {v00 + q1.x, v01 + q1.y};
                float2 o2 = {v10 + q2.x, v11 + q2.y};
                *(float2*)(outf + (size_t)r1 * DM + n) = o1;
                *(float2*)(outf + (size_t)r2 * DM + n) = o2;
            } else if (MODE == 0) {
                int h = n >> 6, d = n & (HD - 1);
                int b1_ = r1 >> 10, s1 = r1 & (SEQ - 1);
                int b2_ = r2 >> 10, s2 = r2 & (SEQ - 1);
                size_t o1 = (((size_t)(b1_ * NH + h) * SEQ + s1) << 6) + d;
                size_t o2 = (((size_t)(b2_ * NH + h) * SEQ + s2) << 6) + d;
                *(uint32_t*)(outh + o1) = packh2(v00, v01);
                *(uint32_t*)(outl + o1) = packl2(v00, v01);
                *(uint32_t*)(outh + o2) = packh2(v10, v11);
                *(uint32_t*)(outl + o2) = packl2(v10, v11);
            } else {
                int h = n >> 6, d = n & (HD - 1);
                int b1_ = r1 >> 10, s1 = r1 & (SEQ - 1);
                int b2_ = r2 >> 10, s2 = r2 & (SEQ - 1);
                size_t base1 = (((size_t)(b1_ * NH + h) * HD + d) << 10) + s1;
                size_t base2 = (((size_t)(b2_ * NH + h) * HD + d) << 10) + s2;
                outh[base1]       = __float2bfloat16(v00);
                outh[base1 + SEQ] = __float2bfloat16(v01);
                outh[base2]       = __float2bfloat16(v10);
                outh[base2 + SEQ] = __float2bfloat16(v11);
            }
        }
    }
}

// ===========================================================================
// Scores + mask + adjoin + EXP epilogue (no-max softmax, proven R12/13).
// ===========================================================================
#define SCM_SMEM (4 * PANEL * 2)
__global__ void __launch_bounds__(256)
gemm_scores_exp(const __nv_bfloat16* __restrict__ qh, const __nv_bfloat16* __restrict__ ql,
                const __nv_bfloat16* __restrict__ kh, const __nv_bfloat16* __restrict__ kl,
                const int* __restrict__ mask, const float* __restrict__ adjoin,
                __nv_bfloat16* __restrict__ ehg, __nv_bfloat16* __restrict__ elg,
                float* __restrict__ psum)
{
    extern __shared__ __nv_bfloat16 sb[];
    __nv_bfloat16* Qh = sb;
    __nv_bfloat16* Ql = Qh + PANEL;
    __nv_bfloat16* Kh = Ql + PANEL;
    __nv_bfloat16* Kl = Kh + PANEL;
    __shared__ float red2[128 * 4];

    const int bh = blockIdx.z;
    const int b_ = bh >> 3;
    const __nv_bfloat16* qg_h = qh + (size_t)bh * SEQ * HD;
    const __nv_bfloat16* qg_l = ql + (size_t)bh * SEQ * HD;
    const __nv_bfloat16* kg_h = kh + (size_t)bh * SEQ * HD;
    const __nv_bfloat16* kg_l = kl + (size_t)bh * SEQ * HD;
    __nv_bfloat16* eh = ehg + (size_t)bh * SEQ * SEQ;
    __nv_bfloat16* el = elg + (size_t)bh * SEQ * SEQ;

    const int tid = threadIdx.x, wid = tid >> 5, lane = tid & 31;
    const int m0 = blockIdx.y * 128, n0 = blockIdx.x * 128;
    const int wm = (wid >> 2) * 64;
    const int wn = (wid & 3) * 32;
    const int lg = lane >> 2;
    const int lq = lane & 3;

    const int sr = tid >> 3;
    const int sc = (tid & 7) * 8;
#pragma unroll
    for (int p = 0; p < 4; p++) {
        int row = sr + p * 32;
        *(uint4*)&Qh[row * PSTR + sc] = *(const uint4*)(qg_h + (size_t)(m0 + row) * HD + sc);
        *(uint4*)&Ql[row * PSTR + sc] = *(const uint4*)(qg_l + (size_t)(m0 + row) * HD + sc);
        *(uint4*)&Kh[row * PSTR + sc] = *(const uint4*)(kg_h + (size_t)(n0 + row) * HD + sc);
        *(uint4*)&Kl[row * PSTR + sc] = *(const uint4*)(kg_l + (size_t)(n0 + row) * HD + sc);
    }
    __syncthreads();

    float acc[4][4][4];
#pragma unroll
    for (int i = 0; i < 4; i++)
#pragma unroll
        for (int j = 0; j < 4; j++)
#pragma unroll
            for (int r = 0; r < 4; r++) acc[i][j][r] = 0.f;

#pragma unroll
    for (int ks = 0; ks < 4; ks++) {
        const int kb = ks * 16;
        uint32_t ah[4][4], al[4][4];
#pragma unroll
        for (int i = 0; i < 4; i++) {
            int r = wm + i * 16 + lg;
            int c = kb + lq * 2;
            ah[i][0] = *(const uint32_t*)&Qh[r * PSTR + c];
            ah[i][1] = *(const uint32_t*)&Qh[(r + 8) * PSTR + c];
            ah[i][2] = *(const uint32_t*)&Qh[r * PSTR + c + 8];
            ah[i][3] = *(const uint32_t*)&Qh[(r + 8) * PSTR + c + 8];
            al[i][0] = *(const uint32_t*)&Ql[r * PSTR + c];
            al[i][1] = *(const uint32_t*)&Ql[(r + 8) * PSTR + c];
            al[i][2] = *(const uint32_t*)&Ql[r * PSTR + c + 8];
            al[i][3] = *(const uint32_t*)&Ql[(r + 8) * PSTR + c + 8];
        }
#pragma unroll
        for (int j = 0; j < 4; j++) {
            int n = wn + j * 8 + lg;
            int ck = kb + lq * 2;
            uint32_t bh0 = *(const uint32_t*)&Kh[n * PSTR + ck];
            uint32_t bh1 = *(const uint32_t*)&Kh[n * PSTR + ck + 8];
            uint32_t bl0 = *(const uint32_t*)&Kl[n * PSTR + ck];
            uint32_t bl1 = *(const uint32_t*)&Kl[n * PSTR + ck + 8];
#pragma unroll
            for (int i = 0; i < 4; i++) {
                mma_bf16(acc[i][j], ah[i], bh0, bh1);
                mma_bf16(acc[i][j], ah[i], bl0, bl1);
                mma_bf16(acc[i][j], al[i], bh0, bh1);
            }
        }
    }

    const int*   mb = mask   + (size_t)b_ * SEQ * SEQ;
    const float* ab = adjoin + (size_t)b_ * SEQ * SEQ;

    float rs[8];
#pragma unroll
    for (int r = 0; r < 8; r++) rs[r] = 0.f;

#pragma unroll
    for (int i = 0; i < 4; i++) {
        int r1 = m0 + wm + i * 16 + lg;
        int r2 = r1 + 8;
#pragma unroll
        for (int j = 0; j < 4; j++) {
            int n = n0 + wn + j * 8 + lq * 2;
            size_t o1 = (size_t)r1 * SEQ + n;
            size_t o2 = (size_t)r2 * SEQ + n;
            int2   m1 = *(const int2*)(mb + o1);
            int2   m2 = *(const int2*)(mb + o2);
            float2 a1 = *(const float2*)(ab + o1);
            float2 a2 = *(const float2*)(ab + o2);
            float e0 = __expf((m1.x ? NEGV : acc[i][j][0] * 0.125f) + a1.x);
            float e1 = __expf((m1.y ? NEGV : acc[i][j][1] * 0.125f) + a1.y);
            float e2 = __expf((m2.x ? NEGV : acc[i][j][2] * 0.125f) + a2.x);
            float e3 = __expf((m2.y ? NEGV : acc[i][j][3] * 0.125f) + a2.y);
            rs[2 * i]     += e0 + e1;
            rs[2 * i + 1] += e2 + e3;
            *(uint32_t*)(eh + o1) = packh2(e0, e1);
            *(uint32_t*)(el + o1) = packl2(e0, e1);
            *(uint32_t*)(eh + o2) = packh2(e2, e3);
            *(uint32_t*)(el + o2) = packl2(e2, e3);
        }
    }

#pragma unroll
    for (int off = 1; off <= 2; off <<= 1)
#pragma unroll
        for (int r = 0; r < 8; r++)
            rs[r] += __shfl_xor_sync(0xffffffffu, rs[r], off);
    if (lq == 0) {
#pragma unroll
        for (int i = 0; i < 4; i++) {
            int rl = wm + i * 16 + lg;
            red2[rl * 4 + (wid & 3)]       = rs[2 * i];
            red2[(rl + 8) * 4 + (wid & 3)] = rs[2 * i + 1];
        }
    }
    __syncthreads();
    if (tid < 128) {
        float s = red2[tid * 4 + 0] + red2[tid * 4 + 1] +
                  red2[tid * 4 + 2] + red2[tid * 4 + 3];
        psum[((size_t)bh * SEQ + m0 + tid) * 8 + blockIdx.x] = s;
    }
}

// ===========================================================================
// Row-sum reduce + invert
// ===========================================================================
__global__ void __launch_bounds__(256)
rowsum_inv(const float* __restrict__ psum, float* __restrict__ rinv)
{
    int r = blockIdx.x * 256 + threadIdx.x;
    float s = 0.f;
#pragma unroll
    for (int k = 0; k < 8; k++) s += psum[(size_t)r * 8 + k];
    rinv[r] = 1.f / s;
}

// ===========================================================================
// Ctx via mma.sync (single pass E@Vh) + fused attn writer.
// ===========================================================================
__global__ void __launch_bounds__(256)
gemm_ctx_mma(const __nv_bfloat16* __restrict__ ehg, const __nv_bfloat16* __restrict__ elg,
             const __nv_bfloat16* __restrict__ vh,
             const float* __restrict__ rinv, float* __restrict__ attn,
             __nv_bfloat16* __restrict__ ch, __nv_bfloat16* __restrict__ cl)
{
    __shared__ __nv_bfloat16 Ps[128 * PSTR];
    __shared__ __nv_bfloat16 Vh[64 * PSTR];

    const int bh = blockIdx.y;
    const int b_ = bh >> 3, h = bh & 7;
    const int m0 = blockIdx.x * 128;
    const __nv_bfloat16* pg = ehg + (size_t)bh * SEQ * SEQ;
    const __nv_bfloat16* lgp = elg + (size_t)bh * SEQ * SEQ;
    const __nv_bfloat16* vg_h = vh + (size_t)bh * HD * SEQ;
    float* ao = attn + (size_t)bh * SEQ * SEQ;
    const float* ri = rinv + (size_t)bh * SEQ;

    const int tid = threadIdx.x, wid = tid >> 5, lane = tid & 31;
    const int wm = (wid >> 1) * 32;
    const int wn = (wid & 1) * 32;
    const int lg = lane >> 2;
    const int lq = lane & 3;

    float acc[2][4][4];
#pragma unroll
    for (int i = 0; i < 2; i++)
#pragma unroll
        for (int j = 0; j < 4; j++)
#pragma unroll
            for (int r = 0; r < 4; r++) acc[i][j][r] = 0.f;

    for (int k0 = 0; k0 < SEQ; k0 += 64) {
        __syncthreads();
#pragma unroll
        for (int p = 0; p < 4; p++) {
            int f = p * 256 + tid;
            int row = f >> 3, col = (f & 7) * 8;
            uint4 hv = *(const uint4*)(pg + (size_t)(m0 + row) * SEQ + k0 + col);
            *(uint4*)&Ps[row * PSTR + col] = hv;
            {
                uint4 lv = *(const uint4*)(lgp + (size_t)(m0 + row) * SEQ + k0 + col);
                float inv = ri[m0 + row];
                const __nv_bfloat162* hp = (const __nv_bfloat162*)&hv;
                const __nv_bfloat162* lp = (const __nv_bfloat162*)&lv;
                float4 o0, o1;
                o0.x = (__bfloat162float(hp[0].x) + __bfloat162float(lp[0].x)) * inv;
                o0.y = (__bfloat162float(hp[0].y) + __bfloat162float(lp[0].y)) * inv;
                o0.z = (__bfloat162float(hp[1].x) + __bfloat162float(lp[1].x)) * inv;
                o0.w = (__bfloat162float(hp[1].y) + __bfloat162float(lp[1].y)) * inv;
                o1.x = (__bfloat162float(hp[2].x) + __bfloat162float(lp[2].x)) * inv;
                o1.y = (__bfloat162float(hp[2].y) + __bfloat162float(lp[2].y)) * inv;
                o1.z = (__bfloat162float(hp[3].x) + __bfloat162float(lp[3].x)) * inv;
                o1.w = (__bfloat162float(hp[3].y) + __bfloat162float(lp[3].y)) * inv;
                float* ap = ao + (size_t)(m0 + row) * SEQ + k0 + col;
                *(float4*)(ap)     = o0;
                *(float4*)(ap + 4) = o1;
            }
        }
#pragma unroll
        for (int p = 0; p < 2; p++) {
            int f = p * 256 + tid;
            int row = f >> 3, col = (f & 7) * 8;
            *(uint4*)&Vh[row * PSTR + col] =
                *(const uint4*)(vg_h + ((size_t)row << 10) + k0 + col);
        }
        __syncthreads();

#pragma unroll
        for (int ks = 0; ks < 4; ks++) {
            const int kb = ks * 16;
            uint32_t a[2][4];
#pragma unroll
            for (int i = 0; i < 2; i++) {
                int r = wm + i * 16 + lg;
                int c = kb + lq * 2;
                a[i][0] = *(const uint32_t*)&Ps[r * PSTR + c];
                a[i][1] = *(const uint32_t*)&Ps[(r + 8) * PSTR + c];
                a[i][2] = *(const uint32_t*)&Ps[r * PSTR + c + 8];
                a[i][3] = *(const uint32_t*)&Ps[(r + 8) * PSTR + c + 8];
            }
#pragma unroll
            for (int j = 0; j < 4; j++) {
                int n = wn + j * 8 + lg;
                int ck = kb + lq * 2;
                uint32_t bh0 = *(const uint32_t*)&Vh[n * PSTR + ck];
                uint32_t bh1 = *(const uint32_t*)&Vh[n * PSTR + ck + 8];
#pragma unroll
                for (int i = 0; i < 2; i++)
                    mma_bf16(acc[i][j], a[i], bh0, bh1);
            }
        }
    }

#pragma unroll
    for (int i = 0; i < 2; i++) {
        int r1 = m0 + wm + i * 16 + lg;
        int r2 = r1 + 8;
        float inv1 = ri[r1];
        float inv2 = ri[r2];
#pragma unroll
        for (int j = 0; j < 4; j++) {
            int d = wn + j * 8 + lq * 2;
            size_t o1 = ((size_t)(b_ * SEQ) + r1) * DM + h * HD + d;
            size_t o2 = ((size_t)(b_ * SEQ) + r2) * DM + h * HD + d;
            float c00 = acc[i][j][0] * inv1, c01 = acc[i][j][1] * inv1;
            float c10 = acc[i][j][2] * inv2, c11 = acc[i][j][3] * inv2;
            *(uint32_t*)(ch + o1) = packh2(c00, c01);
            *(uint32_t*)(cl + o1) = packl2(c00, c01);
            *(uint32_t*)(ch + o2) = packh2(c10, c11);
            *(uint32_t*)(cl + o2) = packl2(c10, c11);
        }
    }
}

// ===========================================================================
// LayerNorm
// ===========================================================================
__global__ void __launch_bounds__(256)
layernorm_rows(const float* __restrict__ pre, const float* __restrict__ g,
               const float* __restrict__ be, float* __restrict__ out)
{
    int warp = threadIdx.x >> 5, lane = threadIdx.x & 31;
    size_t row = (size_t)blockIdx.x * 8 + warp;
    const float* p = pre + row * DM;

    float x[16];
    float s = 0.f, s2 = 0.f;
#pragma unroll
    for (int i = 0; i < 4; i++) {
        float4 v = *(const float4*)(p + i * 128 + lane * 4);
        x[i * 4 + 0] = v.x; x[i * 4 + 1] = v.y;
        x[i * 4 + 2] = v.z; x[i * 4 + 3] = v.w;
        s  += v.x + v.y + v.z + v.w;
        s2 += v.x * v.x + v.y * v.y + v.z * v.z + v.w * v.w;
    }
#pragma unroll
    for (int o = 16; o; o >>= 1) {
        s  += __shfl_xor_sync(0xffffffffu, s,  o);
        s2 += __shfl_xor_sync(0xffffffffu, s2, o);
    }
    float mu  = s  * (1.f / DM);
    float var = s2 * (1.f / DM) - mu * mu;
    float inv = rsqrtf(var + 1e-6f);

    float* po = out + row * DM;
#pragma unroll
    for (int i = 0; i < 4; i++) {
        float4 w;
        int c = i * 128 + lane * 4;
        w.x = (x[i * 4 + 0] - mu) * inv * g[c + 0] + be[c + 0];
        w.y = (x[i * 4 + 1] - mu) * inv * g[c + 1] + be[c + 1];
        w.z = (x[i * 4 + 2] - mu) * inv * g[c + 2] + be[c + 2];
        w.w = (x[i * 4 + 3] - mu) * inv * g[c + 3] + be[c + 3];
        *(float4*)(po + c) = w;
    }
}

// ---------------------------------------------------------------------------
// Launch
// ---------------------------------------------------------------------------
extern "C" void kernel_launch(void* const* d_in, const int* in_sizes, int n_in,
                              void* d_out, int out_size)
{
    const float* Q   = (const float*)d_in[0];
    const float* K   = (const float*)d_in[1];
    const float* V   = (const float*)d_in[2];
    const int*   mask = (const int*)d_in[3];
    const float* adjoin = (const float*)d_in[4];
    const float* Wq = (const float*)d_in[5];
    const float* bq = (const float*)d_in[6];
    const float* Wk = (const float*)d_in[7];
    const float* bk = (const float*)d_in[8];
    const float* Wv = (const float*)d_in[9];
    const float* bv = (const float*)d_in[10];
    const float* Wo = (const float*)d_in[11];
    const float* bo = (const float*)d_in[12];
    const float* lg = (const float*)d_in[13];
    const float* lb = (const float*)d_in[14];

    float *pb, *afb, *psum, *rinv;
    cudaGetSymbolAddress((void**)&pb,   g_pre);
    cudaGetSymbolAddress((void**)&afb,  g_attn_fb);
    cudaGetSymbolAddress((void**)&psum, g_psum);
    cudaGetSymbolAddress((void**)&rinv, g_rinv);

    __nv_bfloat16 *xh, *xl, *wh, *wl, *qh, *ql, *kh, *kl, *vh, *eh, *el;
    cudaGetSymbolAddress((void**)&xh, g_xh);
    cudaGetSymbolAddress((void**)&xl, g_xl);
    cudaGetSymbolAddress((void**)&wh, g_wh);
    cudaGetSymbolAddress((void**)&wl, g_wl);
    cudaGetSymbolAddress((void**)&qh, g_qh);
    cudaGetSymbolAddress((void**)&ql, g_ql);
    cudaGetSymbolAddress((void**)&kh, g_kh);
    cudaGetSymbolAddress((void**)&kl, g_kl);
    cudaGetSymbolAddress((void**)&vh, g_vh);
    cudaGetSymbolAddress((void**)&eh, g_eh);
    cudaGetSymbolAddress((void**)&el, g_el);
    const size_t WSZ = (size_t)DM * DM;

    float* out0 = (float*)d_out;
    const size_t OUT0 = (size_t)BSZ * SEQ * DM;
    const size_t ATTN = (size_t)BSZ * NH * SEQ * SEQ;
    const bool need_attn = ((size_t)out_size >= OUT0 + ATTN);
    float* attn = need_attn ? (out0 + OUT0) : afb;   // measured: always true

    static int attr_set = 0;
    if (!attr_set) {
        cudaFuncSetAttribute(gemm_proj_mma3<0,3>,
                             cudaFuncAttributeMaxDynamicSharedMemorySize, PROJ_SMEM);
        cudaFuncSetAttribute(gemm_proj_mma3<1,3>,
                             cudaFuncAttributeMaxDynamicSharedMemorySize, PROJ_SMEM);
        cudaFuncSetAttribute(gemm_proj_mma3<2,2>,
                             cudaFuncAttributeMaxDynamicSharedMemorySize, PROJ_SMEM);
        cudaFuncSetAttribute(gemm_scores_exp,
                             cudaFuncAttributeMaxDynamicSharedMemorySize, SCM_SMEM);
        attr_set = 1;
    }

    dim3 wgrid(DM / 32, DM / 32, 4), wblk(32, 8);
    dim3 xgrid((unsigned)(XSZ / 4 / 256), 3);
    dim3 gp(DM / 128, (BSZ * SEQ) / 128);   // (4, 64)

    // 0) All weights -> [n][k] bf16 hi/lo (one launch)
    convert_w4<<<wgrid, wblk>>>(Wq, Wk, Wv, Wo, wh, wl);

    // 1) All activations -> bf16 hi/lo slots (one launch)
    convert_x3<<<xgrid, 256>>>(Q, K, V, xh, xl);

    // 2) Projections
    gemm_proj_mma3<0,3><<<gp, 256, PROJ_SMEM>>>(xh + 0 * XSZ, xl + 0 * XSZ,
                                                wh + 0 * WSZ, wl + 0 * WSZ,
                                                bq, nullptr, nullptr, qh, ql);
    gemm_proj_mma3<0,3><<<gp, 256, PROJ_SMEM>>>(xh + 1 * XSZ, xl + 1 * XSZ,
                                                wh + 1 * WSZ, wl + 1 * WSZ,
                                                bk, nullptr, nullptr, kh, kl);
    gemm_proj_mma3<1,3><<<gp, 256, PROJ_SMEM>>>(xh + 2 * XSZ, xl + 2 * XSZ,
                                                wh + 2 * WSZ, wl + 2 * WSZ,
                                                bv, nullptr, nullptr, vh, nullptr);

    // 3) Scores + mask + adjoin + exp -> eh/el + per-tile row sums
    dim3 gs(SEQ / 128, SEQ / 128, BSZ * NH);
    gemm_scores_exp<<<gs, 256, SCM_SMEM>>>(qh, ql, kh, kl, mask, adjoin,
                                           eh, el, psum);

    // 4) Row sums -> 1/sum
    rowsum_inv<<<(BSZ * NH * SEQ) / 256, 256>>>(psum, rinv);

    // 5) Context (1-pass E@Vh) + fused attn write -> ctx bf16 in slot 0
    dim3 gc(SEQ / 128, BSZ * NH);
    gemm_ctx_mma<<<gc, 256>>>(eh, el, vh, rinv, attn, xh, xl);

    // 6) Output projection (2-pass) + bias + residual(Q)
    gemm_proj_mma3<2,2><<<gp, 256, PROJ_SMEM>>>(xh, xl, wh + 3 * WSZ, wl + 3 * WSZ,
                                                bo, Q, pb, nullptr, nullptr);

    // 7) LayerNorm -> out
    layernorm_rows<<<(BSZ * SEQ) / 8, 256>>>(pb, lg, lb, out0);
}

// round 15
// speedup vs baseline: 1.2415x; 1.0168x over previous
#include <cuda_runtime.h>
#include <cuda_bf16.h>
#include <math.h>
#include <stdint.h>

// Problem constants
#define BSZ 8
#define SEQ 1024
#define DM  512
#define NH  8
#define HD  64
#define NEGV (-1e9f)

#define XSZ ((size_t)BSZ * SEQ * DM)

// ---------------------------------------------------------------------------
// Scratch
// ---------------------------------------------------------------------------
__device__ float g_pre[(size_t)BSZ * SEQ * DM];
__device__ float g_attn_fb[64];

__device__ __nv_bfloat16 g_xh[3 * XSZ];
__device__ __nv_bfloat16 g_xl[3 * XSZ];
__device__ __nv_bfloat16 g_wh[4][(size_t)DM * DM];
__device__ __nv_bfloat16 g_wl[4][(size_t)DM * DM];

__device__ __nv_bfloat16 g_qh[(size_t)BSZ * NH * SEQ * HD];
__device__ __nv_bfloat16 g_ql[(size_t)BSZ * NH * SEQ * HD];
__device__ __nv_bfloat16 g_kh[(size_t)BSZ * NH * SEQ * HD];
__device__ __nv_bfloat16 g_kl[(size_t)BSZ * NH * SEQ * HD];
__device__ __nv_bfloat16 g_vh[(size_t)BSZ * NH * HD * SEQ];

__device__ __nv_bfloat16 g_eh[(size_t)BSZ * NH * SEQ * SEQ];
__device__ __nv_bfloat16 g_el[(size_t)BSZ * NH * SEQ * SEQ];
__device__ float g_psum[(size_t)BSZ * NH * SEQ * 8];
__device__ float g_rinv[(size_t)BSZ * NH * SEQ];

// ===========================================================================
// Helpers
// ===========================================================================
__device__ __forceinline__ void mma_bf16(float* d, const uint32_t* a,
                                         uint32_t b0, uint32_t b1)
{
    asm volatile(
        "mma.sync.aligned.m16n8k16.row.col.f32.bf16.bf16.f32 "
        "{%0,%1,%2,%3}, {%4,%5,%6,%7}, {%8,%9}, {%0,%1,%2,%3};"
        : "+f"(d[0]), "+f"(d[1]), "+f"(d[2]), "+f"(d[3])
        : "r"(a[0]), "r"(a[1]), "r"(a[2]), "r"(a[3]), "r"(b0), "r"(b1));
}

__device__ __forceinline__ uint32_t packh2(float x, float y) {
    __nv_bfloat162 p = __halves2bfloat162(__float2bfloat16(x), __float2bfloat16(y));
    return *(uint32_t*)&p;
}
__device__ __forceinline__ uint32_t packl2(float x, float y) {
    __nv_bfloat16 hx = __float2bfloat16(x), hy = __float2bfloat16(y);
    __nv_bfloat162 p = __halves2bfloat162(
        __float2bfloat16(x - __bfloat162float(hx)),
        __float2bfloat16(y - __bfloat162float(hy)));
    return *(uint32_t*)&p;
}

__device__ __forceinline__ uint32_t smem_u32(const void* p) {
    uint32_t a;
    asm("{ .reg .u64 t; cvta.to.shared.u64 t, %1; cvt.u32.u64 %0, t; }"
        : "=r"(a) : "l"(p));
    return a;
}
__device__ __forceinline__ void cp16(uint32_t dst, const void* src) {
    asm volatile("cp.async.cg.shared.global [%0], [%1], 16;"
                 :: "r"(dst), "l"(src));
}
#define CP_COMMIT() asm volatile("cp.async.commit_group;" ::: "memory")
#define CP_WAIT0()  asm volatile("cp.async.wait_group 0;" ::: "memory")

// ===========================================================================
// Pre-convert kernels (proven R14)
// ===========================================================================
__global__ void __launch_bounds__(256)
convert_x3(const float* __restrict__ Q, const float* __restrict__ K,
           const float* __restrict__ V,
           __nv_bfloat16* __restrict__ hi, __nv_bfloat16* __restrict__ lo)
{
    const float* src = (blockIdx.y == 0) ? Q : (blockIdx.y == 1) ? K : V;
    size_t slot = (size_t)blockIdx.y * XSZ;
    size_t i = ((size_t)blockIdx.x * 256 + threadIdx.x) * 4;
    float4 v = *(const float4*)(src + i);
    uint2 uh = {packh2(v.x, v.y), packh2(v.z, v.w)};
    uint2 ul = {packl2(v.x, v.y), packl2(v.z, v.w)};
    *(uint2*)(hi + slot + i) = uh;
    *(uint2*)(lo + slot + i) = ul;
}

__global__ void __launch_bounds__(256)
convert_w4(const float* __restrict__ W0, const float* __restrict__ W1,
           const float* __restrict__ W2, const float* __restrict__ W3,
           __nv_bfloat16* __restrict__ th, __nv_bfloat16* __restrict__ tl)
{
    __shared__ float tile[32][33];
    const float* W = (blockIdx.z == 0) ? W0 : (blockIdx.z == 1) ? W1 :
                     (blockIdx.z == 2) ? W2 : W3;
    size_t wo = (size_t)blockIdx.z * DM * DM;
    int tx = threadIdx.x, ty = threadIdx.y;
    int n_in = blockIdx.x * 32 + tx;
    int k0 = blockIdx.y * 32;
#pragma unroll
    for (int j = ty; j < 32; j += 8)
        tile[j][tx] = W[(size_t)(k0 + j) * DM + n_in];
    __syncthreads();
#pragma unroll
    for (int j = ty; j < 32; j += 8) {
        int n = blockIdx.x * 32 + j;
        int k = k0 + tx;
        float v = tile[tx][j];
        __nv_bfloat16 h = __float2bfloat16(v);
        th[wo + (size_t)n * DM + k] = h;
        tl[wo + (size_t)n * DM + k] = __float2bfloat16(v - __bfloat162float(h));
    }
}

// ===========================================================================
// Projection GEMM via mma.sync — cp.async DOUBLE-BUFFERED pipeline.
// MODE 0: bf16 hi/lo out [b,h,s,d]; MODE 1: bf16 HI-only [b,h,d,s];
// MODE 2: fp32 + resid row-major.  PASSES: 3 = Ah*Bh+Ah*Bl+Al*Bh, 2 = drop Al*Bh.
// ===========================================================================
#define PSTR 72
#define PANEL (128 * PSTR)
#define PBUF_BYTES (4 * PANEL * 2)          // one buffer: 4 panels
#define PROJ_SMEM (2 * PBUF_BYTES)          // 147456 B, double buffered

template<int MODE, int PASSES>
__global__ void __launch_bounds__(256)
gemm_proj_mma3(const __nv_bfloat16* __restrict__ Ahg,
               const __nv_bfloat16* __restrict__ Alg,
               const __nv_bfloat16* __restrict__ Bhg,
               const __nv_bfloat16* __restrict__ Blg,
               const float* __restrict__ bias, const float* __restrict__ resid,
               float* __restrict__ outf,
               __nv_bfloat16* __restrict__ outh, __nv_bfloat16* __restrict__ outl)
{
    extern __shared__ __nv_bfloat16 sb[];
    const uint32_t sb32 = smem_u32(sb);

    const int tid = threadIdx.x, wid = tid >> 5, lane = tid & 31;
    const int m0 = blockIdx.y * 128, n0 = blockIdx.x * 128;
    const int wm = (wid >> 2) * 64;
    const int wn = (wid & 3) * 32;
    const int lg = lane >> 2;
    const int lq = lane & 3;

    const int sr = tid >> 3;
    const int sc = (tid & 7) * 8;

    // stage chunk kc into buffer b (cp.async, 16B units)
    auto stage = [&](int kc, int b) {
        const int k0 = kc * 64;
        const uint32_t base = sb32 + (uint32_t)b * PBUF_BYTES;
#pragma unroll
        for (int p = 0; p < 4; p++) {
            int row = sr + p * 32;
            uint32_t doff = (uint32_t)(row * PSTR + sc) * 2;
            cp16(base + doff,
                 Ahg + (size_t)(m0 + row) * DM + k0 + sc);
            if (PASSES >= 3)
                cp16(base + PANEL * 2 + doff,
                     Alg + (size_t)(m0 + row) * DM + k0 + sc);
            cp16(base + 2 * PANEL * 2 + doff,
                 Bhg + (size_t)(n0 + row) * DM + k0 + sc);
            cp16(base + 3 * PANEL * 2 + doff,
                 Blg + (size_t)(n0 + row) * DM + k0 + sc);
        }
    };

    float acc[4][4][4];
#pragma unroll
    for (int i = 0; i < 4; i++)
#pragma unroll
        for (int j = 0; j < 4; j++)
#pragma unroll
            for (int r = 0; r < 4; r++) acc[i][j][r] = 0.f;

    stage(0, 0);
    CP_COMMIT();

    for (int kc = 0; kc < 8; kc++) {
        CP_WAIT0();
        __syncthreads();                 // chunk kc visible; prev compute done
        if (kc < 7) { stage(kc + 1, (kc + 1) & 1); CP_COMMIT(); }

        const __nv_bfloat16* Ah = sb + (size_t)(kc & 1) * (4 * PANEL);
        const __nv_bfloat16* Al = Ah + PANEL;
        const __nv_bfloat16* Bh = Al + PANEL;
        const __nv_bfloat16* Bl = Bh + PANEL;

#pragma unroll
        for (int ks = 0; ks < 4; ks++) {
            const int kb = ks * 16;
            uint32_t ah[4][4], al[4][4];
#pragma unroll
            for (int i = 0; i < 4; i++) {
                int r = wm + i * 16 + lg;
                int c = kb + lq * 2;
                ah[i][0] = *(const uint32_t*)&Ah[r * PSTR + c];
                ah[i][1] = *(const uint32_t*)&Ah[(r + 8) * PSTR + c];
                ah[i][2] = *(const uint32_t*)&Ah[r * PSTR + c + 8];
                ah[i][3] = *(const uint32_t*)&Ah[(r + 8) * PSTR + c + 8];
                if (PASSES >= 3) {
                    al[i][0] = *(const uint32_t*)&Al[r * PSTR + c];
                    al[i][1] = *(const uint32_t*)&Al[(r + 8) * PSTR + c];
                    al[i][2] = *(const uint32_t*)&Al[r * PSTR + c + 8];
                    al[i][3] = *(const uint32_t*)&Al[(r + 8) * PSTR + c + 8];
                }
            }
#pragma unroll
            for (int j = 0; j < 4; j++) {
                int n = wn + j * 8 + lg;
                int ck = kb + lq * 2;
                uint32_t bh0 = *(const uint32_t*)&Bh[n * PSTR + ck];
                uint32_t bh1 = *(const uint32_t*)&Bh[n * PSTR + ck + 8];
                uint32_t bl0 = *(const uint32_t*)&Bl[n * PSTR + ck];
                uint32_t bl1 = *(const uint32_t*)&Bl[n * PSTR + ck + 8];
#pragma unroll
                for (int i = 0; i < 4; i++) {
                    mma_bf16(acc[i][j], ah[i], bh0, bh1);
                    mma_bf16(acc[i][j], ah[i], bl0, bl1);
                    if (PASSES >= 3) mma_bf16(acc[i][j], al[i], bh0, bh1);
                }
            }
        }
        __syncthreads();                 // all reads of buf[kc&1] done
    }

#pragma unroll
    for (int i = 0; i < 4; i++) {
        int r1 = m0 + wm + i * 16 + lg;
        int r2 = r1 + 8;
#pragma unroll
        for (int j = 0; j < 4; j++) {
            int n = n0 + wn + j * 8 + lq * 2;
            float b0 = bias[n], b1 = bias[n + 1];
            float v00 = acc[i][j][0] + b0, v01 = acc[i][j][1] + b1;
            float v10 = acc[i][j][2] + b0, v11 = acc[i][j][3] + b1;
            if (MODE == 2) {
                float2 q1 = *(const float2*)(resid + (size_t)r1 * DM + n);
                float2 q2 = *(const float2*)(resid + (size_t)r2 * DM + n);
                float2 o1 = {v00 + q1.x, v01 + q1.y};
                float2 o2 = {v10 + q2.x, v11 + q2.y};
                *(float2*)(outf + (size_t)r1 * DM + n) = o1;
                *(float2*)(outf + (size_t)r2 * DM + n) = o2;
            } else if (MODE == 0) {
                int h = n >> 6, d = n & (HD - 1);
                int b1_ = r1 >> 10, s1 = r1 & (SEQ - 1);
                int b2_ = r2 >> 10, s2 = r2 & (SEQ - 1);
                size_t o1 = (((size_t)(b1_ * NH + h) * SEQ + s1) << 6) + d;
                size_t o2 = (((size_t)(b2_ * NH + h) * SEQ + s2) << 6) + d;
                *(uint32_t*)(outh + o1) = packh2(v00, v01);
                *(uint32_t*)(outl + o1) = packl2(v00, v01);
                *(uint32_t*)(outh + o2) = packh2(v10, v11);
                *(uint32_t*)(outl + o2) = packl2(v10, v11);
            } else {
                int h = n >> 6, d = n & (HD - 1);
                int b1_ = r1 >> 10, s1 = r1 & (SEQ - 1);
                int b2_ = r2 >> 10, s2 = r2 & (SEQ - 1);
                size_t base1 = (((size_t)(b1_ * NH + h) * HD + d) << 10) + s1;
                size_t base2 = (((size_t)(b2_ * NH + h) * HD + d) << 10) + s2;
                outh[base1]       = __float2bfloat16(v00);
                outh[base1 + SEQ] = __float2bfloat16(v01);
                outh[base2]       = __float2bfloat16(v10);
                outh[base2 + SEQ] = __float2bfloat16(v11);
            }
        }
    }
}

// ===========================================================================
// Scores + mask + adjoin + EXP epilogue (proven R12/13/14)
// ===========================================================================
#define SCM_SMEM (4 * PANEL * 2)
__global__ void __launch_bounds__(256)
gemm_scores_exp(const __nv_bfloat16* __restrict__ qh, const __nv_bfloat16* __restrict__ ql,
                const __nv_bfloat16* __restrict__ kh, const __nv_bfloat16* __restrict__ kl,
                const int* __restrict__ mask, const float* __restrict__ adjoin,
                __nv_bfloat16* __restrict__ ehg, __nv_bfloat16* __restrict__ elg,
                float* __restrict__ psum)
{
    extern __shared__ __nv_bfloat16 sb[];
    __nv_bfloat16* Qh = sb;
    __nv_bfloat16* Ql = Qh + PANEL;
    __nv_bfloat16* Kh = Ql + PANEL;
    __nv_bfloat16* Kl = Kh + PANEL;
    __shared__ float red2[128 * 4];

    const int bh = blockIdx.z;
    const int b_ = bh >> 3;
    const __nv_bfloat16* qg_h = qh + (size_t)bh * SEQ * HD;
    const __nv_bfloat16* qg_l = ql + (size_t)bh * SEQ * HD;
    const __nv_bfloat16* kg_h = kh + (size_t)bh * SEQ * HD;
    const __nv_bfloat16* kg_l = kl + (size_t)bh * SEQ * HD;
    __nv_bfloat16* eh = ehg + (size_t)bh * SEQ * SEQ;
    __nv_bfloat16* el = elg + (size_t)bh * SEQ * SEQ;

    const int tid = threadIdx.x, wid = tid >> 5, lane = tid & 31;
    const int m0 = blockIdx.y * 128, n0 = blockIdx.x * 128;
    const int wm = (wid >> 2) * 64;
    const int wn = (wid & 3) * 32;
    const int lg = lane >> 2;
    const int lq = lane & 3;

    const int sr = tid >> 3;
    const int sc = (tid & 7) * 8;
#pragma unroll
    for (int p = 0; p < 4; p++) {
        int row = sr + p * 32;
        *(uint4*)&Qh[row * PSTR + sc] = *(const uint4*)(qg_h + (size_t)(m0 + row) * HD + sc);
        *(uint4*)&Ql[row * PSTR + sc] = *(const uint4*)(qg_l + (size_t)(m0 + row) * HD + sc);
        *(uint4*)&Kh[row * PSTR + sc] = *(const uint4*)(kg_h + (size_t)(n0 + row) * HD + sc);
        *(uint4*)&Kl[row * PSTR + sc] = *(const uint4*)(kg_l + (size_t)(n0 + row) * HD + sc);
    }
    __syncthreads();

    float acc[4][4][4];
#pragma unroll
    for (int i = 0; i < 4; i++)
#pragma unroll
        for (int j = 0; j < 4; j++)
#pragma unroll
            for (int r = 0; r < 4; r++) acc[i][j][r] = 0.f;

#pragma unroll
    for (int ks = 0; ks < 4; ks++) {
        const int kb = ks * 16;
        uint32_t ah[4][4], al[4][4];
#pragma unroll
        for (int i = 0; i < 4; i++) {
            int r = wm + i * 16 + lg;
            int c = kb + lq * 2;
            ah[i][0] = *(const uint32_t*)&Qh[r * PSTR + c];
            ah[i][1] = *(const uint32_t*)&Qh[(r + 8) * PSTR + c];
            ah[i][2] = *(const uint32_t*)&Qh[r * PSTR + c + 8];
            ah[i][3] = *(const uint32_t*)&Qh[(r + 8) * PSTR + c + 8];
            al[i][0] = *(const uint32_t*)&Ql[r * PSTR + c];
            al[i][1] = *(const uint32_t*)&Ql[(r + 8) * PSTR + c];
            al[i][2] = *(const uint32_t*)&Ql[r * PSTR + c + 8];
            al[i][3] = *(const uint32_t*)&Ql[(r + 8) * PSTR + c + 8];
        }
#pragma unroll
        for (int j = 0; j < 4; j++) {
            int n = wn + j * 8 + lg;
            int ck = kb + lq * 2;
            uint32_t bh0 = *(const uint32_t*)&Kh[n * PSTR + ck];
            uint32_t bh1 = *(const uint32_t*)&Kh[n * PSTR + ck + 8];
            uint32_t bl0 = *(const uint32_t*)&Kl[n * PSTR + ck];
            uint32_t bl1 = *(const uint32_t*)&Kl[n * PSTR + ck + 8];
#pragma unroll
            for (int i = 0; i < 4; i++) {
                mma_bf16(acc[i][j], ah[i], bh0, bh1);
                mma_bf16(acc[i][j], ah[i], bl0, bl1);
                mma_bf16(acc[i][j], al[i], bh0, bh1);
            }
        }
    }

    const int*   mb = mask   + (size_t)b_ * SEQ * SEQ;
    const float* ab = adjoin + (size_t)b_ * SEQ * SEQ;

    float rs[8];
#pragma unroll
    for (int r = 0; r < 8; r++) rs[r] = 0.f;

#pragma unroll
    for (int i = 0; i < 4; i++) {
        int r1 = m0 + wm + i * 16 + lg;
        int r2 = r1 + 8;
#pragma unroll
        for (int j = 0; j < 4; j++) {
            int n = n0 + wn + j * 8 + lq * 2;
            size_t o1 = (size_t)r1 * SEQ + n;
            size_t o2 = (size_t)r2 * SEQ + n;
            int2   m1 = *(const int2*)(mb + o1);
            int2   m2 = *(const int2*)(mb + o2);
            float2 a1 = *(const float2*)(ab + o1);
            float2 a2 = *(const float2*)(ab + o2);
            float e0 = __expf((m1.x ? NEGV : acc[i][j][0] * 0.125f) + a1.x);
            float e1 = __expf((m1.y ? NEGV : acc[i][j][1] * 0.125f) + a1.y);
            float e2 = __expf((m2.x ? NEGV : acc[i][j][2] * 0.125f) + a2.x);
            float e3 = __expf((m2.y ? NEGV : acc[i][j][3] * 0.125f) + a2.y);
            rs[2 * i]     += e0 + e1;
            rs[2 * i + 1] += e2 + e3;
            *(uint32_t*)(eh + o1) = packh2(e0, e1);
            *(uint32_t*)(el + o1) = packl2(e0, e1);
            *(uint32_t*)(eh + o2) = packh2(e2, e3);
            *(uint32_t*)(el + o2) = packl2(e2, e3);
        }
    }

#pragma unroll
    for (int off = 1; off <= 2; off <<= 1)
#pragma unroll
        for (int r = 0; r < 8; r++)
            rs[r] += __shfl_xor_sync(0xffffffffu, rs[r], off);
    if (lq == 0) {
#pragma unroll
        for (int i = 0; i < 4; i++) {
            int rl = wm + i * 16 + lg;
            red2[rl * 4 + (wid & 3)]       = rs[2 * i];
            red2[(rl + 8) * 4 + (wid & 3)] = rs[2 * i + 1];
        }
    }
    __syncthreads();
    if (tid < 128) {
        float s = red2[tid * 4 + 0] + red2[tid * 4 + 1] +
                  red2[tid * 4 + 2] + red2[tid * 4 + 3];
        psum[((size_t)bh * SEQ + m0 + tid) * 8 + blockIdx.x] = s;
    }
}

// ===========================================================================
// Row-sum reduce + invert
// ===========================================================================
__global__ void __launch_bounds__(256)
rowsum_inv(const float* __restrict__ psum, float* __restrict__ rinv)
{
    int r = blockIdx.x * 256 + threadIdx.x;
    float s = 0.f;
#pragma unroll
    for (int k = 0; k < 8; k++) s += psum[(size_t)r * 8 + k];
    rinv[r] = 1.f / s;
}

// ===========================================================================
// Ctx via mma.sync (single pass E@Vh) + fused attn writer (proven R14)
// ===========================================================================
__global__ void __launch_bounds__(256)
gemm_ctx_mma(const __nv_bfloat16* __restrict__ ehg, const __nv_bfloat16* __restrict__ elg,
             const __nv_bfloat16* __restrict__ vh,
             const float* __restrict__ rinv, float* __restrict__ attn,
             __nv_bfloat16* __restrict__ ch, __nv_bfloat16* __restrict__ cl)
{
    __shared__ __nv_bfloat16 Ps[128 * PSTR];
    __shared__ __nv_bfloat16 Vh[64 * PSTR];

    const int bh = blockIdx.y;
    const int b_ = bh >> 3, h = bh & 7;
    const int m0 = blockIdx.x * 128;
    const __nv_bfloat16* pg = ehg + (size_t)bh * SEQ * SEQ;
    const __nv_bfloat16* lgp = elg + (size_t)bh * SEQ * SEQ;
    const __nv_bfloat16* vg_h = vh + (size_t)bh * HD * SEQ;
    float* ao = attn + (size_t)bh * SEQ * SEQ;
    const float* ri = rinv + (size_t)bh * SEQ;

    const int tid = threadIdx.x, wid = tid >> 5, lane = tid & 31;
    const int wm = (wid >> 1) * 32;
    const int wn = (wid & 1) * 32;
    const int lg = lane >> 2;
    const int lq = lane & 3;

    float acc[2][4][4];
#pragma unroll
    for (int i = 0; i < 2; i++)
#pragma unroll
        for (int j = 0; j < 4; j++)
#pragma unroll
            for (int r = 0; r < 4; r++) acc[i][j][r] = 0.f;

    for (int k0 = 0; k0 < SEQ; k0 += 64) {
        __syncthreads();
#pragma unroll
        for (int p = 0; p < 4; p++) {
            int f = p * 256 + tid;
            int row = f >> 3, col = (f & 7) * 8;
            uint4 hv = *(const uint4*)(pg + (size_t)(m0 + row) * SEQ + k0 + col);
            *(uint4*)&Ps[row * PSTR + col] = hv;
            {
                uint4 lv = *(const uint4*)(lgp + (size_t)(m0 + row) * SEQ + k0 + col);
                float inv = ri[m0 + row];
                const __nv_bfloat162* hp = (const __nv_bfloat162*)&hv;
                const __nv_bfloat162* lp = (const __nv_bfloat162*)&lv;
                float4 o0, o1;
                o0.x = (__bfloat162float(hp[0].x) + __bfloat162float(lp[0].x)) * inv;
                o0.y = (__bfloat162float(hp[0].y) + __bfloat162float(lp[0].y)) * inv;
                o0.z = (__bfloat162float(hp[1].x) + __bfloat162float(lp[1].x)) * inv;
                o0.w = (__bfloat162float(hp[1].y) + __bfloat162float(lp[1].y)) * inv;
                o1.x = (__bfloat162float(hp[2].x) + __bfloat162float(lp[2].x)) * inv;
                o1.y = (__bfloat162float(hp[2].y) + __bfloat162float(lp[2].y)) * inv;
                o1.z = (__bfloat162float(hp[3].x) + __bfloat162float(lp[3].x)) * inv;
                o1.w = (__bfloat162float(hp[3].y) + __bfloat162float(lp[3].y)) * inv;
                float* ap = ao + (size_t)(m0 + row) * SEQ + k0 + col;
                *(float4*)(ap)     = o0;
                *(float4*)(ap + 4) = o1;
            }
        }
#pragma unroll
        for (int p = 0; p < 2; p++) {
            int f = p * 256 + tid;
            int row = f >> 3, col = (f & 7) * 8;
            *(uint4*)&Vh[row * PSTR + col] =
                *(const uint4*)(vg_h + ((size_t)row << 10) + k0 + col);
        }
        __syncthreads();

#pragma unroll
        for (int ks = 0; ks < 4; ks++) {
            const int kb = ks * 16;
            uint32_t a[2][4];
#pragma unroll
            for (int i = 0; i < 2; i++) {
                int r = wm + i * 16 + lg;
                int c = kb + lq * 2;
                a[i][0] = *(const uint32_t*)&Ps[r * PSTR + c];
                a[i][1] = *(const uint32_t*)&Ps[(r + 8) * PSTR + c];
                a[i][2] = *(const uint32_t*)&Ps[r * PSTR + c + 8];
                a[i][3] = *(const uint32_t*)&Ps[(r + 8) * PSTR + c + 8];
            }
#pragma unroll
            for (int j = 0; j < 4; j++) {
                int n = wn + j * 8 + lg;
                int ck = kb + lq * 2;
                uint32_t bh0 = *(const uint32_t*)&Vh[n * PSTR + ck];
                uint32_t bh1 = *(const uint32_t*)&Vh[n * PSTR + ck + 8];
#pragma unroll
                for (int i = 0; i < 2; i++)
                    mma_bf16(acc[i][j], a[i], bh0, bh1);
            }
        }
    }

#pragma unroll
    for (int i = 0; i < 2; i++) {
        int r1 = m0 + wm + i * 16 + lg;
        int r2 = r1 + 8;
        float inv1 = ri[r1];
        float inv2 = ri[r2];
#pragma unroll
        for (int j = 0; j < 4; j++) {
            int d = wn + j * 8 + lq * 2;
            size_t o1 = ((size_t)(b_ * SEQ) + r1) * DM + h * HD + d;
            size_t o2 = ((size_t)(b_ * SEQ) + r2) * DM + h * HD + d;
            float c00 = acc[i][j][0] * inv1, c01 = acc[i][j][1] * inv1;
            float c10 = acc[i][j][2] * inv2, c11 = acc[i][j][3] * inv2;
            *(uint32_t*)(ch + o1) = packh2(c00, c01);
            *(uint32_t*)(cl + o1) = packl2(c00, c01);
            *(uint32_t*)(ch + o2) = packh2(c10, c11);
            *(uint32_t*)(cl + o2) = packl2(c10, c11);
        }
    }
}

// ===========================================================================
// LayerNorm
// ===========================================================================
__global__ void __launch_bounds__(256)
layernorm_rows(const float* __restrict__ pre, const float* __restrict__ g,
               const float* __restrict__ be, float* __restrict__ out)
{
    int warp = threadIdx.x >> 5, lane = threadIdx.x & 31;
    size_t row = (size_t)blockIdx.x * 8 + warp;
    const float* p = pre + row * DM;

    float x[16];
    float s = 0.f, s2 = 0.f;
#pragma unroll
    for (int i = 0; i < 4; i++) {
        float4 v = *(const float4*)(p + i * 128 + lane * 4);
        x[i * 4 + 0] = v.x; x[i * 4 + 1] = v.y;
        x[i * 4 + 2] = v.z; x[i * 4 + 3] = v.w;
        s  += v.x + v.y + v.z + v.w;
        s2 += v.x * v.x + v.y * v.y + v.z * v.z + v.w * v.w;
    }
#pragma unroll
    for (int o = 16; o; o >>= 1) {
        s  += __shfl_xor_sync(0xffffffffu, s,  o);
        s2 += __shfl_xor_sync(0xffffffffu, s2, o);
    }
    float mu  = s  * (1.f / DM);
    float var = s2 * (1.f / DM) - mu * mu;
    float inv = rsqrtf(var + 1e-6f);

    float* po = out + row * DM;
#pragma unroll
    for (int i = 0; i < 4; i++) {
        float4 w;
        int c = i * 128 + lane * 4;
        w.x = (x[i * 4 + 0] - mu) * inv * g[c + 0] + be[c + 0];
        w.y = (x[i * 4 + 1] - mu) * inv * g[c + 1] + be[c + 1];
        w.z = (x[i * 4 + 2] - mu) * inv * g[c + 2] + be[c + 2];
        w.w = (x[i * 4 + 3] - mu) * inv * g[c + 3] + be[c + 3];
        *(float4*)(po + c) = w;
    }
}

// ---------------------------------------------------------------------------
// Launch
// ---------------------------------------------------------------------------
extern "C" void kernel_launch(void* const* d_in, const int* in_sizes, int n_in,
                              void* d_out, int out_size)
{
    const float* Q   = (const float*)d_in[0];
    const float* K   = (const float*)d_in[1];
    const float* V   = (const float*)d_in[2];
    const int*   mask = (const int*)d_in[3];
    const float* adjoin = (const float*)d_in[4];
    const float* Wq = (const float*)d_in[5];
    const float* bq = (const float*)d_in[6];
    const float* Wk = (const float*)d_in[7];
    const float* bk = (const float*)d_in[8];
    const float* Wv = (const float*)d_in[9];
    const float* bv = (const float*)d_in[10];
    const float* Wo = (const float*)d_in[11];
    const float* bo = (const float*)d_in[12];
    const float* lg = (const float*)d_in[13];
    const float* lb = (const float*)d_in[14];

    float *pb, *afb, *psum, *rinv;
    cudaGetSymbolAddress((void**)&pb,   g_pre);
    cudaGetSymbolAddress((void**)&afb,  g_attn_fb);
    cudaGetSymbolAddress((void**)&psum, g_psum);
    cudaGetSymbolAddress((void**)&rinv, g_rinv);

    __nv_bfloat16 *xh, *xl, *wh, *wl, *qh, *ql, *kh, *kl, *vh, *eh, *el;
    cudaGetSymbolAddress((void**)&xh, g_xh);
    cudaGetSymbolAddress((void**)&xl, g_xl);
    cudaGetSymbolAddress((void**)&wh, g_wh);
    cudaGetSymbolAddress((void**)&wl, g_wl);
    cudaGetSymbolAddress((void**)&qh, g_qh);
    cudaGetSymbolAddress((void**)&ql, g_ql);
    cudaGetSymbolAddress((void**)&kh, g_kh);
    cudaGetSymbolAddress((void**)&kl, g_kl);
    cudaGetSymbolAddress((void**)&vh, g_vh);
    cudaGetSymbolAddress((void**)&eh, g_eh);
    cudaGetSymbolAddress((void**)&el, g_el);
    const size_t WSZ = (size_t)DM * DM;

    float* out0 = (float*)d_out;
    const size_t OUT0 = (size_t)BSZ * SEQ * DM;
    const size_t ATTN = (size_t)BSZ * NH * SEQ * SEQ;
    const bool need_attn = ((size_t)out_size >= OUT0 + ATTN);
    float* attn = need_attn ? (out0 + OUT0) : afb;

    static int attr_set = 0;
    if (!attr_set) {
        cudaFuncSetAttribute(gemm_proj_mma3<0,3>,
                             cudaFuncAttributeMaxDynamicSharedMemorySize, PROJ_SMEM);
        cudaFuncSetAttribute(gemm_proj_mma3<1,3>,
                             cudaFuncAttributeMaxDynamicSharedMemorySize, PROJ_SMEM);
        cudaFuncSetAttribute(gemm_proj_mma3<2,2>,
                             cudaFuncAttributeMaxDynamicSharedMemorySize, PROJ_SMEM);
        cudaFuncSetAttribute(gemm_scores_exp,
                             cudaFuncAttributeMaxDynamicSharedMemorySize, SCM_SMEM);
        attr_set = 1;
    }

    dim3 wgrid(DM / 32, DM / 32, 4), wblk(32, 8);
    dim3 xgrid((unsigned)(XSZ / 4 / 256), 3);
    dim3 gp(DM / 128, (BSZ * SEQ) / 128);   // (4, 64)

    // 0) All weights -> [n][k] bf16 hi/lo
    convert_w4<<<wgrid, wblk>>>(Wq, Wk, Wv, Wo, wh, wl);

    // 1) All activations -> bf16 hi/lo slots
    convert_x3<<<xgrid, 256>>>(Q, K, V, xh, xl);

    // 2) Projections (cp.async double-buffered)
    gemm_proj_mma3<0,3><<<gp, 256, PROJ_SMEM>>>(xh + 0 * XSZ, xl + 0 * XSZ,
                                                wh + 0 * WSZ, wl + 0 * WSZ,
                                                bq, nullptr, nullptr, qh, ql);
    gemm_proj_mma3<0,3><<<gp, 256, PROJ_SMEM>>>(xh + 1 * XSZ, xl + 1 * XSZ,
                                                wh + 1 * WSZ, wl + 1 * WSZ,
                                                bk, nullptr, nullptr, kh, kl);
    gemm_proj_mma3<1,3><<<gp, 256, PROJ_SMEM>>>(xh + 2 * XSZ, xl + 2 * XSZ,
                                                wh + 2 * WSZ, wl + 2 * WSZ,
                                                bv, nullptr, nullptr, vh, nullptr);

    // 3) Scores + mask + adjoin + exp -> eh/el + per-tile row sums
    dim3 gs(SEQ / 128, SEQ / 128, BSZ * NH);
    gemm_scores_exp<<<gs, 256, SCM_SMEM>>>(qh, ql, kh, kl, mask, adjoin,
                                           eh, el, psum);

    // 4) Row sums -> 1/sum
    rowsum_inv<<<(BSZ * NH * SEQ) / 256, 256>>>(psum, rinv);

    // 5) Context (1-pass E@Vh) + fused attn write -> ctx bf16 in slot 0
    dim3 gc(SEQ / 128, BSZ * NH);
    gemm_ctx_mma<<<gc, 256>>>(eh, el, vh, rinv, attn, xh, xl);

    // 6) Output projection (2-pass) + bias + residual(Q)
    gemm_proj_mma3<2,2><<<gp, 256, PROJ_SMEM>>>(xh, xl, wh + 3 * WSZ, wl + 3 * WSZ,
                                                bo, Q, pb, nullptr, nullptr);

    // 7) LayerNorm -> out
    layernorm_rows<<<(BSZ * SEQ) / 8, 256>>>(pb, lg, lb, out0);
}

// round 16
// speedup vs baseline: 1.2769x; 1.0286x over previous
#include <cuda_runtime.h>
#include <cuda_bf16.h>
#include <math.h>
#include <stdint.h>

// Problem constants
#define BSZ 8
#define SEQ 1024
#define DM  512
#define NH  8
#define HD  64
#define NEGV (-1e9f)

#define XSZ ((size_t)BSZ * SEQ * DM)
#define WSZC ((size_t)DM * DM)

// ---------------------------------------------------------------------------
// Scratch
// ---------------------------------------------------------------------------
__device__ float g_pre[(size_t)BSZ * SEQ * DM];
__device__ float g_attn_fb[64];

__device__ __nv_bfloat16 g_xh[3 * XSZ];
__device__ __nv_bfloat16 g_xl[3 * XSZ];
__device__ __nv_bfloat16 g_wh[4][(size_t)DM * DM];
__device__ __nv_bfloat16 g_wl[4][(size_t)DM * DM];

__device__ __nv_bfloat16 g_qh[(size_t)BSZ * NH * SEQ * HD];
__device__ __nv_bfloat16 g_ql[(size_t)BSZ * NH * SEQ * HD];
__device__ __nv_bfloat16 g_kh[(size_t)BSZ * NH * SEQ * HD];
__device__ __nv_bfloat16 g_kl[(size_t)BSZ * NH * SEQ * HD];
__device__ __nv_bfloat16 g_vh[(size_t)BSZ * NH * HD * SEQ];

__device__ __nv_bfloat16 g_eh[(size_t)BSZ * NH * SEQ * SEQ];
__device__ __nv_bfloat16 g_el[(size_t)BSZ * NH * SEQ * SEQ];
__device__ float g_psum[(size_t)BSZ * NH * SEQ * 8];
__device__ float g_rinv[(size_t)BSZ * NH * SEQ];

// ===========================================================================
// Helpers
// ===========================================================================
__device__ __forceinline__ void mma_bf16(float* d, const uint32_t* a,
                                         uint32_t b0, uint32_t b1)
{
    asm volatile(
        "mma.sync.aligned.m16n8k16.row.col.f32.bf16.bf16.f32 "
        "{%0,%1,%2,%3}, {%4,%5,%6,%7}, {%8,%9}, {%0,%1,%2,%3};"
        : "+f"(d[0]), "+f"(d[1]), "+f"(d[2]), "+f"(d[3])
        : "r"(a[0]), "r"(a[1]), "r"(a[2]), "r"(a[3]), "r"(b0), "r"(b1));
}

__device__ __forceinline__ uint32_t packh2(float x, float y) {
    __nv_bfloat162 p = __halves2bfloat162(__float2bfloat16(x), __float2bfloat16(y));
    return *(uint32_t*)&p;
}
__device__ __forceinline__ uint32_t packl2(float x, float y) {
    __nv_bfloat16 hx = __float2bfloat16(x), hy = __float2bfloat16(y);
    __nv_bfloat162 p = __halves2bfloat162(
        __float2bfloat16(x - __bfloat162float(hx)),
        __float2bfloat16(y - __bfloat162float(hy)));
    return *(uint32_t*)&p;
}

__device__ __forceinline__ uint32_t smem_u32(const void* p) {
    uint32_t a;
    asm("{ .reg .u64 t; cvta.to.shared.u64 t, %1; cvt.u32.u64 %0, t; }"
        : "=r"(a) : "l"(p));
    return a;
}
__device__ __forceinline__ void cp16(uint32_t dst, const void* src) {
    asm volatile("cp.async.cg.shared.global [%0], [%1], 16;"
                 :: "r"(dst), "l"(src));
}
#define CP_COMMIT() asm volatile("cp.async.commit_group;" ::: "memory")
#define CP_WAIT0()  asm volatile("cp.async.wait_group 0;" ::: "memory")

// ===========================================================================
// Pre-convert kernels (proven)
// ===========================================================================
__global__ void __launch_bounds__(256)
convert_x3(const float* __restrict__ Q, const float* __restrict__ K,
           const float* __restrict__ V,
           __nv_bfloat16* __restrict__ hi, __nv_bfloat16* __restrict__ lo)
{
    const float* src = (blockIdx.y == 0) ? Q : (blockIdx.y == 1) ? K : V;
    size_t slot = (size_t)blockIdx.y * XSZ;
    size_t i = ((size_t)blockIdx.x * 256 + threadIdx.x) * 4;
    float4 v = *(const float4*)(src + i);
    uint2 uh = {packh2(v.x, v.y), packh2(v.z, v.w)};
    uint2 ul = {packl2(v.x, v.y), packl2(v.z, v.w)};
    *(uint2*)(hi + slot + i) = uh;
    *(uint2*)(lo + slot + i) = ul;
}

__global__ void __launch_bounds__(256)
convert_w4(const float* __restrict__ W0, const float* __restrict__ W1,
           const float* __restrict__ W2, const float* __restrict__ W3,
           __nv_bfloat16* __restrict__ th, __nv_bfloat16* __restrict__ tl)
{
    __shared__ float tile[32][33];
    const float* W = (blockIdx.z == 0) ? W0 : (blockIdx.z == 1) ? W1 :
                     (blockIdx.z == 2) ? W2 : W3;
    size_t wo = (size_t)blockIdx.z * WSZC;
    int tx = threadIdx.x, ty = threadIdx.y;
    int n_in = blockIdx.x * 32 + tx;
    int k0 = blockIdx.y * 32;
#pragma unroll
    for (int j = ty; j < 32; j += 8)
        tile[j][tx] = W[(size_t)(k0 + j) * DM + n_in];
    __syncthreads();
#pragma unroll
    for (int j = ty; j < 32; j += 8) {
        int n = blockIdx.x * 32 + j;
        int k = k0 + tx;
        float v = tile[tx][j];
        __nv_bfloat16 h = __float2bfloat16(v);
        th[wo + (size_t)n * DM + k] = h;
        tl[wo + (size_t)n * DM + k] = __float2bfloat16(v - __bfloat162float(h));
    }
}

// ===========================================================================
// QKV projection (merged): 128m x 64n tile, 8 warps (4x2 of 32x32),
// 2 CTAs/SM, single-buffered cp.async. blockIdx.z selects q/k/v.
// q,k: bf16 hi/lo [b,h,s,d].  v: bf16 hi [b,h,d,s].
// ===========================================================================
#define PSTR 72
#define APAN (128 * PSTR)              // A panel elements
#define BPAN (64 * PSTR)               // B panel elements
#define QKV_SMEM ((2 * APAN + 2 * BPAN) * 2)   // 55296 B

__global__ void __launch_bounds__(256, 2)
gemm_proj_qkv(const __nv_bfloat16* __restrict__ xh, const __nv_bfloat16* __restrict__ xl,
              const __nv_bfloat16* __restrict__ wh, const __nv_bfloat16* __restrict__ wl,
              const float* __restrict__ bq, const float* __restrict__ bk,
              const float* __restrict__ bv,
              __nv_bfloat16* __restrict__ qh, __nv_bfloat16* __restrict__ ql,
              __nv_bfloat16* __restrict__ kh, __nv_bfloat16* __restrict__ kl,
              __nv_bfloat16* __restrict__ vh)
{
    extern __shared__ __nv_bfloat16 sb[];
    __nv_bfloat16* Ah = sb;
    __nv_bfloat16* Al = Ah + APAN;
    __nv_bfloat16* Bh = Al + APAN;
    __nv_bfloat16* Bl = Bh + BPAN;
    const uint32_t sb32 = smem_u32(sb);

    const int z = blockIdx.z;
    const __nv_bfloat16* Ahg = xh + (size_t)z * XSZ;
    const __nv_bfloat16* Alg = xl + (size_t)z * XSZ;
    const __nv_bfloat16* Bhg = wh + (size_t)z * WSZC;
    const __nv_bfloat16* Blg = wl + (size_t)z * WSZC;
    const float* bias = (z == 0) ? bq : (z == 1) ? bk : bv;

    const int tid = threadIdx.x, wid = tid >> 5, lane = tid & 31;
    const int m0 = blockIdx.y * 128, n0 = blockIdx.x * 64;
    const int wm = (wid >> 1) * 32;
    const int wn = (wid & 1) * 32;
    const int lg = lane >> 2;
    const int lq = lane & 3;

    const int sr = tid >> 3;
    const int sc = (tid & 7) * 8;

    float acc[2][4][4];
#pragma unroll
    for (int i = 0; i < 2; i++)
#pragma unroll
        for (int j = 0; j < 4; j++)
#pragma unroll
            for (int r = 0; r < 4; r++) acc[i][j][r] = 0.f;

    for (int kc = 0; kc < 8; kc++) {
        const int k0 = kc * 64;
        __syncthreads();
#pragma unroll
        for (int p = 0; p < 4; p++) {
            int row = sr + p * 32;
            uint32_t doff = (uint32_t)(row * PSTR + sc) * 2;
            cp16(sb32 + doff, Ahg + (size_t)(m0 + row) * DM + k0 + sc);
            cp16(sb32 + APAN * 2 + doff, Alg + (size_t)(m0 + row) * DM + k0 + sc);
        }
#pragma unroll
        for (int p = 0; p < 2; p++) {
            int row = sr + p * 32;
            uint32_t doff = (uint32_t)(row * PSTR + sc) * 2;
            cp16(sb32 + 2 * APAN * 2 + doff, Bhg + (size_t)(n0 + row) * DM + k0 + sc);
            cp16(sb32 + (2 * APAN + BPAN) * 2 + doff,
                 Blg + (size_t)(n0 + row) * DM + k0 + sc);
        }
        CP_COMMIT();
        CP_WAIT0();
        __syncthreads();

#pragma unroll
        for (int ks = 0; ks < 4; ks++) {
            const int kb = ks * 16;
            uint32_t ah[2][4], al[2][4];
#pragma unroll
            for (int i = 0; i < 2; i++) {
                int r = wm + i * 16 + lg;
                int c = kb + lq * 2;
                ah[i][0] = *(const uint32_t*)&Ah[r * PSTR + c];
                ah[i][1] = *(const uint32_t*)&Ah[(r + 8) * PSTR + c];
                ah[i][2] = *(const uint32_t*)&Ah[r * PSTR + c + 8];
                ah[i][3] = *(const uint32_t*)&Ah[(r + 8) * PSTR + c + 8];
                al[i][0] = *(const uint32_t*)&Al[r * PSTR + c];
                al[i][1] = *(const uint32_t*)&Al[(r + 8) * PSTR + c];
                al[i][2] = *(const uint32_t*)&Al[r * PSTR + c + 8];
                al[i][3] = *(const uint32_t*)&Al[(r + 8) * PSTR + c + 8];
            }
#pragma unroll
            for (int j = 0; j < 4; j++) {
                int n = wn + j * 8 + lg;
                int ck = kb + lq * 2;
                uint32_t bh0 = *(const uint32_t*)&Bh[n * PSTR + ck];
                uint32_t bh1 = *(const uint32_t*)&Bh[n * PSTR + ck + 8];
                uint32_t bl0 = *(const uint32_t*)&Bl[n * PSTR + ck];
                uint32_t bl1 = *(const uint32_t*)&Bl[n * PSTR + ck + 8];
#pragma unroll
                for (int i = 0; i < 2; i++) {
                    mma_bf16(acc[i][j], ah[i], bh0, bh1);
                    mma_bf16(acc[i][j], ah[i], bl0, bl1);
                    mma_bf16(acc[i][j], al[i], bh0, bh1);
                }
            }
        }
    }

    __nv_bfloat16* oh = (z == 0) ? qh : (z == 1) ? kh : vh;
    __nv_bfloat16* ol = (z == 0) ? ql : kl;   // unused for z==2

#pragma unroll
    for (int i = 0; i < 2; i++) {
        int r1 = m0 + wm + i * 16 + lg;
        int r2 = r1 + 8;
#pragma unroll
        for (int j = 0; j < 4; j++) {
            int n = n0 + wn + j * 8 + lq * 2;
            float b0 = bias[n], b1 = bias[n + 1];
            float v00 = acc[i][j][0] + b0, v01 = acc[i][j][1] + b1;
            float v10 = acc[i][j][2] + b0, v11 = acc[i][j][3] + b1;
            int h = n >> 6, d = n & (HD - 1);
            int b1_ = r1 >> 10, s1 = r1 & (SEQ - 1);
            int b2_ = r2 >> 10, s2 = r2 & (SEQ - 1);
            if (z < 2) {
                size_t o1 = (((size_t)(b1_ * NH + h) * SEQ + s1) << 6) + d;
                size_t o2 = (((size_t)(b2_ * NH + h) * SEQ + s2) << 6) + d;
                *(uint32_t*)(oh + o1) = packh2(v00, v01);
                *(uint32_t*)(ol + o1) = packl2(v00, v01);
                *(uint32_t*)(oh + o2) = packh2(v10, v11);
                *(uint32_t*)(ol + o2) = packl2(v10, v11);
            } else {
                size_t base1 = (((size_t)(b1_ * NH + h) * HD + d) << 10) + s1;
                size_t base2 = (((size_t)(b2_ * NH + h) * HD + d) << 10) + s2;
                oh[base1]       = __float2bfloat16(v00);
                oh[base1 + SEQ] = __float2bfloat16(v01);
                oh[base2]       = __float2bfloat16(v10);
                oh[base2 + SEQ] = __float2bfloat16(v11);
            }
        }
    }
}

// ===========================================================================
// Output projection: same 128x64 tile, 2 passes, fp32 + resid out.
// ===========================================================================
__global__ void __launch_bounds__(256, 2)
gemm_proj_out(const __nv_bfloat16* __restrict__ Ahg, const __nv_bfloat16* __restrict__ Alg,
              const __nv_bfloat16* __restrict__ Bhg, const __nv_bfloat16* __restrict__ Blg,
              const float* __restrict__ bias, const float* __restrict__ resid,
              float* __restrict__ outf)
{
    extern __shared__ __nv_bfloat16 sb[];
    __nv_bfloat16* Ah = sb;
    __nv_bfloat16* Al = Ah + APAN;    // unused (layout kept)
    __nv_bfloat16* Bh = Al + APAN;
    __nv_bfloat16* Bl = Bh + BPAN;
    const uint32_t sb32 = smem_u32(sb);

    const int tid = threadIdx.x, wid = tid >> 5, lane = tid & 31;
    const int m0 = blockIdx.y * 128, n0 = blockIdx.x * 64;
    const int wm = (wid >> 1) * 32;
    const int wn = (wid & 1) * 32;
    const int lg = lane >> 2;
    const int lq = lane & 3;

    const int sr = tid >> 3;
    const int sc = (tid & 7) * 8;

    float acc[2][4][4];
#pragma unroll
    for (int i = 0; i < 2; i++)
#pragma unroll
        for (int j = 0; j < 4; j++)
#pragma unroll
            for (int r = 0; r < 4; r++) acc[i][j][r] = 0.f;

    for (int kc = 0; kc < 8; kc++) {
        const int k0 = kc * 64;
        __syncthreads();
#pragma unroll
        for (int p = 0; p < 4; p++) {
            int row = sr + p * 32;
            uint32_t doff = (uint32_t)(row * PSTR + sc) * 2;
            cp16(sb32 + doff, Ahg + (size_t)(m0 + row) * DM + k0 + sc);
        }
#pragma unroll
        for (int p = 0; p < 2; p++) {
            int row = sr + p * 32;
            uint32_t doff = (uint32_t)(row * PSTR + sc) * 2;
            cp16(sb32 + 2 * APAN * 2 + doff, Bhg + (size_t)(n0 + row) * DM + k0 + sc);
            cp16(sb32 + (2 * APAN + BPAN) * 2 + doff,
                 Blg + (size_t)(n0 + row) * DM + k0 + sc);
        }
        CP_COMMIT();
        CP_WAIT0();
        __syncthreads();

#pragma unroll
        for (int ks = 0; ks < 4; ks++) {
            const int kb = ks * 16;
            uint32_t ah[2][4];
#pragma unroll
            for (int i = 0; i < 2; i++) {
                int r = wm + i * 16 + lg;
                int c = kb + lq * 2;
                ah[i][0] = *(const uint32_t*)&Ah[r * PSTR + c];
                ah[i][1] = *(const uint32_t*)&Ah[(r + 8) * PSTR + c];
                ah[i][2] = *(const uint32_t*)&Ah[r * PSTR + c + 8];
                ah[i][3] = *(const uint32_t*)&Ah[(r + 8) * PSTR + c + 8];
            }
#pragma unroll
            for (int j = 0; j < 4; j++) {
                int n = wn + j * 8 + lg;
                int ck = kb + lq * 2;
                uint32_t bh0 = *(const uint32_t*)&Bh[n * PSTR + ck];
                uint32_t bh1 = *(const uint32_t*)&Bh[n * PSTR + ck + 8];
                uint32_t bl0 = *(const uint32_t*)&Bl[n * PSTR + ck];
                uint32_t bl1 = *(const uint32_t*)&Bl[n * PSTR + ck + 8];
#pragma unroll
                for (int i = 0; i < 2; i++) {
                    mma_bf16(acc[i][j], ah[i], bh0, bh1);
                    mma_bf16(acc[i][j], ah[i], bl0, bl1);
                }
            }
        }
    }

#pragma unroll
    for (int i = 0; i < 2; i++) {
        int r1 = m0 + wm + i * 16 + lg;
        int r2 = r1 + 8;
#pragma unroll
        for (int j = 0; j < 4; j++) {
            int n = n0 + wn + j * 8 + lq * 2;
            float b0 = bias[n], b1 = bias[n + 1];
            float2 q1 = *(const float2*)(resid + (size_t)r1 * DM + n);
            float2 q2 = *(const float2*)(resid + (size_t)r2 * DM + n);
            float2 o1 = {acc[i][j][0] + b0 + q1.x, acc[i][j][1] + b1 + q1.y};
            float2 o2 = {acc[i][j][2] + b0 + q2.x, acc[i][j][3] + b1 + q2.y};
            *(float2*)(outf + (size_t)r1 * DM + n) = o1;
            *(float2*)(outf + (size_t)r2 * DM + n) = o2;
        }
    }
}

// ===========================================================================
// Scores + mask + adjoin + EXP epilogue (proven R12-R15)
// ===========================================================================
#define PANEL (128 * PSTR)
#define SCM_SMEM (4 * PANEL * 2)
__global__ void __launch_bounds__(256)
gemm_scores_exp(const __nv_bfloat16* __restrict__ qh, const __nv_bfloat16* __restrict__ ql,
                const __nv_bfloat16* __restrict__ kh, const __nv_bfloat16* __restrict__ kl,
                const int* __restrict__ mask, const float* __restrict__ adjoin,
                __nv_bfloat16* __restrict__ ehg, __nv_bfloat16* __restrict__ elg,
                float* __restrict__ psum)
{
    extern __shared__ __nv_bfloat16 sb[];
    __nv_bfloat16* Qh = sb;
    __nv_bfloat16* Ql = Qh + PANEL;
    __nv_bfloat16* Kh = Ql + PANEL;
    __nv_bfloat16* Kl = Kh + PANEL;
    __shared__ float red2[128 * 4];

    const int bh = blockIdx.z;
    const int b_ = bh >> 3;
    const __nv_bfloat16* qg_h = qh + (size_t)bh * SEQ * HD;
    const __nv_bfloat16* qg_l = ql + (size_t)bh * SEQ * HD;
    const __nv_bfloat16* kg_h = kh + (size_t)bh * SEQ * HD;
    const __nv_bfloat16* kg_l = kl + (size_t)bh * SEQ * HD;
    __nv_bfloat16* eh = ehg + (size_t)bh * SEQ * SEQ;
    __nv_bfloat16* el = elg + (size_t)bh * SEQ * SEQ;

    const int tid = threadIdx.x, wid = tid >> 5, lane = tid & 31;
    const int m0 = blockIdx.y * 128, n0 = blockIdx.x * 128;
    const int wm = (wid >> 2) * 64;
    const int wn = (wid & 3) * 32;
    const int lg = lane >> 2;
    const int lq = lane & 3;

    const int sr = tid >> 3;
    const int sc = (tid & 7) * 8;
#pragma unroll
    for (int p = 0; p < 4; p++) {
        int row = sr + p * 32;
        *(uint4*)&Qh[row * PSTR + sc] = *(const uint4*)(qg_h + (size_t)(m0 + row) * HD + sc);
        *(uint4*)&Ql[row * PSTR + sc] = *(const uint4*)(qg_l + (size_t)(m0 + row) * HD + sc);
        *(uint4*)&Kh[row * PSTR + sc] = *(const uint4*)(kg_h + (size_t)(n0 + row) * HD + sc);
        *(uint4*)&Kl[row * PSTR + sc] = *(const uint4*)(kg_l + (size_t)(n0 + row) * HD + sc);
    }
    __syncthreads();

    float acc[4][4][4];
#pragma unroll
    for (int i = 0; i < 4; i++)
#pragma unroll
        for (int j = 0; j < 4; j++)
#pragma unroll
            for (int r = 0; r < 4; r++) acc[i][j][r] = 0.f;

#pragma unroll
    for (int ks = 0; ks < 4; ks++) {
        const int kb = ks * 16;
        uint32_t ah[4][4], al[4][4];
#pragma unroll
        for (int i = 0; i < 4; i++) {
            int r = wm + i * 16 + lg;
            int c = kb + lq * 2;
            ah[i][0] = *(const uint32_t*)&Qh[r * PSTR + c];
            ah[i][1] = *(const uint32_t*)&Qh[(r + 8) * PSTR + c];
            ah[i][2] = *(const uint32_t*)&Qh[r * PSTR + c + 8];
            ah[i][3] = *(const uint32_t*)&Qh[(r + 8) * PSTR + c + 8];
            al[i][0] = *(const uint32_t*)&Ql[r * PSTR + c];
            al[i][1] = *(const uint32_t*)&Ql[(r + 8) * PSTR + c];
            al[i][2] = *(const uint32_t*)&Ql[r * PSTR + c + 8];
            al[i][3] = *(const uint32_t*)&Ql[(r + 8) * PSTR + c + 8];
        }
#pragma unroll
        for (int j = 0; j < 4; j++) {
            int n = wn + j * 8 + lg;
            int ck = kb + lq * 2;
            uint32_t bh0 = *(const uint32_t*)&Kh[n * PSTR + ck];
            uint32_t bh1 = *(const uint32_t*)&Kh[n * PSTR + ck + 8];
            uint32_t bl0 = *(const uint32_t*)&Kl[n * PSTR + ck];
            uint32_t bl1 = *(const uint32_t*)&Kl[n * PSTR + ck + 8];
#pragma unroll
            for (int i = 0; i < 4; i++) {
                mma_bf16(acc[i][j], ah[i], bh0, bh1);
                mma_bf16(acc[i][j], ah[i], bl0, bl1);
                mma_bf16(acc[i][j], al[i], bh0, bh1);
            }
        }
    }

    const int*   mb = mask   + (size_t)b_ * SEQ * SEQ;
    const float* ab = adjoin + (size_t)b_ * SEQ * SEQ;

    float rs[8];
#pragma unroll
    for (int r = 0; r < 8; r++) rs[r] = 0.f;

#pragma unroll
    for (int i = 0; i < 4; i++) {
        int r1 = m0 + wm + i * 16 + lg;
        int r2 = r1 + 8;
#pragma unroll
        for (int j = 0; j < 4; j++) {
            int n = n0 + wn + j * 8 + lq * 2;
            size_t o1 = (size_t)r1 * SEQ + n;
            size_t o2 = (size_t)r2 * SEQ + n;
            int2   m1 = *(const int2*)(mb + o1);
            int2   m2 = *(const int2*)(mb + o2);
            float2 a1 = *(const float2*)(ab + o1);
            float2 a2 = *(const float2*)(ab + o2);
            float e0 = __expf((m1.x ? NEGV : acc[i][j][0] * 0.125f) + a1.x);
            float e1 = __expf((m1.y ? NEGV : acc[i][j][1] * 0.125f) + a1.y);
            float e2 = __expf((m2.x ? NEGV : acc[i][j][2] * 0.125f) + a2.x);
            float e3 = __expf((m2.y ? NEGV : acc[i][j][3] * 0.125f) + a2.y);
            rs[2 * i]     += e0 + e1;
            rs[2 * i + 1] += e2 + e3;
            *(uint32_t*)(eh + o1) = packh2(e0, e1);
            *(uint32_t*)(el + o1) = packl2(e0, e1);
            *(uint32_t*)(eh + o2) = packh2(e2, e3);
            *(uint32_t*)(el + o2) = packl2(e2, e3);
        }
    }

#pragma unroll
    for (int off = 1; off <= 2; off <<= 1)
#pragma unroll
        for (int r = 0; r < 8; r++)
            rs[r] += __shfl_xor_sync(0xffffffffu, rs[r], off);
    if (lq == 0) {
#pragma unroll
        for (int i = 0; i < 4; i++) {
            int rl = wm + i * 16 + lg;
            red2[rl * 4 + (wid & 3)]       = rs[2 * i];
            red2[(rl + 8) * 4 + (wid & 3)] = rs[2 * i + 1];
        }
    }
    __syncthreads();
    if (tid < 128) {
        float s = red2[tid * 4 + 0] + red2[tid * 4 + 1] +
                  red2[tid * 4 + 2] + red2[tid * 4 + 3];
        psum[((size_t)bh * SEQ + m0 + tid) * 8 + blockIdx.x] = s;
    }
}

// ===========================================================================
// Row-sum reduce + invert
// ===========================================================================
__global__ void __launch_bounds__(256)
rowsum_inv(const float* __restrict__ psum, float* __restrict__ rinv)
{
    int r = blockIdx.x * 256 + threadIdx.x;
    float s = 0.f;
#pragma unroll
    for (int k = 0; k < 8; k++) s += psum[(size_t)r * 8 + k];
    rinv[r] = 1.f / s;
}

// ===========================================================================
// Ctx via mma.sync (single pass E@Vh) + fused attn writer (proven R14/15)
// ===========================================================================
__global__ void __launch_bounds__(256)
gemm_ctx_mma(const __nv_bfloat16* __restrict__ ehg, const __nv_bfloat16* __restrict__ elg,
             const __nv_bfloat16* __restrict__ vh,
             const float* __restrict__ rinv, float* __restrict__ attn,
             __nv_bfloat16* __restrict__ ch, __nv_bfloat16* __restrict__ cl)
{
    __shared__ __nv_bfloat16 Ps[128 * PSTR];
    __shared__ __nv_bfloat16 Vh[64 * PSTR];

    const int bh = blockIdx.y;
    const int b_ = bh >> 3, h = bh & 7;
    const int m0 = blockIdx.x * 128;
    const __nv_bfloat16* pg = ehg + (size_t)bh * SEQ * SEQ;
    const __nv_bfloat16* lgp = elg + (size_t)bh * SEQ * SEQ;
    const __nv_bfloat16* vg_h = vh + (size_t)bh * HD * SEQ;
    float* ao = attn + (size_t)bh * SEQ * SEQ;
    const float* ri = rinv + (size_t)bh * SEQ;

    const int tid = threadIdx.x, wid = tid >> 5, lane = tid & 31;
    const int wm = (wid >> 1) * 32;
    const int wn = (wid & 1) * 32;
    const int lg = lane >> 2;
    const int lq = lane & 3;

    float acc[2][4][4];
#pragma unroll
    for (int i = 0; i < 2; i++)
#pragma unroll
        for (int j = 0; j < 4; j++)
#pragma unroll
            for (int r = 0; r < 4; r++) acc[i][j][r] = 0.f;

    for (int k0 = 0; k0 < SEQ; k0 += 64) {
        __syncthreads();
#pragma unroll
        for (int p = 0; p < 4; p++) {
            int f = p * 256 + tid;
            int row = f >> 3, col = (f & 7) * 8;
            uint4 hv = *(const uint4*)(pg + (size_t)(m0 + row) * SEQ + k0 + col);
            *(uint4*)&Ps[row * PSTR + col] = hv;
            {
                uint4 lv = *(const uint4*)(lgp + (size_t)(m0 + row) * SEQ + k0 + col);
                float inv = ri[m0 + row];
                const __nv_bfloat162* hp = (const __nv_bfloat162*)&hv;
                const __nv_bfloat162* lp = (const __nv_bfloat162*)&lv;
                float4 o0, o1;
                o0.x = (__bfloat162float(hp[0].x) + __bfloat162float(lp[0].x)) * inv;
                o0.y = (__bfloat162float(hp[0].y) + __bfloat162float(lp[0].y)) * inv;
                o0.z = (__bfloat162float(hp[1].x) + __bfloat162float(lp[1].x)) * inv;
                o0.w = (__bfloat162float(hp[1].y) + __bfloat162float(lp[1].y)) * inv;
                o1.x = (__bfloat162float(hp[2].x) + __bfloat162float(lp[2].x)) * inv;
                o1.y = (__bfloat162float(hp[2].y) + __bfloat162float(lp[2].y)) * inv;
                o1.z = (__bfloat162float(hp[3].x) + __bfloat162float(lp[3].x)) * inv;
                o1.w = (__bfloat162float(hp[3].y) + __bfloat162float(lp[3].y)) * inv;
                float* ap = ao + (size_t)(m0 + row) * SEQ + k0 + col;
                *(float4*)(ap)     = o0;
                *(float4*)(ap + 4) = o1;
            }
        }
#pragma unroll
        for (int p = 0; p < 2; p++) {
            int f = p * 256 + tid;
            int row = f >> 3, col = (f & 7) * 8;
            *(uint4*)&Vh[row * PSTR + col] =
                *(const uint4*)(vg_h + ((size_t)row << 10) + k0 + col);
        }
        __syncthreads();

#pragma unroll
        for (int ks = 0; ks < 4; ks++) {
            const int kb = ks * 16;
            uint32_t a[2][4];
#pragma unroll
            for (int i = 0; i < 2; i++) {
                int r = wm + i * 16 + lg;
                int c = kb + lq * 2;
                a[i][0] = *(const uint32_t*)&Ps[r * PSTR + c];
                a[i][1] = *(const uint32_t*)&Ps[(r + 8) * PSTR + c];
                a[i][2] = *(const uint32_t*)&Ps[r * PSTR + c + 8];
                a[i][3] = *(const uint32_t*)&Ps[(r + 8) * PSTR + c + 8];
            }
#pragma unroll
            for (int j = 0; j < 4; j++) {
                int n = wn + j * 8 + lg;
                int ck = kb + lq * 2;
                uint32_t bh0 = *(const uint32_t*)&Vh[n * PSTR + ck];
                uint32_t bh1 = *(const uint32_t*)&Vh[n * PSTR + ck + 8];
#pragma unroll
                for (int i = 0; i < 2; i++)
                    mma_bf16(acc[i][j], a[i], bh0, bh1);
            }
        }
    }

#pragma unroll
    for (int i = 0; i < 2; i++) {
        int r1 = m0 + wm + i * 16 + lg;
        int r2 = r1 + 8;
        float inv1 = ri[r1];
        float inv2 = ri[r2];
#pragma unroll
        for (int j = 0; j < 4; j++) {
            int d = wn + j * 8 + lq * 2;
            size_t o1 = ((size_t)(b_ * SEQ) + r1) * DM + h * HD + d;
            size_t o2 = ((size_t)(b_ * SEQ) + r2) * DM + h * HD + d;
            float c00 = acc[i][j][0] * inv1, c01 = acc[i][j][1] * inv1;
            float c10 = acc[i][j][2] * inv2, c11 = acc[i][j][3] * inv2;
            *(uint32_t*)(ch + o1) = packh2(c00, c01);
            *(uint32_t*)(cl + o1) = packl2(c00, c01);
            *(uint32_t*)(ch + o2) = packh2(c10, c11);
            *(uint32_t*)(cl + o2) = packl2(c10, c11);
        }
    }
}

// ===========================================================================
// LayerNorm
// ===========================================================================
__global__ void __launch_bounds__(256)
layernorm_rows(const float* __restrict__ pre, const float* __restrict__ g,
               const float* __restrict__ be, float* __restrict__ out)
{
    int warp = threadIdx.x >> 5, lane = threadIdx.x & 31;
    size_t row = (size_t)blockIdx.x * 8 + warp;
    const float* p = pre + row * DM;

    float x[16];
    float s = 0.f, s2 = 0.f;
#pragma unroll
    for (int i = 0; i < 4; i++) {
        float4 v = *(const float4*)(p + i * 128 + lane * 4);
        x[i * 4 + 0] = v.x; x[i * 4 + 1] = v.y;
        x[i * 4 + 2] = v.z; x[i * 4 + 3] = v.w;
        s  += v.x + v.y + v.z + v.w;
        s2 += v.x * v.x + v.y * v.y + v.z * v.z + v.w * v.w;
    }
#pragma unroll
    for (int o = 16; o; o >>= 1) {
        s  += __shfl_xor_sync(0xffffffffu, s,  o);
        s2 += __shfl_xor_sync(0xffffffffu, s2, o);
    }
    float mu  = s  * (1.f / DM);
    float var = s2 * (1.f / DM) - mu * mu;
    float inv = rsqrtf(var + 1e-6f);

    float* po = out + row * DM;
#pragma unroll
    for (int i = 0; i < 4; i++) {
        float4 w;
        int c = i * 128 + lane * 4;
        w.x = (x[i * 4 + 0] - mu) * inv * g[c + 0] + be[c + 0];
        w.y = (x[i * 4 + 1] - mu) * inv * g[c + 1] + be[c + 1];
        w.z = (x[i * 4 + 2] - mu) * inv * g[c + 2] + be[c + 2];
        w.w = (x[i * 4 + 3] - mu) * inv * g[c + 3] + be[c + 3];
        *(float4*)(po + c) = w;
    }
}

// ---------------------------------------------------------------------------
// Launch
// ---------------------------------------------------------------------------
extern "C" void kernel_launch(void* const* d_in, const int* in_sizes, int n_in,
                              void* d_out, int out_size)
{
    const float* Q   = (const float*)d_in[0];
    const float* K   = (const float*)d_in[1];
    const float* V   = (const float*)d_in[2];
    const int*   mask = (const int*)d_in[3];
    const float* adjoin = (const float*)d_in[4];
    const float* Wq = (const float*)d_in[5];
    const float* bq = (const float*)d_in[6];
    const float* Wk = (const float*)d_in[7];
    const float* bk = (const float*)d_in[8];
    const float* Wv = (const float*)d_in[9];
    const float* bv = (const float*)d_in[10];
    const float* Wo = (const float*)d_in[11];
    const float* bo = (const float*)d_in[12];
    const float* lg = (const float*)d_in[13];
    const float* lb = (const float*)d_in[14];

    float *pb, *afb, *psum, *rinv;
    cudaGetSymbolAddress((void**)&pb,   g_pre);
    cudaGetSymbolAddress((void**)&afb,  g_attn_fb);
    cudaGetSymbolAddress((void**)&psum, g_psum);
    cudaGetSymbolAddress((void**)&rinv, g_rinv);

    __nv_bfloat16 *xh, *xl, *wh, *wl, *qh, *ql, *kh, *kl, *vh, *eh, *el;
    cudaGetSymbolAddress((void**)&xh, g_xh);
    cudaGetSymbolAddress((void**)&xl, g_xl);
    cudaGetSymbolAddress((void**)&wh, g_wh);
    cudaGetSymbolAddress((void**)&wl, g_wl);
    cudaGetSymbolAddress((void**)&qh, g_qh);
    cudaGetSymbolAddress((void**)&ql, g_ql);
    cudaGetSymbolAddress((void**)&kh, g_kh);
    cudaGetSymbolAddress((void**)&kl, g_kl);
    cudaGetSymbolAddress((void**)&vh, g_vh);
    cudaGetSymbolAddress((void**)&eh, g_eh);
    cudaGetSymbolAddress((void**)&el, g_el);

    float* out0 = (float*)d_out;
    const size_t OUT0 = (size_t)BSZ * SEQ * DM;
    const size_t ATTN = (size_t)BSZ * NH * SEQ * SEQ;
    const bool need_attn = ((size_t)out_size >= OUT0 + ATTN);
    float* attn = need_attn ? (out0 + OUT0) : afb;

    static int attr_set = 0;
    if (!attr_set) {
        cudaFuncSetAttribute(gemm_proj_qkv,
                             cudaFuncAttributeMaxDynamicSharedMemorySize, QKV_SMEM);
        cudaFuncSetAttribute(gemm_proj_out,
                             cudaFuncAttributeMaxDynamicSharedMemorySize, QKV_SMEM);
        cudaFuncSetAttribute(gemm_scores_exp,
                             cudaFuncAttributeMaxDynamicSharedMemorySize, SCM_SMEM);
        attr_set = 1;
    }

    dim3 wgrid(DM / 32, DM / 32, 4), wblk(32, 8);
    dim3 xgrid((unsigned)(XSZ / 4 / 256), 3);

    // 0) All weights -> [n][k] bf16 hi/lo
    convert_w4<<<wgrid, wblk>>>(Wq, Wk, Wv, Wo, wh, wl);

    // 1) All activations -> bf16 hi/lo slots
    convert_x3<<<xgrid, 256>>>(Q, K, V, xh, xl);

    // 2) QKV projections: ONE launch, 128x64 tiles, 2 CTAs/SM
    dim3 gq(DM / 64, (BSZ * SEQ) / 128, 3);   // (8, 64, 3)
    gemm_proj_qkv<<<gq, 256, QKV_SMEM>>>(xh, xl, wh, wl, bq, bk, bv,
                                         qh, ql, kh, kl, vh);

    // 3) Scores + mask + adjoin + exp -> eh/el + per-tile row sums
    dim3 gs(SEQ / 128, SEQ / 128, BSZ * NH);
    gemm_scores_exp<<<gs, 256, SCM_SMEM>>>(qh, ql, kh, kl, mask, adjoin,
                                           eh, el, psum);

    // 4) Row sums -> 1/sum
    rowsum_inv<<<(BSZ * NH * SEQ) / 256, 256>>>(psum, rinv);

    // 5) Context (1-pass E@Vh) + fused attn write -> ctx bf16 in slot 0
    dim3 gc(SEQ / 128, BSZ * NH);
    gemm_ctx_mma<<<gc, 256>>>(eh, el, vh, rinv, attn, xh, xl);

    // 6) Output projection (2-pass, 128x64 tiles, 2 CTAs/SM)
    dim3 go(DM / 64, (BSZ * SEQ) / 128);      // (8, 64)
    gemm_proj_out<<<go, 256, QKV_SMEM>>>(xh, xl, wh + 3 * WSZC, wl + 3 * WSZC,
                                         bo, Q, pb);

    // 7) LayerNorm -> out
    layernorm_rows<<<(BSZ * SEQ) / 8, 256>>>(pb, lg, lb, out0);
}

// round 17
// speedup vs baseline: 1.3830x; 1.0831x over previous
#include <cuda_runtime.h>
#include <cuda_bf16.h>
#include <math.h>
#include <stdint.h>

// Problem constants
#define BSZ 8
#define SEQ 1024
#define DM  512
#define NH  8
#define HD  64
#define NEGV (-1e9f)

#define XSZ ((size_t)BSZ * SEQ * DM)
#define WSZC ((size_t)DM * DM)

// ---------------------------------------------------------------------------
// Scratch
// ---------------------------------------------------------------------------
__device__ float g_pre[(size_t)BSZ * SEQ * DM];
__device__ float g_attn_fb[64];
__device__ float g_madj[(size_t)BSZ * SEQ * SEQ];        // mask?NEGV:adjoin

__device__ __nv_bfloat16 g_xh[3 * XSZ];
__device__ __nv_bfloat16 g_xl[3 * XSZ];
__device__ __nv_bfloat16 g_wh[4][(size_t)DM * DM];
__device__ __nv_bfloat16 g_wl[4][(size_t)DM * DM];

__device__ __nv_bfloat16 g_qh[(size_t)BSZ * NH * SEQ * HD];
__device__ __nv_bfloat16 g_ql[(size_t)BSZ * NH * SEQ * HD];
__device__ __nv_bfloat16 g_kh[(size_t)BSZ * NH * SEQ * HD];
__device__ __nv_bfloat16 g_kl[(size_t)BSZ * NH * SEQ * HD];
__device__ __nv_bfloat16 g_vh[(size_t)BSZ * NH * HD * SEQ];

__device__ __nv_bfloat16 g_eh[(size_t)BSZ * NH * SEQ * SEQ];
__device__ __nv_bfloat16 g_el[(size_t)BSZ * NH * SEQ * SEQ];
__device__ float g_psum[(size_t)BSZ * NH * SEQ * 8];
__device__ float g_rinv[(size_t)BSZ * NH * SEQ];

// ===========================================================================
// Helpers
// ===========================================================================
__device__ __forceinline__ void mma_bf16(float* d, const uint32_t* a,
                                         uint32_t b0, uint32_t b1)
{
    asm volatile(
        "mma.sync.aligned.m16n8k16.row.col.f32.bf16.bf16.f32 "
        "{%0,%1,%2,%3}, {%4,%5,%6,%7}, {%8,%9}, {%0,%1,%2,%3};"
        : "+f"(d[0]), "+f"(d[1]), "+f"(d[2]), "+f"(d[3])
        : "r"(a[0]), "r"(a[1]), "r"(a[2]), "r"(a[3]), "r"(b0), "r"(b1));
}

__device__ __forceinline__ uint32_t packh2(float x, float y) {
    __nv_bfloat162 p = __halves2bfloat162(__float2bfloat16(x), __float2bfloat16(y));
    return *(uint32_t*)&p;
}
__device__ __forceinline__ uint32_t packl2(float x, float y) {
    __nv_bfloat16 hx = __float2bfloat16(x), hy = __float2bfloat16(y);
    __nv_bfloat162 p = __halves2bfloat162(
        __float2bfloat16(x - __bfloat162float(hx)),
        __float2bfloat16(y - __bfloat162float(hy)));
    return *(uint32_t*)&p;
}

__device__ __forceinline__ uint32_t smem_u32(const void* p) {
    uint32_t a;
    asm("{ .reg .u64 t; cvta.to.shared.u64 t, %1; cvt.u32.u64 %0, t; }"
        : "=r"(a) : "l"(p));
    return a;
}
__device__ __forceinline__ void cp16(uint32_t dst, const void* src) {
    asm volatile("cp.async.cg.shared.global [%0], [%1], 16;"
                 :: "r"(dst), "l"(src));
}
#define CP_COMMIT() asm volatile("cp.async.commit_group;" ::: "memory")
#define CP_WAIT0()  asm volatile("cp.async.wait_group 0;" ::: "memory")

// ===========================================================================
// Pre-convert kernels
// ===========================================================================
__global__ void __launch_bounds__(256)
convert_x3(const float* __restrict__ Q, const float* __restrict__ K,
           const float* __restrict__ V,
           __nv_bfloat16* __restrict__ hi, __nv_bfloat16* __restrict__ lo)
{
    const float* src = (blockIdx.y == 0) ? Q : (blockIdx.y == 1) ? K : V;
    size_t slot = (size_t)blockIdx.y * XSZ;
    size_t i = ((size_t)blockIdx.x * 256 + threadIdx.x) * 4;
    float4 v = *(const float4*)(src + i);
    uint2 uh = {packh2(v.x, v.y), packh2(v.z, v.w)};
    uint2 ul = {packl2(v.x, v.y), packl2(v.z, v.w)};
    *(uint2*)(hi + slot + i) = uh;
    *(uint2*)(lo + slot + i) = ul;
}

__global__ void __launch_bounds__(256)
convert_w4(const float* __restrict__ W0, const float* __restrict__ W1,
           const float* __restrict__ W2, const float* __restrict__ W3,
           __nv_bfloat16* __restrict__ th, __nv_bfloat16* __restrict__ tl)
{
    __shared__ float tile[32][33];
    const float* W = (blockIdx.z == 0) ? W0 : (blockIdx.z == 1) ? W1 :
                     (blockIdx.z == 2) ? W2 : W3;
    size_t wo = (size_t)blockIdx.z * WSZC;
    int tx = threadIdx.x, ty = threadIdx.y;
    int n_in = blockIdx.x * 32 + tx;
    int k0 = blockIdx.y * 32;
#pragma unroll
    for (int j = ty; j < 32; j += 8)
        tile[j][tx] = W[(size_t)(k0 + j) * DM + n_in];
    __syncthreads();
#pragma unroll
    for (int j = ty; j < 32; j += 8) {
        int n = blockIdx.x * 32 + j;
        int k = k0 + tx;
        float v = tile[tx][j];
        __nv_bfloat16 h = __float2bfloat16(v);
        th[wo + (size_t)n * DM + k] = h;
        tl[wo + (size_t)n * DM + k] = __float2bfloat16(v - __bfloat162float(h));
    }
}

// madj = mask ? NEGV : adjoin   (fp32, one stream)
__global__ void __launch_bounds__(256)
combine_madj(const int* __restrict__ mask, const float* __restrict__ adjoin,
             float* __restrict__ madj)
{
    size_t i = ((size_t)blockIdx.x * 256 + threadIdx.x) * 4;
    int4   m = *(const int4*)(mask + i);
    float4 a = *(const float4*)(adjoin + i);
    float4 o;
    o.x = m.x ? NEGV : a.x;
    o.y = m.y ? NEGV : a.y;
    o.z = m.z ? NEGV : a.z;
    o.w = m.w ? NEGV : a.w;
    *(float4*)(madj + i) = o;
}

// ===========================================================================
// QKV projection (merged, 128x64 tiles, 2 CTAs/SM) — proven R16
// ===========================================================================
#define PSTR 72
#define APAN (128 * PSTR)
#define BPAN (64 * PSTR)
#define QKV_SMEM ((2 * APAN + 2 * BPAN) * 2)   // 55296 B

__global__ void __launch_bounds__(256, 2)
gemm_proj_qkv(const __nv_bfloat16* __restrict__ xh, const __nv_bfloat16* __restrict__ xl,
              const __nv_bfloat16* __restrict__ wh, const __nv_bfloat16* __restrict__ wl,
              const float* __restrict__ bq, const float* __restrict__ bk,
              const float* __restrict__ bv,
              __nv_bfloat16* __restrict__ qh, __nv_bfloat16* __restrict__ ql,
              __nv_bfloat16* __restrict__ kh, __nv_bfloat16* __restrict__ kl,
              __nv_bfloat16* __restrict__ vh)
{
    extern __shared__ __nv_bfloat16 sb[];
    __nv_bfloat16* Ah = sb;
    __nv_bfloat16* Al = Ah + APAN;
    __nv_bfloat16* Bh = Al + APAN;
    __nv_bfloat16* Bl = Bh + BPAN;
    const uint32_t sb32 = smem_u32(sb);

    const int z = blockIdx.z;
    const __nv_bfloat16* Ahg = xh + (size_t)z * XSZ;
    const __nv_bfloat16* Alg = xl + (size_t)z * XSZ;
    const __nv_bfloat16* Bhg = wh + (size_t)z * WSZC;
    const __nv_bfloat16* Blg = wl + (size_t)z * WSZC;
    const float* bias = (z == 0) ? bq : (z == 1) ? bk : bv;

    const int tid = threadIdx.x, wid = tid >> 5, lane = tid & 31;
    const int m0 = blockIdx.y * 128, n0 = blockIdx.x * 64;
    const int wm = (wid >> 1) * 32;
    const int wn = (wid & 1) * 32;
    const int lg = lane >> 2;
    const int lq = lane & 3;

    const int sr = tid >> 3;
    const int sc = (tid & 7) * 8;

    float acc[2][4][4];
#pragma unroll
    for (int i = 0; i < 2; i++)
#pragma unroll
        for (int j = 0; j < 4; j++)
#pragma unroll
            for (int r = 0; r < 4; r++) acc[i][j][r] = 0.f;

    for (int kc = 0; kc < 8; kc++) {
        const int k0 = kc * 64;
        __syncthreads();
#pragma unroll
        for (int p = 0; p < 4; p++) {
            int row = sr + p * 32;
            uint32_t doff = (uint32_t)(row * PSTR + sc) * 2;
            cp16(sb32 + doff, Ahg + (size_t)(m0 + row) * DM + k0 + sc);
            cp16(sb32 + APAN * 2 + doff, Alg + (size_t)(m0 + row) * DM + k0 + sc);
        }
#pragma unroll
        for (int p = 0; p < 2; p++) {
            int row = sr + p * 32;
            uint32_t doff = (uint32_t)(row * PSTR + sc) * 2;
            cp16(sb32 + 2 * APAN * 2 + doff, Bhg + (size_t)(n0 + row) * DM + k0 + sc);
            cp16(sb32 + (2 * APAN + BPAN) * 2 + doff,
                 Blg + (size_t)(n0 + row) * DM + k0 + sc);
        }
        CP_COMMIT();
        CP_WAIT0();
        __syncthreads();

#pragma unroll
        for (int ks = 0; ks < 4; ks++) {
            const int kb = ks * 16;
            uint32_t ah[2][4], al[2][4];
#pragma unroll
            for (int i = 0; i < 2; i++) {
                int r = wm + i * 16 + lg;
                int c = kb + lq * 2;
                ah[i][0] = *(const uint32_t*)&Ah[r * PSTR + c];
                ah[i][1] = *(const uint32_t*)&Ah[(r + 8) * PSTR + c];
                ah[i][2] = *(const uint32_t*)&Ah[r * PSTR + c + 8];
                ah[i][3] = *(const uint32_t*)&Ah[(r + 8) * PSTR + c + 8];
                al[i][0] = *(const uint32_t*)&Al[r * PSTR + c];
                al[i][1] = *(const uint32_t*)&Al[(r + 8) * PSTR + c];
                al[i][2] = *(const uint32_t*)&Al[r * PSTR + c + 8];
                al[i][3] = *(const uint32_t*)&Al[(r + 8) * PSTR + c + 8];
            }
#pragma unroll
            for (int j = 0; j < 4; j++) {
                int n = wn + j * 8 + lg;
                int ck = kb + lq * 2;
                uint32_t bh0 = *(const uint32_t*)&Bh[n * PSTR + ck];
                uint32_t bh1 = *(const uint32_t*)&Bh[n * PSTR + ck + 8];
                uint32_t bl0 = *(const uint32_t*)&Bl[n * PSTR + ck];
                uint32_t bl1 = *(const uint32_t*)&Bl[n * PSTR + ck + 8];
#pragma unroll
                for (int i = 0; i < 2; i++) {
                    mma_bf16(acc[i][j], ah[i], bh0, bh1);
                    mma_bf16(acc[i][j], ah[i], bl0, bl1);
                    mma_bf16(acc[i][j], al[i], bh0, bh1);
                }
            }
        }
    }

    __nv_bfloat16* oh = (z == 0) ? qh : (z == 1) ? kh : vh;
    __nv_bfloat16* ol = (z == 0) ? ql : kl;

#pragma unroll
    for (int i = 0; i < 2; i++) {
        int r1 = m0 + wm + i * 16 + lg;
        int r2 = r1 + 8;
#pragma unroll
        for (int j = 0; j < 4; j++) {
            int n = n0 + wn + j * 8 + lq * 2;
            float b0 = bias[n], b1 = bias[n + 1];
            float v00 = acc[i][j][0] + b0, v01 = acc[i][j][1] + b1;
            float v10 = acc[i][j][2] + b0, v11 = acc[i][j][3] + b1;
            int h = n >> 6, d = n & (HD - 1);
            int b1_ = r1 >> 10, s1 = r1 & (SEQ - 1);
            int b2_ = r2 >> 10, s2 = r2 & (SEQ - 1);
            if (z < 2) {
                size_t o1 = (((size_t)(b1_ * NH + h) * SEQ + s1) << 6) + d;
                size_t o2 = (((size_t)(b2_ * NH + h) * SEQ + s2) << 6) + d;
                *(uint32_t*)(oh + o1) = packh2(v00, v01);
                *(uint32_t*)(ol + o1) = packl2(v00, v01);
                *(uint32_t*)(oh + o2) = packh2(v10, v11);
                *(uint32_t*)(ol + o2) = packl2(v10, v11);
            } else {
                size_t base1 = (((size_t)(b1_ * NH + h) * HD + d) << 10) + s1;
                size_t base2 = (((size_t)(b2_ * NH + h) * HD + d) << 10) + s2;
                oh[base1]       = __float2bfloat16(v00);
                oh[base1 + SEQ] = __float2bfloat16(v01);
                oh[base2]       = __float2bfloat16(v10);
                oh[base2 + SEQ] = __float2bfloat16(v11);
            }
        }
    }
}

// ===========================================================================
// Output projection (128x64 tiles, 2 passes, 2 CTAs/SM) — proven R16
// ===========================================================================
__global__ void __launch_bounds__(256, 2)
gemm_proj_out(const __nv_bfloat16* __restrict__ Ahg, const __nv_bfloat16* __restrict__ Alg,
              const __nv_bfloat16* __restrict__ Bhg, const __nv_bfloat16* __restrict__ Blg,
              const float* __restrict__ bias, const float* __restrict__ resid,
              float* __restrict__ outf)
{
    extern __shared__ __nv_bfloat16 sb[];
    __nv_bfloat16* Ah = sb;
    __nv_bfloat16* Al = Ah + APAN;
    __nv_bfloat16* Bh = Al + APAN;
    __nv_bfloat16* Bl = Bh + BPAN;
    const uint32_t sb32 = smem_u32(sb);

    const int tid = threadIdx.x, wid = tid >> 5, lane = tid & 31;
    const int m0 = blockIdx.y * 128, n0 = blockIdx.x * 64;
    const int wm = (wid >> 1) * 32;
    const int wn = (wid & 1) * 32;
    const int lg = lane >> 2;
    const int lq = lane & 3;

    const int sr = tid >> 3;
    const int sc = (tid & 7) * 8;

    float acc[2][4][4];
#pragma unroll
    for (int i = 0; i < 2; i++)
#pragma unroll
        for (int j = 0; j < 4; j++)
#pragma unroll
            for (int r = 0; r < 4; r++) acc[i][j][r] = 0.f;

    for (int kc = 0; kc < 8; kc++) {
        const int k0 = kc * 64;
        __syncthreads();
#pragma unroll
        for (int p = 0; p < 4; p++) {
            int row = sr + p * 32;
            uint32_t doff = (uint32_t)(row * PSTR + sc) * 2;
            cp16(sb32 + doff, Ahg + (size_t)(m0 + row) * DM + k0 + sc);
        }
#pragma unroll
        for (int p = 0; p < 2; p++) {
            int row = sr + p * 32;
            uint32_t doff = (uint32_t)(row * PSTR + sc) * 2;
            cp16(sb32 + 2 * APAN * 2 + doff, Bhg + (size_t)(n0 + row) * DM + k0 + sc);
            cp16(sb32 + (2 * APAN + BPAN) * 2 + doff,
                 Blg + (size_t)(n0 + row) * DM + k0 + sc);
        }
        CP_COMMIT();
        CP_WAIT0();
        __syncthreads();

#pragma unroll
        for (int ks = 0; ks < 4; ks++) {
            const int kb = ks * 16;
            uint32_t ah[2][4];
#pragma unroll
            for (int i = 0; i < 2; i++) {
                int r = wm + i * 16 + lg;
                int c = kb + lq * 2;
                ah[i][0] = *(const uint32_t*)&Ah[r * PSTR + c];
                ah[i][1] = *(const uint32_t*)&Ah[(r + 8) * PSTR + c];
                ah[i][2] = *(const uint32_t*)&Ah[r * PSTR + c + 8];
                ah[i][3] = *(const uint32_t*)&Ah[(r + 8) * PSTR + c + 8];
            }
#pragma unroll
            for (int j = 0; j < 4; j++) {
                int n = wn + j * 8 + lg;
                int ck = kb + lq * 2;
                uint32_t bh0 = *(const uint32_t*)&Bh[n * PSTR + ck];
                uint32_t bh1 = *(const uint32_t*)&Bh[n * PSTR + ck + 8];
                uint32_t bl0 = *(const uint32_t*)&Bl[n * PSTR + ck];
                uint32_t bl1 = *(const uint32_t*)&Bl[n * PSTR + ck + 8];
#pragma unroll
                for (int i = 0; i < 2; i++) {
                    mma_bf16(acc[i][j], ah[i], bh0, bh1);
                    mma_bf16(acc[i][j], ah[i], bl0, bl1);
                }
            }
        }
    }

#pragma unroll
    for (int i = 0; i < 2; i++) {
        int r1 = m0 + wm + i * 16 + lg;
        int r2 = r1 + 8;
#pragma unroll
        for (int j = 0; j < 4; j++) {
            int n = n0 + wn + j * 8 + lq * 2;
            float b0 = bias[n], b1 = bias[n + 1];
            float2 q1 = *(const float2*)(resid + (size_t)r1 * DM + n);
            float2 q2 = *(const float2*)(resid + (size_t)r2 * DM + n);
            float2 o1 = {acc[i][j][0] + b0 + q1.x, acc[i][j][1] + b1 + q1.y};
            float2 o2 = {acc[i][j][2] + b0 + q2.x, acc[i][j][3] + b1 + q2.y};
            *(float2*)(outf + (size_t)r1 * DM + n) = o1;
            *(float2*)(outf + (size_t)r2 * DM + n) = o2;
        }
    }
}

// ===========================================================================
// Scores + madj + EXP epilogue.  2 CTAs/SM; madj single fp32 stream.
// ===========================================================================
#define PANEL (128 * PSTR)
#define SCM_SMEM (4 * PANEL * 2)
__global__ void __launch_bounds__(256, 2)
gemm_scores_exp(const __nv_bfloat16* __restrict__ qh, const __nv_bfloat16* __restrict__ ql,
                const __nv_bfloat16* __restrict__ kh, const __nv_bfloat16* __restrict__ kl,
                const float* __restrict__ madj,
                __nv_bfloat16* __restrict__ ehg, __nv_bfloat16* __restrict__ elg,
                float* __restrict__ psum)
{
    extern __shared__ __nv_bfloat16 sb[];
    __nv_bfloat16* Qh = sb;
    __nv_bfloat16* Ql = Qh + PANEL;
    __nv_bfloat16* Kh = Ql + PANEL;
    __nv_bfloat16* Kl = Kh + PANEL;
    __shared__ float red2[128 * 4];

    const int bh = blockIdx.z;
    const int b_ = bh >> 3;
    const __nv_bfloat16* qg_h = qh + (size_t)bh * SEQ * HD;
    const __nv_bfloat16* qg_l = ql + (size_t)bh * SEQ * HD;
    const __nv_bfloat16* kg_h = kh + (size_t)bh * SEQ * HD;
    const __nv_bfloat16* kg_l = kl + (size_t)bh * SEQ * HD;
    __nv_bfloat16* eh = ehg + (size_t)bh * SEQ * SEQ;
    __nv_bfloat16* el = elg + (size_t)bh * SEQ * SEQ;

    const int tid = threadIdx.x, wid = tid >> 5, lane = tid & 31;
    const int m0 = blockIdx.y * 128, n0 = blockIdx.x * 128;
    const int wm = (wid >> 2) * 64;
    const int wn = (wid & 3) * 32;
    const int lg = lane >> 2;
    const int lq = lane & 3;

    const int sr = tid >> 3;
    const int sc = (tid & 7) * 8;
#pragma unroll
    for (int p = 0; p < 4; p++) {
        int row = sr + p * 32;
        *(uint4*)&Qh[row * PSTR + sc] = *(const uint4*)(qg_h + (size_t)(m0 + row) * HD + sc);
        *(uint4*)&Ql[row * PSTR + sc] = *(const uint4*)(qg_l + (size_t)(m0 + row) * HD + sc);
        *(uint4*)&Kh[row * PSTR + sc] = *(const uint4*)(kg_h + (size_t)(n0 + row) * HD + sc);
        *(uint4*)&Kl[row * PSTR + sc] = *(const uint4*)(kg_l + (size_t)(n0 + row) * HD + sc);
    }
    __syncthreads();

    float acc[4][4][4];
#pragma unroll
    for (int i = 0; i < 4; i++)
#pragma unroll
        for (int j = 0; j < 4; j++)
#pragma unroll
            for (int r = 0; r < 4; r++) acc[i][j][r] = 0.f;

#pragma unroll
    for (int ks = 0; ks < 4; ks++) {
        const int kb = ks * 16;
        uint32_t ah[4][4], al[4][4];
#pragma unroll
        for (int i = 0; i < 4; i++) {
            int r = wm + i * 16 + lg;
            int c = kb + lq * 2;
            ah[i][0] = *(const uint32_t*)&Qh[r * PSTR + c];
            ah[i][1] = *(const uint32_t*)&Qh[(r + 8) * PSTR + c];
            ah[i][2] = *(const uint32_t*)&Qh[r * PSTR + c + 8];
            ah[i][3] = *(const uint32_t*)&Qh[(r + 8) * PSTR + c + 8];
            al[i][0] = *(const uint32_t*)&Ql[r * PSTR + c];
            al[i][1] = *(const uint32_t*)&Ql[(r + 8) * PSTR + c];
            al[i][2] = *(const uint32_t*)&Ql[r * PSTR + c + 8];
            al[i][3] = *(const uint32_t*)&Ql[(r + 8) * PSTR + c + 8];
        }
#pragma unroll
        for (int j = 0; j < 4; j++) {
            int n = wn + j * 8 + lg;
            int ck = kb + lq * 2;
            uint32_t bh0 = *(const uint32_t*)&Kh[n * PSTR + ck];
            uint32_t bh1 = *(const uint32_t*)&Kh[n * PSTR + ck + 8];
            uint32_t bl0 = *(const uint32_t*)&Kl[n * PSTR + ck];
            uint32_t bl1 = *(const uint32_t*)&Kl[n * PSTR + ck + 8];
#pragma unroll
            for (int i = 0; i < 4; i++) {
                mma_bf16(acc[i][j], ah[i], bh0, bh1);
                mma_bf16(acc[i][j], ah[i], bl0, bl1);
                mma_bf16(acc[i][j], al[i], bh0, bh1);
            }
        }
    }

    const float* mj = madj + (size_t)b_ * SEQ * SEQ;

    float rs[8];
#pragma unroll
    for (int r = 0; r < 8; r++) rs[r] = 0.f;

#pragma unroll
    for (int i = 0; i < 4; i++) {
        int r1 = m0 + wm + i * 16 + lg;
        int r2 = r1 + 8;
#pragma unroll
        for (int j = 0; j < 4; j++) {
            int n = n0 + wn + j * 8 + lq * 2;
            size_t o1 = (size_t)r1 * SEQ + n;
            size_t o2 = (size_t)r2 * SEQ + n;
            float2 a1 = *(const float2*)(mj + o1);
            float2 a2 = *(const float2*)(mj + o2);
            float e0 = __expf(fmaf(acc[i][j][0], 0.125f, a1.x));
            float e1 = __expf(fmaf(acc[i][j][1], 0.125f, a1.y));
            float e2 = __expf(fmaf(acc[i][j][2], 0.125f, a2.x));
            float e3 = __expf(fmaf(acc[i][j][3], 0.125f, a2.y));
            rs[2 * i]     += e0 + e1;
            rs[2 * i + 1] += e2 + e3;
            *(uint32_t*)(eh + o1) = packh2(e0, e1);
            *(uint32_t*)(el + o1) = packl2(e0, e1);
            *(uint32_t*)(eh + o2) = packh2(e2, e3);
            *(uint32_t*)(el + o2) = packl2(e2, e3);
        }
    }

#pragma unroll
    for (int off = 1; off <= 2; off <<= 1)
#pragma unroll
        for (int r = 0; r < 8; r++)
            rs[r] += __shfl_xor_sync(0xffffffffu, rs[r], off);
    if (lq == 0) {
#pragma unroll
        for (int i = 0; i < 4; i++) {
            int rl = wm + i * 16 + lg;
            red2[rl * 4 + (wid & 3)]       = rs[2 * i];
            red2[(rl + 8) * 4 + (wid & 3)] = rs[2 * i + 1];
        }
    }
    __syncthreads();
    if (tid < 128) {
        float s = red2[tid * 4 + 0] + red2[tid * 4 + 1] +
                  red2[tid * 4 + 2] + red2[tid * 4 + 3];
        psum[((size_t)bh * SEQ + m0 + tid) * 8 + blockIdx.x] = s;
    }
}

// ===========================================================================
// Row-sum reduce + invert
// ===========================================================================
__global__ void __launch_bounds__(256)
rowsum_inv(const float* __restrict__ psum, float* __restrict__ rinv)
{
    int r = blockIdx.x * 256 + threadIdx.x;
    float s = 0.f;
#pragma unroll
    for (int k = 0; k < 8; k++) s += psum[(size_t)r * 8 + k];
    rinv[r] = 1.f / s;
}

// ===========================================================================
// Ctx via mma.sync (single pass E@Vh) + fused attn writer (proven)
// ===========================================================================
__global__ void __launch_bounds__(256)
gemm_ctx_mma(const __nv_bfloat16* __restrict__ ehg, const __nv_bfloat16* __restrict__ elg,
             const __nv_bfloat16* __restrict__ vh,
             const float* __restrict__ rinv, float* __restrict__ attn,
             __nv_bfloat16* __restrict__ ch, __nv_bfloat16* __restrict__ cl)
{
    __shared__ __nv_bfloat16 Ps[128 * PSTR];
    __shared__ __nv_bfloat16 Vh[64 * PSTR];

    const int bh = blockIdx.y;
    const int b_ = bh >> 3, h = bh & 7;
    const int m0 = blockIdx.x * 128;
    const __nv_bfloat16* pg = ehg + (size_t)bh * SEQ * SEQ;
    const __nv_bfloat16* lgp = elg + (size_t)bh * SEQ * SEQ;
    const __nv_bfloat16* vg_h = vh + (size_t)bh * HD * SEQ;
    float* ao = attn + (size_t)bh * SEQ * SEQ;
    const float* ri = rinv + (size_t)bh * SEQ;

    const int tid = threadIdx.x, wid = tid >> 5, lane = tid & 31;
    const int wm = (wid >> 1) * 32;
    const int wn = (wid & 1) * 32;
    const int lg = lane >> 2;
    const int lq = lane & 3;

    float acc[2][4][4];
#pragma unroll
    for (int i = 0; i < 2; i++)
#pragma unroll
        for (int j = 0; j < 4; j++)
#pragma unroll
            for (int r = 0; r < 4; r++) acc[i][j][r] = 0.f;

    for (int k0 = 0; k0 < SEQ; k0 += 64) {
        __syncthreads();
#pragma unroll
        for (int p = 0; p < 4; p++) {
            int f = p * 256 + tid;
            int row = f >> 3, col = (f & 7) * 8;
            uint4 hv = *(const uint4*)(pg + (size_t)(m0 + row) * SEQ + k0 + col);
            *(uint4*)&Ps[row * PSTR + col] = hv;
            {
                uint4 lv = *(const uint4*)(lgp + (size_t)(m0 + row) * SEQ + k0 + col);
                float inv = ri[m0 + row];
                const __nv_bfloat162* hp = (const __nv_bfloat162*)&hv;
                const __nv_bfloat162* lp = (const __nv_bfloat162*)&lv;
                float4 o0, o1;
                o0.x = (__bfloat162float(hp[0].x) + __bfloat162float(lp[0].x)) * inv;
                o0.y = (__bfloat162float(hp[0].y) + __bfloat162float(lp[0].y)) * inv;
                o0.z = (__bfloat162float(hp[1].x) + __bfloat162float(lp[1].x)) * inv;
                o0.w = (__bfloat162float(hp[1].y) + __bfloat162float(lp[1].y)) * inv;
                o1.x = (__bfloat162float(hp[2].x) + __bfloat162float(lp[2].x)) * inv;
                o1.y = (__bfloat162float(hp[2].y) + __bfloat162float(lp[2].y)) * inv;
                o1.z = (__bfloat162float(hp[3].x) + __bfloat162float(lp[3].x)) * inv;
                o1.w = (__bfloat162float(hp[3].y) + __bfloat162float(lp[3].y)) * inv;
                float* ap = ao + (size_t)(m0 + row) * SEQ + k0 + col;
                *(float4*)(ap)     = o0;
                *(float4*)(ap + 4) = o1;
            }
        }
#pragma unroll
        for (int p = 0; p < 2; p++) {
            int f = p * 256 + tid;
            int row = f >> 3, col = (f & 7) * 8;
            *(uint4*)&Vh[row * PSTR + col] =
                *(const uint4*)(vg_h + ((size_t)row << 10) + k0 + col);
        }
        __syncthreads();

#pragma unroll
        for (int ks = 0; ks < 4; ks++) {
            const int kb = ks * 16;
            uint32_t a[2][4];
#pragma unroll
            for (int i = 0; i < 2; i++) {
                int r = wm + i * 16 + lg;
                int c = kb + lq * 2;
                a[i][0] = *(const uint32_t*)&Ps[r * PSTR + c];
                a[i][1] = *(const uint32_t*)&Ps[(r + 8) * PSTR + c];
                a[i][2] = *(const uint32_t*)&Ps[r * PSTR + c + 8];
                a[i][3] = *(const uint32_t*)&Ps[(r + 8) * PSTR + c + 8];
            }
#pragma unroll
            for (int j = 0; j < 4; j++) {
                int n = wn + j * 8 + lg;
                int ck = kb + lq * 2;
                uint32_t bh0 = *(const uint32_t*)&Vh[n * PSTR + ck];
                uint32_t bh1 = *(const uint32_t*)&Vh[n * PSTR + ck + 8];
#pragma unroll
                for (int i = 0; i < 2; i++)
                    mma_bf16(acc[i][j], a[i], bh0, bh1);
            }
        }
    }

#pragma unroll
    for (int i = 0; i < 2; i++) {
        int r1 = m0 + wm + i * 16 + lg;
        int r2 = r1 + 8;
        float inv1 = ri[r1];
        float inv2 = ri[r2];
#pragma unroll
        for (int j = 0; j < 4; j++) {
            int d = wn + j * 8 + lq * 2;
            size_t o1 = ((size_t)(b_ * SEQ) + r1) * DM + h * HD + d;
            size_t o2 = ((size_t)(b_ * SEQ) + r2) * DM + h * HD + d;
            float c00 = acc[i][j][0] * inv1, c01 = acc[i][j][1] * inv1;
            float c10 = acc[i][j][2] * inv2, c11 = acc[i][j][3] * inv2;
            *(uint32_t*)(ch + o1) = packh2(c00, c01);
            *(uint32_t*)(cl + o1) = packl2(c00, c01);
            *(uint32_t*)(ch + o2) = packh2(c10, c11);
            *(uint32_t*)(cl + o2) = packl2(c10, c11);
        }
    }
}

// ===========================================================================
// LayerNorm
// ===========================================================================
__global__ void __launch_bounds__(256)
layernorm_rows(const float* __restrict__ pre, const float* __restrict__ g,
               const float* __restrict__ be, float* __restrict__ out)
{
    int warp = threadIdx.x >> 5, lane = threadIdx.x & 31;
    size_t row = (size_t)blockIdx.x * 8 + warp;
    const float* p = pre + row * DM;

    float x[16];
    float s = 0.f, s2 = 0.f;
#pragma unroll
    for (int i = 0; i < 4; i++) {
        float4 v = *(const float4*)(p + i * 128 + lane * 4);
        x[i * 4 + 0] = v.x; x[i * 4 + 1] = v.y;
        x[i * 4 + 2] = v.z; x[i * 4 + 3] = v.w;
        s  += v.x + v.y + v.z + v.w;
        s2 += v.x * v.x + v.y * v.y + v.z * v.z + v.w * v.w;
    }
#pragma unroll
    for (int o = 16; o; o >>= 1) {
        s  += __shfl_xor_sync(0xffffffffu, s,  o);
        s2 += __shfl_xor_sync(0xffffffffu, s2, o);
    }
    float mu  = s  * (1.f / DM);
    float var = s2 * (1.f / DM) - mu * mu;
    float inv = rsqrtf(var + 1e-6f);

    float* po = out + row * DM;
#pragma unroll
    for (int i = 0; i < 4; i++) {
        float4 w;
        int c = i * 128 + lane * 4;
        w.x = (x[i * 4 + 0] - mu) * inv * g[c + 0] + be[c + 0];
        w.y = (x[i * 4 + 1] - mu) * inv * g[c + 1] + be[c + 1];
        w.z = (x[i * 4 + 2] - mu) * inv * g[c + 2] + be[c + 2];
        w.w = (x[i * 4 + 3] - mu) * inv * g[c + 3] + be[c + 3];
        *(float4*)(po + c) = w;
    }
}

// ---------------------------------------------------------------------------
// Launch
// ---------------------------------------------------------------------------
extern "C" void kernel_launch(void* const* d_in, const int* in_sizes, int n_in,
                              void* d_out, int out_size)
{
    const float* Q   = (const float*)d_in[0];
    const float* K   = (const float*)d_in[1];
    const float* V   = (const float*)d_in[2];
    const int*   mask = (const int*)d_in[3];
    const float* adjoin = (const float*)d_in[4];
    const float* Wq = (const float*)d_in[5];
    const float* bq = (const float*)d_in[6];
    const float* Wk = (const float*)d_in[7];
    const float* bk = (const float*)d_in[8];
    const float* Wv = (const float*)d_in[9];
    const float* bv = (const float*)d_in[10];
    const float* Wo = (const float*)d_in[11];
    const float* bo = (const float*)d_in[12];
    const float* lg = (const float*)d_in[13];
    const float* lb = (const float*)d_in[14];

    float *pb, *afb, *psum, *rinv, *madj;
    cudaGetSymbolAddress((void**)&pb,   g_pre);
    cudaGetSymbolAddress((void**)&afb,  g_attn_fb);
    cudaGetSymbolAddress((void**)&psum, g_psum);
    cudaGetSymbolAddress((void**)&rinv, g_rinv);
    cudaGetSymbolAddress((void**)&madj, g_madj);

    __nv_bfloat16 *xh, *xl, *wh, *wl, *qh, *ql, *kh, *kl, *vh, *eh, *el;
    cudaGetSymbolAddress((void**)&xh, g_xh);
    cudaGetSymbolAddress((void**)&xl, g_xl);
    cudaGetSymbolAddress((void**)&wh, g_wh);
    cudaGetSymbolAddress((void**)&wl, g_wl);
    cudaGetSymbolAddress((void**)&qh, g_qh);
    cudaGetSymbolAddress((void**)&ql, g_ql);
    cudaGetSymbolAddress((void**)&kh, g_kh);
    cudaGetSymbolAddress((void**)&kl, g_kl);
    cudaGetSymbolAddress((void**)&vh, g_vh);
    cudaGetSymbolAddress((void**)&eh, g_eh);
    cudaGetSymbolAddress((void**)&el, g_el);

    float* out0 = (float*)d_out;
    const size_t OUT0 = (size_t)BSZ * SEQ * DM;
    const size_t ATTN = (size_t)BSZ * NH * SEQ * SEQ;
    const size_t MADJ = (size_t)BSZ * SEQ * SEQ;
    const bool need_attn = ((size_t)out_size >= OUT0 + ATTN);
    float* attn = need_attn ? (out0 + OUT0) : afb;

    static int attr_set = 0;
    if (!attr_set) {
        cudaFuncSetAttribute(gemm_proj_qkv,
                             cudaFuncAttributeMaxDynamicSharedMemorySize, QKV_SMEM);
        cudaFuncSetAttribute(gemm_proj_out,
                             cudaFuncAttributeMaxDynamicSharedMemorySize, QKV_SMEM);
        cudaFuncSetAttribute(gemm_scores_exp,
                             cudaFuncAttributeMaxDynamicSharedMemorySize, SCM_SMEM);
        attr_set = 1;
    }

    dim3 wgrid(DM / 32, DM / 32, 4), wblk(32, 8);
    dim3 xgrid((unsigned)(XSZ / 4 / 256), 3);

    // 0) All weights -> [n][k] bf16 hi/lo; mask+adjoin -> madj
    convert_w4<<<wgrid, wblk>>>(Wq, Wk, Wv, Wo, wh, wl);
    combine_madj<<<(unsigned)(MADJ / 4 / 256), 256>>>(mask, adjoin, madj);

    // 1) All activations -> bf16 hi/lo slots
    convert_x3<<<xgrid, 256>>>(Q, K, V, xh, xl);

    // 2) QKV projections: ONE launch, 128x64 tiles, 2 CTAs/SM
    dim3 gq(DM / 64, (BSZ * SEQ) / 128, 3);
    gemm_proj_qkv<<<gq, 256, QKV_SMEM>>>(xh, xl, wh, wl, bq, bk, bv,
                                         qh, ql, kh, kl, vh);

    // 3) Scores + madj + exp -> eh/el + per-tile row sums (2 CTAs/SM)
    dim3 gs(SEQ / 128, SEQ / 128, BSZ * NH);
    gemm_scores_exp<<<gs, 256, SCM_SMEM>>>(qh, ql, kh, kl, madj, eh, el, psum);

    // 4) Row sums -> 1/sum
    rowsum_inv<<<(BSZ * NH * SEQ) / 256, 256>>>(psum, rinv);

    // 5) Context (1-pass E@Vh) + fused attn write -> ctx bf16 in slot 0
    dim3 gc(SEQ / 128, BSZ * NH);
    gemm_ctx_mma<<<gc, 256>>>(eh, el, vh, rinv, attn, xh, xl);

    // 6) Output projection (2-pass, 128x64 tiles, 2 CTAs/SM)
    dim3 go(DM / 64, (BSZ * SEQ) / 128);
    gemm_proj_out<<<go, 256, QKV_SMEM>>>(xh, xl, wh + 3 * WSZC, wl + 3 * WSZC,
                                         bo, Q, pb);

    // 7) LayerNorm -> out
    layernorm_rows<<<(BSZ * SEQ) / 8, 256>>>(pb, lg, lb, out0);
}